// round 12
// baseline (speedup 1.0000x reference)
#include <cuda_runtime.h>
#include <cuda_bf16.h>
#include <math.h>
#include <stdint.h>

#define N_NODES 30000
#define N_EDGES 300000
#define N_GRAPHS 256
#define DD 128
#define HH 256
#define NLAYERS 3

#define FLAG_RELU 1
#define FLAG_ADDC 2
#define FLAG_BIAS3 4
#define FLAG_COPYSH 8
#define FLAG_ZEROSH 16

// ---------------- scratch -------------------------------------------------
__device__ float g_h[N_NODES * DD];
__device__ float g_PQ[(size_t)N_NODES * 1024];
__device__ float g_SH[(size_t)N_NODES * 640];
__device__ float g_Hu[N_NODES * HH];
__device__ float g_gv[N_GRAPHS * DD];
__device__ float g_gv2[N_GRAPHS * DD];
__device__ int   g_deg[2 * N_NODES];
__device__ int   g_cur[2 * N_NODES];
__device__ int   g_eidt[N_EDGES];
__device__ int   g_eidf[N_EDGES];
__device__ float g_WE[16 * 512];
__device__ float g_c[512];
__device__ float g_Wcat[128 * 1024];
__device__ float g_Vcat[640 * 256];
__device__ float g_bias3[768];

#define OFF_CAT 0
#define OFF_UPD 131072
#define OFF_UW2 294912
#define OFF_AW1 327680
#define OFF_ENW 360448
#define OFF_WET 364544
#define BPOOL   372736
__device__ __nv_bfloat16 g_Bh[BPOOL];
__device__ __nv_bfloat16 g_Bl[BPOOL];

// ---------------- helpers ---------------------------------------------------
__device__ __forceinline__ void red_add_v4(float* addr, float4 v) {
    asm volatile("red.global.add.v4.f32 [%0], {%1,%2,%3,%4};"
                 :: "l"(addr), "f"(v.x), "f"(v.y), "f"(v.z), "f"(v.w) : "memory");
}
__device__ __forceinline__ uint32_t packlo2(float a, float b) {
    uint32_t r;
    asm("cvt.rn.bf16x2.f32 %0, %1, %2;" : "=r"(r) : "f"(b), "f"(a));
    return r;
}
__device__ __forceinline__ uint32_t smem_u32(const void* p) {
    uint32_t a;
    asm("{ .reg .u64 t; cvta.to.shared.u64 t, %1; cvt.u32.u64 %0, t; }" : "=r"(a) : "l"(p));
    return a;
}
__device__ __forceinline__ void mma16816(float* c, const uint32_t* a, const uint32_t* b) {
    asm("mma.sync.aligned.m16n8k16.row.col.f32.bf16.bf16.f32 "
        "{%0,%1,%2,%3}, {%4,%5,%6,%7}, {%8,%9}, {%0,%1,%2,%3};"
        : "+f"(c[0]), "+f"(c[1]), "+f"(c[2]), "+f"(c[3])
        : "r"(a[0]), "r"(a[1]), "r"(a[2]), "r"(a[3]), "r"(b[0]), "r"(b[1]));
}
#define LDSM4(r, addr)                                                         \
    asm volatile("ldmatrix.sync.aligned.m8n8.x4.shared.b16 {%0,%1,%2,%3}, [%4];" \
        : "=r"((r)[0]), "=r"((r)[1]), "=r"((r)[2]), "=r"((r)[3]) : "r"(addr))
__device__ __forceinline__ void cp16(uint32_t dst, const void* src) {
    asm volatile("cp.async.cg.shared.global [%0], [%1], 16;" :: "r"(dst), "l"(src));
}
#define CP_COMMIT() asm volatile("cp.async.commit_group;" ::: "memory")
#define CP_WAIT0()  asm volatile("cp.async.wait_group 0;" ::: "memory")

__global__ void zero_k(float4* p, int n4) {
    int i = blockIdx.x * 256 + threadIdx.x;
    if (i < n4) p[i] = make_float4(0.f, 0.f, 0.f, 0.f);
}

// ---------------- merged weight prep ---------------------------------------
__global__ void prep_w_k(const float* __restrict__ enc_we, const float* __restrict__ enc_be,
                         const float* __restrict__ mw1, const float* __restrict__ mb1,
                         const float* __restrict__ rw1, const float* __restrict__ rb1,
                         const float* __restrict__ mw2, const float* __restrict__ rw2,
                         const float* __restrict__ uw1, const float* __restrict__ mb2,
                         const float* __restrict__ rmb2, const float* __restrict__ ub1) {
    int b = blockIdx.x, tid = threadIdx.x;
    if (b < 512) {
        int idx = b * 256 + tid;
        int d = idx >> 10, c = idx & 1023;
        float v;
        if      (c < 256) v = mw1[d * 256 + c];
        else if (c < 512) v = mw1[(128 + d) * 256 + (c - 256)];
        else if (c < 768) v = rw1[d * 256 + (c - 512)];
        else              v = rw1[(128 + d) * 256 + (c - 768)];
        g_Wcat[idx] = v;
    } else if (b < 1152) {
        int r = b - 512, n = tid;
        float acc = 0.f;
        if (r < 256) {
            for (int d = 0; d < 128; d++)
                acc = fmaf(mw2[r * 128 + d], uw1[d * 256 + n], acc);
        } else if (r < 512) {
            int k = r - 256;
            for (int d = 0; d < 128; d++)
                acc = fmaf(rw2[k * 128 + d], uw1[(128 + d) * 256 + n], acc);
        } else {
            acc = uw1[(256 + r - 512) * 256 + n];
        }
        g_Vcat[r * 256 + n] = acc;
        if (r == 0) {
            float c1 = 0.f, c2 = 0.f;
            for (int d = 0; d < 128; d++) {
                c1 = fmaf(mb2[d], uw1[d * 256 + n], c1);
                c2 = fmaf(rmb2[d], uw1[(128 + d) * 256 + n], c2);
            }
            g_bias3[n] = ub1[n];
            g_bias3[256 + n] = c1;
            g_bias3[512 + n] = c2;
        }
    } else {
        for (int j = tid; j < 512; j += 256) {
            const float* W1 = (j < 256) ? mw1 : rw1;
            const float* b1 = (j < 256) ? mb1 : rb1;
            int jc = j & 255;
            for (int k = 0; k < 16; k++) {
                float acc = 0.f;
                for (int d = 0; d < 128; d++)
                    acc = fmaf(enc_we[k * 128 + d], W1[(256 + d) * 256 + jc], acc);
                g_WE[k * 512 + j] = acc;
            }
            float acc = b1[jc];
            for (int d = 0; d < 128; d++)
                acc = fmaf(enc_be[d], W1[(256 + d) * 256 + jc], acc);
            g_c[j] = acc;
        }
    }
}

__device__ __forceinline__ void spt_one(const float* W, int off, int K, int N, int idx) {
    if (idx >= K * N) return;
    int k = idx / N, n = idx % N;
    float v = W[idx];
    uint32_t xu = __float_as_uint(v);
    unsigned short hb = (unsigned short)(xu >> 16);
    float hf = __uint_as_float(xu & 0xFFFF0000u);
    __nv_bfloat16 l = __float2bfloat16(v - hf);
    union { unsigned short s; __nv_bfloat16 b; } u; u.s = hb;
    g_Bh[off + (size_t)n * K + k] = u.b;
    g_Bl[off + (size_t)n * K + k] = l;
}
__global__ void spt_all_k(const float* __restrict__ uw2, const float* __restrict__ aw1,
                          const float* __restrict__ enc_wn) {
    int b = blockIdx.x, tid = threadIdx.x;
    if      (b < 512)  spt_one(g_Wcat, OFF_CAT, 128, 1024, b * 256 + tid);
    else if (b < 1152) spt_one(g_Vcat, OFF_UPD, 640, 256, (b - 512) * 256 + tid);
    else if (b < 1280) spt_one(uw2,    OFF_UW2, 256, 128, (b - 1152) * 256 + tid);
    else if (b < 1408) spt_one(aw1,    OFF_AW1, 128, 256, (b - 1280) * 256 + tid);
    else if (b < 1424) spt_one(enc_wn, OFF_ENW, 32, 128,  (b - 1408) * 256 + tid);
    else               spt_one(g_WE,   OFF_WET, 16, 512,  (b - 1424) * 256 + tid);
}

__global__ void hist_k(const int* __restrict__ from, const int* __restrict__ to) {
    int i = blockIdx.x * 256 + threadIdx.x;
    if (i >= N_EDGES) return;
    atomicAdd(&g_deg[to[i]], 1);
    atomicAdd(&g_deg[N_NODES + from[i]], 1);
}

__global__ void scan_k() {
    __shared__ int part[1024];
    const int* deg = g_deg + blockIdx.x * N_NODES;
    int* cur = g_cur + blockIdx.x * N_NODES;
    int tid = threadIdx.x;
    int base = tid * 30;
    int local[30];
    int s = 0;
    #pragma unroll
    for (int i = 0; i < 30; i++) {
        int idx = base + i;
        int v = (idx < N_NODES) ? deg[idx] : 0;
        local[i] = s; s += v;
    }
    part[tid] = s;
    __syncthreads();
    for (int d = 1; d < 1024; d <<= 1) {
        int v = (tid >= d) ? part[tid - d] : 0;
        __syncthreads();
        part[tid] += v;
        __syncthreads();
    }
    int pre = (tid > 0) ? part[tid - 1] : 0;
    #pragma unroll
    for (int i = 0; i < 30; i++) {
        int idx = base + i;
        if (idx < N_NODES) cur[idx] = pre + local[i];
    }
}

__global__ void build_k(const int* __restrict__ from, const int* __restrict__ to) {
    int e = blockIdx.x * 256 + threadIdx.x;
    if (e >= N_EDGES) return;
    int pt = atomicAdd(&g_cur[to[e]], 1);
    g_eidt[pt] = e;
    int pf = atomicAdd(&g_cur[N_NODES + from[e]], 1);
    g_eidf[pf] = e;
}

// ---------------- pipelined warp-MMA split-bf16 GEMM ------------------------
#define AST 20
#define SSTW (128 * AST)
#define STGW (4 * SSTW)
#define TG_DSMEM (2 * STGW * 4)

__global__ void __launch_bounds__(256, 2) tgemm_k(
    const float* __restrict__ A, int lda, int K,
    const __nv_bfloat16* __restrict__ Bh, const __nv_bfloat16* __restrict__ Bl,
    const float* __restrict__ bias, const int* __restrict__ rs1,
    const int* __restrict__ rs2,
    float* __restrict__ C, int ldc, int M, int N, int flags)
{
    extern __shared__ __align__(16) uint32_t dsm[];
    const uint32_t sb = smem_u32(dsm);
    const int tid = threadIdx.x, wid = tid >> 5, lane = tid & 31;
    const int g = lane >> 2, t = lane & 3;
    const int m0 = blockIdx.x * 128, n0 = blockIdx.y * 128;
    const int mbase = (wid & 3) * 32, nbase = (wid >> 2) * 64;
    const int lrow = (lane & 7) + ((lane >> 3) & 1) * 8;
    const int lcol = ((lane >> 4) & 1) * 4;

    float acc[2][8][4];
    #pragma unroll
    for (int i = 0; i < 2; i++)
        #pragma unroll
        for (int j = 0; j < 8; j++)
            #pragma unroll
            for (int q = 0; q < 4; q++) acc[i][j][q] = 0.f;

    const int arow = tid >> 1, ahalf = tid & 1;
    const bool mok = (m0 + arow) < M;
    const float* Ap = A + (size_t)(m0 + arow) * lda;
    const __nv_bfloat16* Bhp = Bh + (size_t)(n0 + arow) * K + ahalf * 16;
    const __nv_bfloat16* Blp = Bl + (size_t)(n0 + arow) * K + ahalf * 16;
    const uint32_t bWord = (uint32_t)(arow * AST + ahalf * 8);

    float4 areg[4];
    const int nchunk = K >> 5;

    #pragma unroll
    for (int j = 0; j < 4; j++)
        areg[j] = mok ? *(const float4*)(Ap + ahalf * 16 + j * 4)
                      : make_float4(0.f, 0.f, 0.f, 0.f);
    {
        uint32_t bbase = sb + 2 * SSTW * 4;
        cp16(bbase + bWord * 4, Bhp);
        cp16(bbase + (bWord + 4) * 4, Bhp + 8);
        cp16(bbase + SSTW * 4 + bWord * 4, Blp);
        cp16(bbase + SSTW * 4 + (bWord + 4) * 4, Blp + 8);
        CP_COMMIT();
    }
    {
        uint32_t* pAh = dsm + bWord;
        uint32_t* pAl = dsm + SSTW + bWord;
        #pragma unroll
        for (int j = 0; j < 4; j++) {
            float4 v = areg[j];
            uint32_t x0 = __float_as_uint(v.x), x1 = __float_as_uint(v.y);
            uint32_t x2 = __float_as_uint(v.z), x3 = __float_as_uint(v.w);
            pAh[j * 2]     = (x1 & 0xFFFF0000u) | (x0 >> 16);
            pAh[j * 2 + 1] = (x3 & 0xFFFF0000u) | (x2 >> 16);
            float l0 = v.x - __uint_as_float(x0 & 0xFFFF0000u);
            float l1 = v.y - __uint_as_float(x1 & 0xFFFF0000u);
            float l2 = v.z - __uint_as_float(x2 & 0xFFFF0000u);
            float l3 = v.w - __uint_as_float(x3 & 0xFFFF0000u);
            pAl[j * 2]     = packlo2(l0, l1);
            pAl[j * 2 + 1] = packlo2(l2, l3);
        }
    }
    CP_WAIT0();
    __syncthreads();

    for (int c = 0; c < nchunk; c++) {
        const int cur = c & 1, nxt = (c + 1) & 1;
        const bool more = (c + 1) < nchunk;
        if (more) {
            #pragma unroll
            for (int j = 0; j < 4; j++)
                areg[j] = mok ? *(const float4*)(Ap + (c + 1) * 32 + ahalf * 16 + j * 4)
                              : make_float4(0.f, 0.f, 0.f, 0.f);
            uint32_t bbase = sb + (nxt * STGW + 2 * SSTW) * 4;
            const __nv_bfloat16* bh = Bhp + (c + 1) * 32;
            const __nv_bfloat16* bl = Blp + (c + 1) * 32;
            cp16(bbase + bWord * 4, bh);
            cp16(bbase + (bWord + 4) * 4, bh + 8);
            cp16(bbase + SSTW * 4 + bWord * 4, bl);
            cp16(bbase + SSTW * 4 + (bWord + 4) * 4, bl + 8);
            CP_COMMIT();
        }

        const uint32_t uAh = sb + cur * STGW * 4;
        const uint32_t uBh = uAh + 2 * SSTW * 4;
        const uint32_t dLo = SSTW * 4;
        #pragma unroll
        for (int ks = 0; ks < 2; ks++) {
            uint32_t ah[2][4], al[2][4];
            #pragma unroll
            for (int i = 0; i < 2; i++) {
                uint32_t ad = uAh + (uint32_t)(((mbase + 16 * i + lrow) * AST + ks * 8 + lcol) * 4);
                LDSM4(ah[i], ad);
                LDSM4(al[i], ad + dLo);
            }
            uint32_t bh[2][4], bl[2][4];
            {
                uint32_t bd = uBh + (uint32_t)(((nbase + lrow) * AST + ks * 8 + lcol) * 4);
                LDSM4(bh[0], bd);
                LDSM4(bl[0], bd + dLo);
            }
            #pragma unroll
            for (int jj = 0; jj < 4; jj++) {
                const int cb = jj & 1, nb = cb ^ 1;
                if (jj < 3) {
                    uint32_t bd = uBh + (uint32_t)(((nbase + 16 * (jj + 1) + lrow) * AST + ks * 8 + lcol) * 4);
                    LDSM4(bh[nb], bd);
                    LDSM4(bl[nb], bd + dLo);
                }
                uint32_t b0[2] = { bh[cb][0], bh[cb][2] }, b1[2] = { bh[cb][1], bh[cb][3] };
                uint32_t c0[2] = { bl[cb][0], bl[cb][2] }, c1[2] = { bl[cb][1], bl[cb][3] };
                int j0 = 2 * jj, j1 = 2 * jj + 1;
                mma16816(acc[0][j0], ah[0], b0);
                mma16816(acc[1][j0], ah[1], b0);
                mma16816(acc[0][j1], ah[0], b1);
                mma16816(acc[1][j1], ah[1], b1);
                mma16816(acc[0][j0], al[0], b0);
                mma16816(acc[1][j0], al[1], b0);
                mma16816(acc[0][j1], al[0], b1);
                mma16816(acc[1][j1], al[1], b1);
                mma16816(acc[0][j0], ah[0], c0);
                mma16816(acc[1][j0], ah[1], c0);
                mma16816(acc[0][j1], ah[0], c1);
                mma16816(acc[1][j1], ah[1], c1);
            }
        }

        if (more) {
            uint32_t* pAh = dsm + nxt * STGW + bWord;
            uint32_t* pAl = pAh + SSTW;
            #pragma unroll
            for (int j = 0; j < 4; j++) {
                float4 v = areg[j];
                uint32_t x0 = __float_as_uint(v.x), x1 = __float_as_uint(v.y);
                uint32_t x2 = __float_as_uint(v.z), x3 = __float_as_uint(v.w);
                pAh[j * 2]     = (x1 & 0xFFFF0000u) | (x0 >> 16);
                pAh[j * 2 + 1] = (x3 & 0xFFFF0000u) | (x2 >> 16);
                float l0 = v.x - __uint_as_float(x0 & 0xFFFF0000u);
                float l1 = v.y - __uint_as_float(x1 & 0xFFFF0000u);
                float l2 = v.z - __uint_as_float(x2 & 0xFFFF0000u);
                float l3 = v.w - __uint_as_float(x3 & 0xFFFF0000u);
                pAl[j * 2]     = packlo2(l0, l1);
                pAl[j * 2 + 1] = packlo2(l2, l3);
            }
            CP_WAIT0();
        }
        __syncthreads();
    }

    #pragma unroll
    for (int i = 0; i < 2; i++) {
        #pragma unroll
        for (int rr = 0; rr < 2; rr++) {
            int row = m0 + mbase + 16 * i + g + 8 * rr;
            if (row >= M) continue;
            float r1 = 0.f, r2 = 0.f;
            if (flags & FLAG_BIAS3) { r1 = (float)rs1[row]; r2 = (float)rs2[row]; }
            float* crow = C + (size_t)row * ldc;
            #pragma unroll
            for (int j = 0; j < 8; j++) {
                int nn = n0 + nbase + 8 * j + 2 * t;
                float2 v = make_float2(acc[i][j][2 * rr], acc[i][j][2 * rr + 1]);
                if (flags & FLAG_BIAS3) {
                    v.x += bias[nn] + r1 * bias[256 + nn] + r2 * bias[512 + nn];
                    v.y += bias[nn + 1] + r1 * bias[256 + nn + 1] + r2 * bias[512 + nn + 1];
                } else if (bias) {
                    v.x += bias[nn]; v.y += bias[nn + 1];
                }
                if (flags & FLAG_ADDC) {
                    float2 c0 = *(const float2*)(crow + nn);
                    v.x += c0.x; v.y += c0.y;
                }
                if (flags & FLAG_RELU) {
                    v.x = fmaxf(v.x, 0.f); v.y = fmaxf(v.y, 0.f);
                }
                *(float2*)(crow + nn) = v;
                if (flags & FLAG_COPYSH)
                    *(float2*)(g_SH + (size_t)row * 640 + 512 + nn) = v;
                if ((flags & FLAG_ZEROSH) && nn < 512)
                    *(float2*)(g_SH + (size_t)row * 640 + nn) = make_float2(0.f, 0.f);
            }
        }
    }
}

// ---------------- CSR-sorted fused edge pass (both dirs, one launch) --------
#define CASTE 12
#define ECST 132
#define oAh 0
#define oAl 6144
#define oWh 12288
#define oWl 18432
#define oEc 24576
#define oCc 92160
#define oEi 94208
#define oDs 94720
#define oSr 95232
#define ESMEM 95744
#define GEB ((N_EDGES + 127) / 128)

__global__ void __launch_bounds__(256) edge_csr_k(
    const float* __restrict__ ef, const int* __restrict__ from,
    const int* __restrict__ to)
{
    extern __shared__ __align__(16) char esm[];
    const uint32_t sb = smem_u32(esm);
    float* Ech = (float*)(esm + oEc);
    float* scf = (float*)(esm + oCc);
    int* sEid = (int*)(esm + oEi);
    int* sDest = (int*)(esm + oDs);
    int* sSrc = (int*)(esm + oSr);

    const int tid = threadIdx.x, wid = tid >> 5, lane = tid & 31;
    const int g = lane >> 2, t = lane & 3;
    const int mbase = (wid & 3) * 32, nbase = (wid >> 2) * 64;
    const int lrow = (lane & 7) + ((lane >> 3) & 1) * 8;
    const int lcol = ((lane >> 4) & 1) * 4;

    const int dir = (blockIdx.x >= GEB) ? 1 : 0;
    const int p0 = (blockIdx.x - dir * GEB) * 128;
    const int cnt = (N_EDGES - p0 < 128) ? (N_EDGES - p0) : 128;
    const int* eidArr = dir ? g_eidf : g_eidt;
    const int* dstArr = dir ? from : to;
    const int* srcArr = dir ? to : from;

    if (tid < 128) {
        int p = p0 + tid;
        int e = (p < N_EDGES) ? eidArr[p] : -1;
        sEid[tid] = e;
        sDest[tid] = (e >= 0) ? dstArr[e] : -1;
        sSrc[tid] = (e >= 0) ? srcArr[e] : 0;
    }
    for (int i = tid; i < 512; i += 256) scf[i] = g_c[i];
    __syncthreads();

    {
        int row = tid >> 1, half = tid & 1;
        int e = sEid[row];
        float4 v0 = make_float4(0.f, 0.f, 0.f, 0.f), v1 = v0;
        if (e >= 0) {
            v0 = *(const float4*)(ef + (size_t)e * 16 + half * 8);
            v1 = *(const float4*)(ef + (size_t)e * 16 + half * 8 + 4);
        }
        uint32_t* pAh = (uint32_t*)(esm + oAh) + row * CASTE + half * 4;
        uint32_t* pAl = (uint32_t*)(esm + oAl) + row * CASTE + half * 4;
        #pragma unroll
        for (int q = 0; q < 2; q++) {
            float4 v = q ? v1 : v0;
            uint32_t x0 = __float_as_uint(v.x), x1 = __float_as_uint(v.y);
            uint32_t x2 = __float_as_uint(v.z), x3 = __float_as_uint(v.w);
            pAh[2 * q]     = (x1 & 0xFFFF0000u) | (x0 >> 16);
            pAh[2 * q + 1] = (x3 & 0xFFFF0000u) | (x2 >> 16);
            float l0 = v.x - __uint_as_float(x0 & 0xFFFF0000u);
            float l1 = v.y - __uint_as_float(x1 & 0xFFFF0000u);
            float l2 = v.z - __uint_as_float(x2 & 0xFFFF0000u);
            float l3 = v.w - __uint_as_float(x3 & 0xFFFF0000u);
            pAl[2 * q]     = packlo2(l0, l1);
            pAl[2 * q + 1] = packlo2(l2, l3);
        }
    }
    __syncthreads();

    uint32_t ah[2][4], al[2][4];
    #pragma unroll
    for (int i = 0; i < 2; i++) {
        uint32_t ad = sb + oAh + (uint32_t)(((mbase + 16 * i + lrow) * CASTE + lcol) * 4);
        LDSM4(ah[i], ad);
        LDSM4(al[i], ad + (oAl - oAh));
    }

    for (int c = 0; c < 2; c++) {
        {
            int row = tid >> 1, half = tid & 1;
            const __nv_bfloat16* srcH = g_Bh + OFF_WET + (size_t)((dir * 2 + c) * 128 + row) * 16 + half * 8;
            const __nv_bfloat16* srcL = g_Bl + OFF_WET + (size_t)((dir * 2 + c) * 128 + row) * 16 + half * 8;
            *(uint4*)(esm + oWh + (row * CASTE + half * 4) * 4) = *(const uint4*)srcH;
            *(uint4*)(esm + oWl + (row * CASTE + half * 4) * 4) = *(const uint4*)srcL;
        }
        __syncthreads();

        float acc[2][8][4];
        #pragma unroll
        for (int i = 0; i < 2; i++)
            #pragma unroll
            for (int j = 0; j < 8; j++)
                #pragma unroll
                for (int q = 0; q < 4; q++) acc[i][j][q] = 0.f;
        #pragma unroll
        for (int jj = 0; jj < 4; jj++) {
            uint32_t bd = sb + oWh + (uint32_t)(((nbase + 16 * jj + lrow) * CASTE + lcol) * 4);
            uint32_t bh[4], bl[4];
            LDSM4(bh, bd);
            LDSM4(bl, bd + (oWl - oWh));
            uint32_t b0[2] = { bh[0], bh[2] }, b1[2] = { bh[1], bh[3] };
            uint32_t c0[2] = { bl[0], bl[2] }, c1[2] = { bl[1], bl[3] };
            int j0 = 2 * jj, j1 = 2 * jj + 1;
            mma16816(acc[0][j0], ah[0], b0);
            mma16816(acc[1][j0], ah[1], b0);
            mma16816(acc[0][j1], ah[0], b1);
            mma16816(acc[1][j1], ah[1], b1);
            mma16816(acc[0][j0], al[0], b0);
            mma16816(acc[1][j0], al[1], b0);
            mma16816(acc[0][j1], al[0], b1);
            mma16816(acc[1][j1], al[1], b1);
            mma16816(acc[0][j0], ah[0], c0);
            mma16816(acc[1][j0], ah[1], c0);
            mma16816(acc[0][j1], ah[0], c1);
            mma16816(acc[1][j1], ah[1], c1);
        }
        #pragma unroll
        for (int i = 0; i < 2; i++)
            #pragma unroll
            for (int rr = 0; rr < 2; rr++) {
                int row = mbase + 16 * i + g + 8 * rr;
                #pragma unroll
                for (int j = 0; j < 8; j++) {
                    int col = nbase + 8 * j + 2 * t;
                    *(float2*)&Ech[row * ECST + col] =
                        make_float2(acc[i][j][2 * rr], acc[i][j][2 * rr + 1]);
                }
            }
        __syncthreads();

        // ---- segmented consume with 4-deep prefetch pipeline ----
        {
            const int coff = c * 128 + lane * 4;
            const int rbeg = wid * 16;
            const int rend = (rbeg + 16 < cnt) ? rbeg + 16 : cnt;
            if (rbeg < rend) {
                float4 bias4 = *(float4*)&scf[dir * 256 + coff];
                const size_t pOff = (size_t)(dir * 512 + coff);
                float4 pp[4], qq[4];
                #pragma unroll
                for (int d0 = 0; d0 < 4; d0++) {
                    int rr = rbeg + d0;
                    if (rr < rend) {
                        pp[d0] = *(const float4*)(g_PQ + (size_t)sSrc[rr] * 1024 + pOff);
                        qq[d0] = *(const float4*)(g_PQ + (size_t)sDest[rr] * 1024 + pOff + 256);
                    } else {
                        pp[d0] = make_float4(0.f, 0.f, 0.f, 0.f);
                        qq[d0] = make_float4(0.f, 0.f, 0.f, 0.f);
                    }
                }
                int cur = sDest[rbeg];
                float4 a4 = make_float4(0.f, 0.f, 0.f, 0.f);
                bool first = true;
                #pragma unroll 4
                for (int r = rbeg; r < rend; r++) {
                    const int slot = (r - rbeg) & 3;
                    float4 p4 = pp[slot];
                    float4 q4 = qq[slot];
                    if (r + 4 < rend) {
                        pp[slot] = *(const float4*)(g_PQ + (size_t)sSrc[r + 4] * 1024 + pOff);
                        qq[slot] = *(const float4*)(g_PQ + (size_t)sDest[r + 4] * 1024 + pOff + 256);
                    }
                    int d = sDest[r];
                    if (d != cur) {
                        float* dst = g_SH + (size_t)cur * 640 + dir * 256 + coff;
                        if (first) red_add_v4(dst, a4);
                        else *(float4*)dst = a4;
                        first = false;
                        a4 = make_float4(0.f, 0.f, 0.f, 0.f);
                        cur = d;
                    }
                    float4 e4 = *(float4*)&Ech[r * ECST + lane * 4];
                    a4.x += fmaxf(p4.x + q4.x + e4.x + bias4.x, 0.f);
                    a4.y += fmaxf(p4.y + q4.y + e4.y + bias4.y, 0.f);
                    a4.z += fmaxf(p4.z + q4.z + e4.z + bias4.z, 0.f);
                    a4.w += fmaxf(p4.w + q4.w + e4.w + bias4.w, 0.f);
                }
                bool complete = (!first) && (rend < cnt) && (sDest[rend] != cur);
                float* dst = g_SH + (size_t)cur * 640 + dir * 256 + coff;
                if (complete) *(float4*)dst = a4;
                else red_add_v4(dst, a4);
            }
        }
        __syncthreads();
    }
}

// ---------------- tail kernels ----------------------------------------------
__global__ void gate_k(const int* __restrict__ gidx) {
    int idx = blockIdx.x * 256 + threadIdx.x;
    if (idx >= N_NODES * 32) return;
    int n = idx >> 5, c4 = (idx & 31) * 4;
    const float* gr = g_Hu + (size_t)n * 256;
    float4 a = *(const float4*)&gr[c4];
    float4 b = *(const float4*)&gr[128 + c4];
    float4 v;
    v.x = b.x / (1.f + expf(-a.x));
    v.y = b.y / (1.f + expf(-a.y));
    v.z = b.z / (1.f + expf(-a.z));
    v.w = b.w / (1.f + expf(-a.w));
    red_add_v4(&g_gv[gidx[n] * 128 + c4], v);
}

__global__ void gv2_k(const float* __restrict__ W, const float* __restrict__ b) {
    __shared__ float row[128];
    int r = blockIdx.x, d = threadIdx.x;
    row[d] = g_gv[r * 128 + d];
    __syncthreads();
    float acc = b[d];
    #pragma unroll 8
    for (int k = 0; k < 128; k++) acc = fmaf(row[k], W[k * 128 + d], acc);
    g_gv2[r * 128 + d] = acc;
}

__global__ void out_k(float* __restrict__ out) {
    __shared__ float sdata[128];
    int p = blockIdx.x, t = threadIdx.x;
    float dxy = g_gv2[(2 * p) * 128 + t] - g_gv2[(2 * p + 1) * 128 + t];
    sdata[t] = dxy * dxy;
    __syncthreads();
    for (int s = 64; s > 0; s >>= 1) {
        if (t < s) sdata[t] += sdata[t + s];
        __syncthreads();
    }
    if (t == 0) out[p] = -sdata[0];
}

// ---------------- host launch ----------------------------------------------
static void* sym(const void* s) { void* p = nullptr; cudaGetSymbolAddress(&p, s); return p; }

extern "C" void kernel_launch(void* const* d_in, const int* in_sizes, int n_in,
                              void* d_out, int out_size) {
    const float* nf     = (const float*)d_in[0];
    const float* ef     = (const float*)d_in[1];
    const int*   from   = (const int*)d_in[2];
    const int*   to     = (const int*)d_in[3];
    const int*   gidx   = (const int*)d_in[4];
    const float* enc_wn = (const float*)d_in[5];
    const float* enc_bn = (const float*)d_in[6];
    const float* enc_we = (const float*)d_in[7];
    const float* enc_be = (const float*)d_in[8];
    const float* msg_w1 = (const float*)d_in[9];
    const float* msg_b1 = (const float*)d_in[10];
    const float* msg_w2 = (const float*)d_in[11];
    const float* msg_b2 = (const float*)d_in[12];
    const float* rmsg_w1= (const float*)d_in[13];
    const float* rmsg_b1= (const float*)d_in[14];
    const float* rmsg_w2= (const float*)d_in[15];
    const float* rmsg_b2= (const float*)d_in[16];
    const float* upd_w1 = (const float*)d_in[17];
    const float* upd_b1 = (const float*)d_in[18];
    const float* upd_w2 = (const float*)d_in[19];
    const float* upd_b2 = (const float*)d_in[20];
    const float* agg_w1 = (const float*)d_in[21];
    const float* agg_b1 = (const float*)d_in[22];
    const float* agg_w2 = (const float*)d_in[23];
    const float* agg_b2 = (const float*)d_in[24];
    float* out = (float*)d_out;

    float* p_h    = (float*)sym(g_h);
    float* p_PQ   = (float*)sym(g_PQ);
    float* p_SH   = (float*)sym(g_SH);
    float* p_Hu   = (float*)sym(g_Hu);
    float* p_gv   = (float*)sym(g_gv);
    float* p_b3   = (float*)sym(g_bias3);
    int*   p_deg  = (int*)sym(g_deg);
    __nv_bfloat16* p_Bh = (__nv_bfloat16*)sym(g_Bh);
    __nv_bfloat16* p_Bl = (__nv_bfloat16*)sym(g_Bl);

    cudaFuncSetAttribute(tgemm_k, cudaFuncAttributeMaxDynamicSharedMemorySize, TG_DSMEM);
    cudaFuncSetAttribute(edge_csr_k, cudaFuncAttributeMaxDynamicSharedMemorySize, ESMEM);

    const int GM = (N_NODES + 127) / 128;   // 235

    prep_w_k<<<1153, 256>>>(enc_we, enc_be, msg_w1, msg_b1, rmsg_w1, rmsg_b1,
                            msg_w2, rmsg_w2, upd_w1, msg_b2, rmsg_b2, upd_b1);
    spt_all_k<<<1456, 256>>>(upd_w2, agg_w1, enc_wn);
    tgemm_k<<<dim3(GM, 1), 256, TG_DSMEM>>>(nf, 32, 32, p_Bh + OFF_ENW, p_Bl + OFF_ENW,
                                            enc_bn, nullptr, nullptr, p_h, 128, N_NODES, 128,
                                            FLAG_COPYSH);
    tgemm_k<<<dim3(GM, 8), 256, TG_DSMEM>>>(p_h, 128, 128, p_Bh + OFF_CAT, p_Bl + OFF_CAT,
                                            nullptr, nullptr, nullptr, p_PQ, 1024, N_NODES, 1024,
                                            FLAG_ZEROSH);
    zero_k<<<(2 * N_NODES / 4 + 255) / 256, 256>>>((float4*)p_deg, 2 * N_NODES / 4);
    hist_k<<<(N_EDGES + 255) / 256, 256>>>(from, to);
    scan_k<<<2, 1024>>>();
    build_k<<<(N_EDGES + 255) / 256, 256>>>(from, to);

    for (int l = 0; l < NLAYERS; l++) {
        if (l > 0)
            tgemm_k<<<dim3(GM, 8), 256, TG_DSMEM>>>(p_h, 128, 128, p_Bh + OFF_CAT, p_Bl + OFF_CAT,
                                                    nullptr, nullptr, nullptr, p_PQ, 1024, N_NODES, 1024,
                                                    FLAG_ZEROSH);
        edge_csr_k<<<2 * GEB, 256, ESMEM>>>(ef, from, to);
        tgemm_k<<<dim3(GM, 2), 256, TG_DSMEM>>>(p_SH, 640, 640, p_Bh + OFF_UPD, p_Bl + OFF_UPD,
                                                p_b3, p_deg, p_deg + N_NODES, p_Hu, 256, N_NODES, 256,
                                                FLAG_RELU | FLAG_BIAS3);
        int fl = FLAG_ADDC | ((l < NLAYERS - 1) ? FLAG_COPYSH : 0);
        tgemm_k<<<dim3(GM, 1), 256, TG_DSMEM>>>(p_Hu, 256, 256, p_Bh + OFF_UW2, p_Bl + OFF_UW2,
                                                upd_b2, nullptr, nullptr, p_h, 128, N_NODES, 128, fl);
    }

    tgemm_k<<<dim3(GM, 2), 256, TG_DSMEM>>>(p_h, 128, 128, p_Bh + OFF_AW1, p_Bl + OFF_AW1,
                                            agg_b1, nullptr, nullptr, p_Hu, 256, N_NODES, 256, 0);
    zero_k<<<(N_GRAPHS * 32 + 255) / 256, 256>>>((float4*)p_gv, N_GRAPHS * 32);
    gate_k<<<(N_NODES * 32 + 255) / 256, 256>>>(gidx);
    gv2_k<<<N_GRAPHS, 128>>>(agg_w2, agg_b2);
    out_k<<<128, 128>>>(out);
    (void)in_sizes; (void)n_in; (void)out_size;
}

// round 13
// speedup vs baseline: 1.2924x; 1.2924x over previous
#include <cuda_runtime.h>
#include <cuda_bf16.h>
#include <math.h>
#include <stdint.h>

#define N_NODES 30000
#define N_EDGES 300000
#define N_GRAPHS 256
#define DD 128
#define HH 256
#define NLAYERS 3

#define FLAG_RELU 1
#define FLAG_ADDC 2
#define FLAG_BIAS3 4
#define FLAG_COPYSH 8
#define FLAG_ZEROSH 16

// ---------------- scratch -------------------------------------------------
__device__ float g_h[N_NODES * DD];
__device__ float g_PQ[(size_t)N_NODES * 1024];
__device__ float g_SH[(size_t)N_NODES * 640];
__device__ float g_Hu[N_NODES * HH];
__device__ float g_gv[N_GRAPHS * DD];
__device__ float g_gv2[N_GRAPHS * DD];
__device__ int   g_deg[2 * N_NODES];
__device__ int   g_cur[2 * N_NODES];
__device__ int   g_eidt[N_EDGES];
__device__ int   g_eidf[N_EDGES];
__device__ float g_WE[16 * 512];
__device__ float g_c[512];
__device__ float g_Wcat[128 * 1024];
__device__ float g_Vcat[640 * 256];
__device__ float g_bias3[768];

#define OFF_CAT 0
#define OFF_UPD 131072
#define OFF_UW2 294912
#define OFF_AW1 327680
#define OFF_ENW 360448
#define OFF_WET 364544
#define BPOOL   372736
__device__ __nv_bfloat16 g_Bh[BPOOL];
__device__ __nv_bfloat16 g_Bl[BPOOL];

// ---------------- helpers ---------------------------------------------------
__device__ __forceinline__ void red_add_v4(float* addr, float4 v) {
    asm volatile("red.global.add.v4.f32 [%0], {%1,%2,%3,%4};"
                 :: "l"(addr), "f"(v.x), "f"(v.y), "f"(v.z), "f"(v.w) : "memory");
}
__device__ __forceinline__ uint32_t packlo2(float a, float b) {
    uint32_t r;
    asm("cvt.rn.bf16x2.f32 %0, %1, %2;" : "=r"(r) : "f"(b), "f"(a));
    return r;
}
__device__ __forceinline__ uint32_t smem_u32(const void* p) {
    uint32_t a;
    asm("{ .reg .u64 t; cvta.to.shared.u64 t, %1; cvt.u32.u64 %0, t; }" : "=r"(a) : "l"(p));
    return a;
}
__device__ __forceinline__ void mma16816(float* c, const uint32_t* a, const uint32_t* b) {
    asm("mma.sync.aligned.m16n8k16.row.col.f32.bf16.bf16.f32 "
        "{%0,%1,%2,%3}, {%4,%5,%6,%7}, {%8,%9}, {%0,%1,%2,%3};"
        : "+f"(c[0]), "+f"(c[1]), "+f"(c[2]), "+f"(c[3])
        : "r"(a[0]), "r"(a[1]), "r"(a[2]), "r"(a[3]), "r"(b[0]), "r"(b[1]));
}
#define LDSM4(r, addr)                                                         \
    asm volatile("ldmatrix.sync.aligned.m8n8.x4.shared.b16 {%0,%1,%2,%3}, [%4];" \
        : "=r"((r)[0]), "=r"((r)[1]), "=r"((r)[2]), "=r"((r)[3]) : "r"(addr))
__device__ __forceinline__ void cp16(uint32_t dst, const void* src) {
    asm volatile("cp.async.cg.shared.global [%0], [%1], 16;" :: "r"(dst), "l"(src));
}
#define CP_COMMIT() asm volatile("cp.async.commit_group;" ::: "memory")
#define CP_WAIT0()  asm volatile("cp.async.wait_group 0;" ::: "memory")

__global__ void zero_k(float4* p, int n4) {
    int i = blockIdx.x * 256 + threadIdx.x;
    if (i < n4) p[i] = make_float4(0.f, 0.f, 0.f, 0.f);
}

// ---------------- merged weight prep ---------------------------------------
__global__ void prep_w_k(const float* __restrict__ enc_we, const float* __restrict__ enc_be,
                         const float* __restrict__ mw1, const float* __restrict__ mb1,
                         const float* __restrict__ rw1, const float* __restrict__ rb1,
                         const float* __restrict__ mw2, const float* __restrict__ rw2,
                         const float* __restrict__ uw1, const float* __restrict__ mb2,
                         const float* __restrict__ rmb2, const float* __restrict__ ub1) {
    int b = blockIdx.x, tid = threadIdx.x;
    if (b < 512) {
        int idx = b * 256 + tid;
        int d = idx >> 10, c = idx & 1023;
        float v;
        if      (c < 256) v = mw1[d * 256 + c];
        else if (c < 512) v = mw1[(128 + d) * 256 + (c - 256)];
        else if (c < 768) v = rw1[d * 256 + (c - 512)];
        else              v = rw1[(128 + d) * 256 + (c - 768)];
        g_Wcat[idx] = v;
    } else if (b < 1152) {
        int r = b - 512, n = tid;
        float acc = 0.f;
        if (r < 256) {
            for (int d = 0; d < 128; d++)
                acc = fmaf(mw2[r * 128 + d], uw1[d * 256 + n], acc);
        } else if (r < 512) {
            int k = r - 256;
            for (int d = 0; d < 128; d++)
                acc = fmaf(rw2[k * 128 + d], uw1[(128 + d) * 256 + n], acc);
        } else {
            acc = uw1[(256 + r - 512) * 256 + n];
        }
        g_Vcat[r * 256 + n] = acc;
        if (r == 0) {
            float c1 = 0.f, c2 = 0.f;
            for (int d = 0; d < 128; d++) {
                c1 = fmaf(mb2[d], uw1[d * 256 + n], c1);
                c2 = fmaf(rmb2[d], uw1[(128 + d) * 256 + n], c2);
            }
            g_bias3[n] = ub1[n];
            g_bias3[256 + n] = c1;
            g_bias3[512 + n] = c2;
        }
    } else {
        for (int j = tid; j < 512; j += 256) {
            const float* W1 = (j < 256) ? mw1 : rw1;
            const float* b1 = (j < 256) ? mb1 : rb1;
            int jc = j & 255;
            for (int k = 0; k < 16; k++) {
                float acc = 0.f;
                for (int d = 0; d < 128; d++)
                    acc = fmaf(enc_we[k * 128 + d], W1[(256 + d) * 256 + jc], acc);
                g_WE[k * 512 + j] = acc;
            }
            float acc = b1[jc];
            for (int d = 0; d < 128; d++)
                acc = fmaf(enc_be[d], W1[(256 + d) * 256 + jc], acc);
            g_c[j] = acc;
        }
    }
}

__device__ __forceinline__ void spt_one(const float* W, int off, int K, int N, int idx) {
    if (idx >= K * N) return;
    int k = idx / N, n = idx % N;
    float v = W[idx];
    uint32_t xu = __float_as_uint(v);
    unsigned short hb = (unsigned short)(xu >> 16);
    float hf = __uint_as_float(xu & 0xFFFF0000u);
    __nv_bfloat16 l = __float2bfloat16(v - hf);
    union { unsigned short s; __nv_bfloat16 b; } u; u.s = hb;
    g_Bh[off + (size_t)n * K + k] = u.b;
    g_Bl[off + (size_t)n * K + k] = l;
}
__global__ void spt_all_k(const float* __restrict__ uw2, const float* __restrict__ aw1,
                          const float* __restrict__ enc_wn) {
    int b = blockIdx.x, tid = threadIdx.x;
    if      (b < 512)  spt_one(g_Wcat, OFF_CAT, 128, 1024, b * 256 + tid);
    else if (b < 1152) spt_one(g_Vcat, OFF_UPD, 640, 256, (b - 512) * 256 + tid);
    else if (b < 1280) spt_one(uw2,    OFF_UW2, 256, 128, (b - 1152) * 256 + tid);
    else if (b < 1408) spt_one(aw1,    OFF_AW1, 128, 256, (b - 1280) * 256 + tid);
    else if (b < 1424) spt_one(enc_wn, OFF_ENW, 32, 128,  (b - 1408) * 256 + tid);
    else               spt_one(g_WE,   OFF_WET, 16, 512,  (b - 1424) * 256 + tid);
}

__global__ void hist_k(const int* __restrict__ from, const int* __restrict__ to) {
    int i = blockIdx.x * 256 + threadIdx.x;
    if (i >= N_EDGES) return;
    atomicAdd(&g_deg[to[i]], 1);
    atomicAdd(&g_deg[N_NODES + from[i]], 1);
}

__global__ void scan_k() {
    __shared__ int part[1024];
    const int* deg = g_deg + blockIdx.x * N_NODES;
    int* cur = g_cur + blockIdx.x * N_NODES;
    int tid = threadIdx.x;
    int base = tid * 30;
    int local[30];
    int s = 0;
    #pragma unroll
    for (int i = 0; i < 30; i++) {
        int idx = base + i;
        int v = (idx < N_NODES) ? deg[idx] : 0;
        local[i] = s; s += v;
    }
    part[tid] = s;
    __syncthreads();
    for (int d = 1; d < 1024; d <<= 1) {
        int v = (tid >= d) ? part[tid - d] : 0;
        __syncthreads();
        part[tid] += v;
        __syncthreads();
    }
    int pre = (tid > 0) ? part[tid - 1] : 0;
    #pragma unroll
    for (int i = 0; i < 30; i++) {
        int idx = base + i;
        if (idx < N_NODES) cur[idx] = pre + local[i];
    }
}

__global__ void build_k(const int* __restrict__ from, const int* __restrict__ to) {
    int e = blockIdx.x * 256 + threadIdx.x;
    if (e >= N_EDGES) return;
    int pt = atomicAdd(&g_cur[to[e]], 1);
    g_eidt[pt] = e;
    int pf = atomicAdd(&g_cur[N_NODES + from[e]], 1);
    g_eidf[pf] = e;
}

// ---------------- pipelined warp-MMA split-bf16 GEMM ------------------------
#define AST 20
#define SSTW (128 * AST)
#define STGW (4 * SSTW)
#define TG_DSMEM (2 * STGW * 4)

__global__ void __launch_bounds__(256, 2) tgemm_k(
    const float* __restrict__ A, int lda, int K,
    const __nv_bfloat16* __restrict__ Bh, const __nv_bfloat16* __restrict__ Bl,
    const float* __restrict__ bias, const int* __restrict__ rs1,
    const int* __restrict__ rs2,
    float* __restrict__ C, int ldc, int M, int N, int flags)
{
    extern __shared__ __align__(16) uint32_t dsm[];
    const uint32_t sb = smem_u32(dsm);
    const int tid = threadIdx.x, wid = tid >> 5, lane = tid & 31;
    const int g = lane >> 2, t = lane & 3;
    const int m0 = blockIdx.x * 128, n0 = blockIdx.y * 128;
    const int mbase = (wid & 3) * 32, nbase = (wid >> 2) * 64;
    const int lrow = (lane & 7) + ((lane >> 3) & 1) * 8;
    const int lcol = ((lane >> 4) & 1) * 4;

    float acc[2][8][4];
    #pragma unroll
    for (int i = 0; i < 2; i++)
        #pragma unroll
        for (int j = 0; j < 8; j++)
            #pragma unroll
            for (int q = 0; q < 4; q++) acc[i][j][q] = 0.f;

    const int arow = tid >> 1, ahalf = tid & 1;
    const bool mok = (m0 + arow) < M;
    const float* Ap = A + (size_t)(m0 + arow) * lda;
    const __nv_bfloat16* Bhp = Bh + (size_t)(n0 + arow) * K + ahalf * 16;
    const __nv_bfloat16* Blp = Bl + (size_t)(n0 + arow) * K + ahalf * 16;
    const uint32_t bWord = (uint32_t)(arow * AST + ahalf * 8);

    float4 areg[4];
    const int nchunk = K >> 5;

    #pragma unroll
    for (int j = 0; j < 4; j++)
        areg[j] = mok ? *(const float4*)(Ap + ahalf * 16 + j * 4)
                      : make_float4(0.f, 0.f, 0.f, 0.f);
    {
        uint32_t bbase = sb + 2 * SSTW * 4;
        cp16(bbase + bWord * 4, Bhp);
        cp16(bbase + (bWord + 4) * 4, Bhp + 8);
        cp16(bbase + SSTW * 4 + bWord * 4, Blp);
        cp16(bbase + SSTW * 4 + (bWord + 4) * 4, Blp + 8);
        CP_COMMIT();
    }
    {
        uint32_t* pAh = dsm + bWord;
        uint32_t* pAl = dsm + SSTW + bWord;
        #pragma unroll
        for (int j = 0; j < 4; j++) {
            float4 v = areg[j];
            uint32_t x0 = __float_as_uint(v.x), x1 = __float_as_uint(v.y);
            uint32_t x2 = __float_as_uint(v.z), x3 = __float_as_uint(v.w);
            pAh[j * 2]     = (x1 & 0xFFFF0000u) | (x0 >> 16);
            pAh[j * 2 + 1] = (x3 & 0xFFFF0000u) | (x2 >> 16);
            float l0 = v.x - __uint_as_float(x0 & 0xFFFF0000u);
            float l1 = v.y - __uint_as_float(x1 & 0xFFFF0000u);
            float l2 = v.z - __uint_as_float(x2 & 0xFFFF0000u);
            float l3 = v.w - __uint_as_float(x3 & 0xFFFF0000u);
            pAl[j * 2]     = packlo2(l0, l1);
            pAl[j * 2 + 1] = packlo2(l2, l3);
        }
    }
    CP_WAIT0();
    __syncthreads();

    for (int c = 0; c < nchunk; c++) {
        const int cur = c & 1, nxt = (c + 1) & 1;
        const bool more = (c + 1) < nchunk;
        if (more) {
            #pragma unroll
            for (int j = 0; j < 4; j++)
                areg[j] = mok ? *(const float4*)(Ap + (c + 1) * 32 + ahalf * 16 + j * 4)
                              : make_float4(0.f, 0.f, 0.f, 0.f);
            uint32_t bbase = sb + (nxt * STGW + 2 * SSTW) * 4;
            const __nv_bfloat16* bh = Bhp + (c + 1) * 32;
            const __nv_bfloat16* bl = Blp + (c + 1) * 32;
            cp16(bbase + bWord * 4, bh);
            cp16(bbase + (bWord + 4) * 4, bh + 8);
            cp16(bbase + SSTW * 4 + bWord * 4, bl);
            cp16(bbase + SSTW * 4 + (bWord + 4) * 4, bl + 8);
            CP_COMMIT();
        }

        const uint32_t uAh = sb + cur * STGW * 4;
        const uint32_t uBh = uAh + 2 * SSTW * 4;
        const uint32_t dLo = SSTW * 4;
        #pragma unroll
        for (int ks = 0; ks < 2; ks++) {
            uint32_t ah[2][4], al[2][4];
            #pragma unroll
            for (int i = 0; i < 2; i++) {
                uint32_t ad = uAh + (uint32_t)(((mbase + 16 * i + lrow) * AST + ks * 8 + lcol) * 4);
                LDSM4(ah[i], ad);
                LDSM4(al[i], ad + dLo);
            }
            uint32_t bh[2][4], bl[2][4];
            {
                uint32_t bd = uBh + (uint32_t)(((nbase + lrow) * AST + ks * 8 + lcol) * 4);
                LDSM4(bh[0], bd);
                LDSM4(bl[0], bd + dLo);
            }
            #pragma unroll
            for (int jj = 0; jj < 4; jj++) {
                const int cb = jj & 1, nb = cb ^ 1;
                if (jj < 3) {
                    uint32_t bd = uBh + (uint32_t)(((nbase + 16 * (jj + 1) + lrow) * AST + ks * 8 + lcol) * 4);
                    LDSM4(bh[nb], bd);
                    LDSM4(bl[nb], bd + dLo);
                }
                uint32_t b0[2] = { bh[cb][0], bh[cb][2] }, b1[2] = { bh[cb][1], bh[cb][3] };
                uint32_t c0[2] = { bl[cb][0], bl[cb][2] }, c1[2] = { bl[cb][1], bl[cb][3] };
                int j0 = 2 * jj, j1 = 2 * jj + 1;
                mma16816(acc[0][j0], ah[0], b0);
                mma16816(acc[1][j0], ah[1], b0);
                mma16816(acc[0][j1], ah[0], b1);
                mma16816(acc[1][j1], ah[1], b1);
                mma16816(acc[0][j0], al[0], b0);
                mma16816(acc[1][j0], al[1], b0);
                mma16816(acc[0][j1], al[0], b1);
                mma16816(acc[1][j1], al[1], b1);
                mma16816(acc[0][j0], ah[0], c0);
                mma16816(acc[1][j0], ah[1], c0);
                mma16816(acc[0][j1], ah[0], c1);
                mma16816(acc[1][j1], ah[1], c1);
            }
        }

        if (more) {
            uint32_t* pAh = dsm + nxt * STGW + bWord;
            uint32_t* pAl = pAh + SSTW;
            #pragma unroll
            for (int j = 0; j < 4; j++) {
                float4 v = areg[j];
                uint32_t x0 = __float_as_uint(v.x), x1 = __float_as_uint(v.y);
                uint32_t x2 = __float_as_uint(v.z), x3 = __float_as_uint(v.w);
                pAh[j * 2]     = (x1 & 0xFFFF0000u) | (x0 >> 16);
                pAh[j * 2 + 1] = (x3 & 0xFFFF0000u) | (x2 >> 16);
                float l0 = v.x - __uint_as_float(x0 & 0xFFFF0000u);
                float l1 = v.y - __uint_as_float(x1 & 0xFFFF0000u);
                float l2 = v.z - __uint_as_float(x2 & 0xFFFF0000u);
                float l3 = v.w - __uint_as_float(x3 & 0xFFFF0000u);
                pAl[j * 2]     = packlo2(l0, l1);
                pAl[j * 2 + 1] = packlo2(l2, l3);
            }
            CP_WAIT0();
        }
        __syncthreads();
    }

    #pragma unroll
    for (int i = 0; i < 2; i++) {
        #pragma unroll
        for (int rr = 0; rr < 2; rr++) {
            int row = m0 + mbase + 16 * i + g + 8 * rr;
            if (row >= M) continue;
            float r1 = 0.f, r2 = 0.f;
            if (flags & FLAG_BIAS3) { r1 = (float)rs1[row]; r2 = (float)rs2[row]; }
            float* crow = C + (size_t)row * ldc;
            #pragma unroll
            for (int j = 0; j < 8; j++) {
                int nn = n0 + nbase + 8 * j + 2 * t;
                float2 v = make_float2(acc[i][j][2 * rr], acc[i][j][2 * rr + 1]);
                if (flags & FLAG_BIAS3) {
                    v.x += bias[nn] + r1 * bias[256 + nn] + r2 * bias[512 + nn];
                    v.y += bias[nn + 1] + r1 * bias[256 + nn + 1] + r2 * bias[512 + nn + 1];
                } else if (bias) {
                    v.x += bias[nn]; v.y += bias[nn + 1];
                }
                if (flags & FLAG_ADDC) {
                    float2 c0 = *(const float2*)(crow + nn);
                    v.x += c0.x; v.y += c0.y;
                }
                if (flags & FLAG_RELU) {
                    v.x = fmaxf(v.x, 0.f); v.y = fmaxf(v.y, 0.f);
                }
                *(float2*)(crow + nn) = v;
                if (flags & FLAG_COPYSH)
                    *(float2*)(g_SH + (size_t)row * 640 + 512 + nn) = v;
                if ((flags & FLAG_ZEROSH) && nn < 512)
                    *(float2*)(g_SH + (size_t)row * 640 + nn) = make_float2(0.f, 0.f);
            }
        }
    }
}

// ---------------- CSR-sorted fused edge pass (both dirs, one launch) --------
#define CASTE 12
#define ECST 132
#define oAh 0
#define oAl 6144
#define oWh 12288
#define oWl 18432
#define oEc 24576
#define oCc 92160
#define oEi 94208
#define oDs 94720
#define oSr 95232
#define ESMEM 95744
#define GEB ((N_EDGES + 127) / 128)

__global__ void __launch_bounds__(256) edge_csr_k(
    const float* __restrict__ ef, const int* __restrict__ from,
    const int* __restrict__ to)
{
    extern __shared__ __align__(16) char esm[];
    const uint32_t sb = smem_u32(esm);
    float* Ech = (float*)(esm + oEc);
    float* scf = (float*)(esm + oCc);
    int* sEid = (int*)(esm + oEi);
    int* sDest = (int*)(esm + oDs);
    int* sSrc = (int*)(esm + oSr);

    const int tid = threadIdx.x, wid = tid >> 5, lane = tid & 31;
    const int g = lane >> 2, t = lane & 3;
    const int mbase = (wid & 3) * 32, nbase = (wid >> 2) * 64;
    const int lrow = (lane & 7) + ((lane >> 3) & 1) * 8;
    const int lcol = ((lane >> 4) & 1) * 4;

    const int dir = (blockIdx.x >= GEB) ? 1 : 0;
    const int p0 = (blockIdx.x - dir * GEB) * 128;
    const int cnt = (N_EDGES - p0 < 128) ? (N_EDGES - p0) : 128;
    const int* eidArr = dir ? g_eidf : g_eidt;
    const int* dstArr = dir ? from : to;
    const int* srcArr = dir ? to : from;

    if (tid < 128) {
        int p = p0 + tid;
        int e = (p < N_EDGES) ? eidArr[p] : -1;
        sEid[tid] = e;
        sDest[tid] = (e >= 0) ? dstArr[e] : -1;
        sSrc[tid] = (e >= 0) ? srcArr[e] : 0;
    }
    for (int i = tid; i < 512; i += 256) scf[i] = g_c[i];
    __syncthreads();

    {
        int row = tid >> 1, half = tid & 1;
        int e = sEid[row];
        float4 v0 = make_float4(0.f, 0.f, 0.f, 0.f), v1 = v0;
        if (e >= 0) {
            v0 = *(const float4*)(ef + (size_t)e * 16 + half * 8);
            v1 = *(const float4*)(ef + (size_t)e * 16 + half * 8 + 4);
        }
        uint32_t* pAh = (uint32_t*)(esm + oAh) + row * CASTE + half * 4;
        uint32_t* pAl = (uint32_t*)(esm + oAl) + row * CASTE + half * 4;
        #pragma unroll
        for (int q = 0; q < 2; q++) {
            float4 v = q ? v1 : v0;
            uint32_t x0 = __float_as_uint(v.x), x1 = __float_as_uint(v.y);
            uint32_t x2 = __float_as_uint(v.z), x3 = __float_as_uint(v.w);
            pAh[2 * q]     = (x1 & 0xFFFF0000u) | (x0 >> 16);
            pAh[2 * q + 1] = (x3 & 0xFFFF0000u) | (x2 >> 16);
            float l0 = v.x - __uint_as_float(x0 & 0xFFFF0000u);
            float l1 = v.y - __uint_as_float(x1 & 0xFFFF0000u);
            float l2 = v.z - __uint_as_float(x2 & 0xFFFF0000u);
            float l3 = v.w - __uint_as_float(x3 & 0xFFFF0000u);
            pAl[2 * q]     = packlo2(l0, l1);
            pAl[2 * q + 1] = packlo2(l2, l3);
        }
    }
    __syncthreads();

    uint32_t ah[2][4], al[2][4];
    #pragma unroll
    for (int i = 0; i < 2; i++) {
        uint32_t ad = sb + oAh + (uint32_t)(((mbase + 16 * i + lrow) * CASTE + lcol) * 4);
        LDSM4(ah[i], ad);
        LDSM4(al[i], ad + (oAl - oAh));
    }

    for (int c = 0; c < 2; c++) {
        {
            int row = tid >> 1, half = tid & 1;
            const __nv_bfloat16* srcH = g_Bh + OFF_WET + (size_t)((dir * 2 + c) * 128 + row) * 16 + half * 8;
            const __nv_bfloat16* srcL = g_Bl + OFF_WET + (size_t)((dir * 2 + c) * 128 + row) * 16 + half * 8;
            *(uint4*)(esm + oWh + (row * CASTE + half * 4) * 4) = *(const uint4*)srcH;
            *(uint4*)(esm + oWl + (row * CASTE + half * 4) * 4) = *(const uint4*)srcL;
        }
        __syncthreads();

        float acc[2][8][4];
        #pragma unroll
        for (int i = 0; i < 2; i++)
            #pragma unroll
            for (int j = 0; j < 8; j++)
                #pragma unroll
                for (int q = 0; q < 4; q++) acc[i][j][q] = 0.f;
        #pragma unroll
        for (int jj = 0; jj < 4; jj++) {
            uint32_t bd = sb + oWh + (uint32_t)(((nbase + 16 * jj + lrow) * CASTE + lcol) * 4);
            uint32_t bh[4], bl[4];
            LDSM4(bh, bd);
            LDSM4(bl, bd + (oWl - oWh));
            uint32_t b0[2] = { bh[0], bh[2] }, b1[2] = { bh[1], bh[3] };
            uint32_t c0[2] = { bl[0], bl[2] }, c1[2] = { bl[1], bl[3] };
            int j0 = 2 * jj, j1 = 2 * jj + 1;
            mma16816(acc[0][j0], ah[0], b0);
            mma16816(acc[1][j0], ah[1], b0);
            mma16816(acc[0][j1], ah[0], b1);
            mma16816(acc[1][j1], ah[1], b1);
            mma16816(acc[0][j0], al[0], b0);
            mma16816(acc[1][j0], al[1], b0);
            mma16816(acc[0][j1], al[0], b1);
            mma16816(acc[1][j1], al[1], b1);
            mma16816(acc[0][j0], ah[0], c0);
            mma16816(acc[1][j0], ah[1], c0);
            mma16816(acc[0][j1], ah[0], c1);
            mma16816(acc[1][j1], ah[1], c1);
        }
        #pragma unroll
        for (int i = 0; i < 2; i++)
            #pragma unroll
            for (int rr = 0; rr < 2; rr++) {
                int row = mbase + 16 * i + g + 8 * rr;
                #pragma unroll
                for (int j = 0; j < 8; j++) {
                    int col = nbase + 8 * j + 2 * t;
                    *(float2*)&Ech[row * ECST + col] =
                        make_float2(acc[i][j][2 * rr], acc[i][j][2 * rr + 1]);
                }
            }
        __syncthreads();

        // ---- segmented consume with depth-1 scalar prefetch ----
        {
            const int coff = c * 128 + lane * 4;
            const int rbeg = wid * 16;
            const int rend = (rbeg + 16 < cnt) ? rbeg + 16 : cnt;
            if (rbeg < rend) {
                float4 bias4 = *(float4*)&scf[dir * 256 + coff];
                const size_t pOff = (size_t)(dir * 512 + coff);
                int cur = sDest[rbeg];
                float4 pN = *(const float4*)(g_PQ + (size_t)sSrc[rbeg] * 1024 + pOff);
                float4 qN = *(const float4*)(g_PQ + (size_t)cur * 1024 + pOff + 256);
                float4 a4 = make_float4(0.f, 0.f, 0.f, 0.f);
                bool first = true;
                for (int r = rbeg; r < rend; r++) {
                    float4 p4 = pN, q4 = qN;
                    if (r + 1 < rend) {
                        pN = *(const float4*)(g_PQ + (size_t)sSrc[r + 1] * 1024 + pOff);
                        qN = *(const float4*)(g_PQ + (size_t)sDest[r + 1] * 1024 + pOff + 256);
                    }
                    int d = sDest[r];
                    if (d != cur) {
                        float* dst = g_SH + (size_t)cur * 640 + dir * 256 + coff;
                        if (first) red_add_v4(dst, a4);
                        else *(float4*)dst = a4;
                        first = false;
                        a4 = make_float4(0.f, 0.f, 0.f, 0.f);
                        cur = d;
                    }
                    float4 e4 = *(float4*)&Ech[r * ECST + lane * 4];
                    a4.x += fmaxf(p4.x + q4.x + e4.x + bias4.x, 0.f);
                    a4.y += fmaxf(p4.y + q4.y + e4.y + bias4.y, 0.f);
                    a4.z += fmaxf(p4.z + q4.z + e4.z + bias4.z, 0.f);
                    a4.w += fmaxf(p4.w + q4.w + e4.w + bias4.w, 0.f);
                }
                bool complete = (!first) && (rend < cnt) && (sDest[rend] != cur);
                float* dst = g_SH + (size_t)cur * 640 + dir * 256 + coff;
                if (complete) *(float4*)dst = a4;
                else red_add_v4(dst, a4);
            }
        }
        __syncthreads();
    }
}

// ---------------- tail kernels ----------------------------------------------
__global__ void gate_k(const int* __restrict__ gidx) {
    int idx = blockIdx.x * 256 + threadIdx.x;
    if (idx >= N_NODES * 32) return;
    int n = idx >> 5, c4 = (idx & 31) * 4;
    const float* gr = g_Hu + (size_t)n * 256;
    float4 a = *(const float4*)&gr[c4];
    float4 b = *(const float4*)&gr[128 + c4];
    float4 v;
    v.x = b.x / (1.f + expf(-a.x));
    v.y = b.y / (1.f + expf(-a.y));
    v.z = b.z / (1.f + expf(-a.z));
    v.w = b.w / (1.f + expf(-a.w));
    red_add_v4(&g_gv[gidx[n] * 128 + c4], v);
}

__global__ void gv2_k(const float* __restrict__ W, const float* __restrict__ b) {
    __shared__ float row[128];
    int r = blockIdx.x, d = threadIdx.x;
    row[d] = g_gv[r * 128 + d];
    __syncthreads();
    float acc = b[d];
    #pragma unroll 8
    for (int k = 0; k < 128; k++) acc = fmaf(row[k], W[k * 128 + d], acc);
    g_gv2[r * 128 + d] = acc;
}

__global__ void out_k(float* __restrict__ out) {
    __shared__ float sdata[128];
    int p = blockIdx.x, t = threadIdx.x;
    float dxy = g_gv2[(2 * p) * 128 + t] - g_gv2[(2 * p + 1) * 128 + t];
    sdata[t] = dxy * dxy;
    __syncthreads();
    for (int s = 64; s > 0; s >>= 1) {
        if (t < s) sdata[t] += sdata[t + s];
        __syncthreads();
    }
    if (t == 0) out[p] = -sdata[0];
}

// ---------------- host launch ----------------------------------------------
static void* sym(const void* s) { void* p = nullptr; cudaGetSymbolAddress(&p, s); return p; }

extern "C" void kernel_launch(void* const* d_in, const int* in_sizes, int n_in,
                              void* d_out, int out_size) {
    const float* nf     = (const float*)d_in[0];
    const float* ef     = (const float*)d_in[1];
    const int*   from   = (const int*)d_in[2];
    const int*   to     = (const int*)d_in[3];
    const int*   gidx   = (const int*)d_in[4];
    const float* enc_wn = (const float*)d_in[5];
    const float* enc_bn = (const float*)d_in[6];
    const float* enc_we = (const float*)d_in[7];
    const float* enc_be = (const float*)d_in[8];
    const float* msg_w1 = (const float*)d_in[9];
    const float* msg_b1 = (const float*)d_in[10];
    const float* msg_w2 = (const float*)d_in[11];
    const float* msg_b2 = (const float*)d_in[12];
    const float* rmsg_w1= (const float*)d_in[13];
    const float* rmsg_b1= (const float*)d_in[14];
    const float* rmsg_w2= (const float*)d_in[15];
    const float* rmsg_b2= (const float*)d_in[16];
    const float* upd_w1 = (const float*)d_in[17];
    const float* upd_b1 = (const float*)d_in[18];
    const float* upd_w2 = (const float*)d_in[19];
    const float* upd_b2 = (const float*)d_in[20];
    const float* agg_w1 = (const float*)d_in[21];
    const float* agg_b1 = (const float*)d_in[22];
    const float* agg_w2 = (const float*)d_in[23];
    const float* agg_b2 = (const float*)d_in[24];
    float* out = (float*)d_out;

    float* p_h    = (float*)sym(g_h);
    float* p_PQ   = (float*)sym(g_PQ);
    float* p_SH   = (float*)sym(g_SH);
    float* p_Hu   = (float*)sym(g_Hu);
    float* p_gv   = (float*)sym(g_gv);
    float* p_b3   = (float*)sym(g_bias3);
    int*   p_deg  = (int*)sym(g_deg);
    __nv_bfloat16* p_Bh = (__nv_bfloat16*)sym(g_Bh);
    __nv_bfloat16* p_Bl = (__nv_bfloat16*)sym(g_Bl);

    cudaFuncSetAttribute(tgemm_k, cudaFuncAttributeMaxDynamicSharedMemorySize, TG_DSMEM);
    cudaFuncSetAttribute(edge_csr_k, cudaFuncAttributeMaxDynamicSharedMemorySize, ESMEM);

    const int GM = (N_NODES + 127) / 128;   // 235

    prep_w_k<<<1153, 256>>>(enc_we, enc_be, msg_w1, msg_b1, rmsg_w1, rmsg_b1,
                            msg_w2, rmsg_w2, upd_w1, msg_b2, rmsg_b2, upd_b1);
    spt_all_k<<<1456, 256>>>(upd_w2, agg_w1, enc_wn);
    tgemm_k<<<dim3(GM, 1), 256, TG_DSMEM>>>(nf, 32, 32, p_Bh + OFF_ENW, p_Bl + OFF_ENW,
                                            enc_bn, nullptr, nullptr, p_h, 128, N_NODES, 128,
                                            FLAG_COPYSH);
    tgemm_k<<<dim3(GM, 8), 256, TG_DSMEM>>>(p_h, 128, 128, p_Bh + OFF_CAT, p_Bl + OFF_CAT,
                                            nullptr, nullptr, nullptr, p_PQ, 1024, N_NODES, 1024,
                                            FLAG_ZEROSH);
    zero_k<<<(2 * N_NODES / 4 + 255) / 256, 256>>>((float4*)p_deg, 2 * N_NODES / 4);
    hist_k<<<(N_EDGES + 255) / 256, 256>>>(from, to);
    scan_k<<<2, 1024>>>();
    build_k<<<(N_EDGES + 255) / 256, 256>>>(from, to);

    for (int l = 0; l < NLAYERS; l++) {
        if (l > 0)
            tgemm_k<<<dim3(GM, 8), 256, TG_DSMEM>>>(p_h, 128, 128, p_Bh + OFF_CAT, p_Bl + OFF_CAT,
                                                    nullptr, nullptr, nullptr, p_PQ, 1024, N_NODES, 1024,
                                                    FLAG_ZEROSH);
        edge_csr_k<<<2 * GEB, 256, ESMEM>>>(ef, from, to);
        tgemm_k<<<dim3(GM, 2), 256, TG_DSMEM>>>(p_SH, 640, 640, p_Bh + OFF_UPD, p_Bl + OFF_UPD,
                                                p_b3, p_deg, p_deg + N_NODES, p_Hu, 256, N_NODES, 256,
                                                FLAG_RELU | FLAG_BIAS3);
        int fl = FLAG_ADDC | ((l < NLAYERS - 1) ? FLAG_COPYSH : 0);
        tgemm_k<<<dim3(GM, 1), 256, TG_DSMEM>>>(p_Hu, 256, 256, p_Bh + OFF_UW2, p_Bl + OFF_UW2,
                                                upd_b2, nullptr, nullptr, p_h, 128, N_NODES, 128, fl);
    }

    tgemm_k<<<dim3(GM, 2), 256, TG_DSMEM>>>(p_h, 128, 128, p_Bh + OFF_AW1, p_Bl + OFF_AW1,
                                            agg_b1, nullptr, nullptr, p_Hu, 256, N_NODES, 256, 0);
    zero_k<<<(N_GRAPHS * 32 + 255) / 256, 256>>>((float4*)p_gv, N_GRAPHS * 32);
    gate_k<<<(N_NODES * 32 + 255) / 256, 256>>>(gidx);
    gv2_k<<<N_GRAPHS, 128>>>(agg_w2, agg_b2);
    out_k<<<128, 128>>>(out);
    (void)in_sizes; (void)n_in; (void)out_size;
}

// round 14
// speedup vs baseline: 1.3384x; 1.0356x over previous
#include <cuda_runtime.h>
#include <cuda_bf16.h>
#include <cuda_fp16.h>
#include <math.h>
#include <stdint.h>

#define N_NODES 30000
#define N_EDGES 300000
#define N_GRAPHS 256
#define DD 128
#define HH 256
#define NLAYERS 3

#define FLAG_RELU 1
#define FLAG_ADDC 2
#define FLAG_BIAS3 4
#define FLAG_COPYSH 8
#define FLAG_ZEROSH 16
#define FLAG_FP16OUT 32

// ---------------- scratch -------------------------------------------------
__device__ float g_h[N_NODES * DD];
__device__ __half g_PQh[(size_t)N_NODES * 1024];   // fp16 PQ (61 MB, L2-resident)
__device__ float g_SH[(size_t)N_NODES * 640];
__device__ float g_Hu[N_NODES * HH];
__device__ float g_gv[N_GRAPHS * DD];
__device__ float g_gv2[N_GRAPHS * DD];
__device__ int   g_deg[2 * N_NODES];
__device__ int   g_cur[2 * N_NODES];
__device__ int   g_eidt[N_EDGES];
__device__ int   g_eidf[N_EDGES];
__device__ float g_WE[16 * 512];
__device__ float g_c[512];
__device__ float g_Wcat[128 * 1024];
__device__ float g_Vcat[640 * 256];
__device__ float g_bias3[768];

#define OFF_CAT 0
#define OFF_UPD 131072
#define OFF_UW2 294912
#define OFF_AW1 327680
#define OFF_ENW 360448
#define OFF_WET 364544
#define BPOOL   372736
__device__ __nv_bfloat16 g_Bh[BPOOL];
__device__ __nv_bfloat16 g_Bl[BPOOL];

// ---------------- helpers ---------------------------------------------------
__device__ __forceinline__ void red_add_v4(float* addr, float4 v) {
    asm volatile("red.global.add.v4.f32 [%0], {%1,%2,%3,%4};"
                 :: "l"(addr), "f"(v.x), "f"(v.y), "f"(v.z), "f"(v.w) : "memory");
}
__device__ __forceinline__ uint32_t packlo2(float a, float b) {
    uint32_t r;
    asm("cvt.rn.bf16x2.f32 %0, %1, %2;" : "=r"(r) : "f"(b), "f"(a));
    return r;
}
__device__ __forceinline__ uint32_t smem_u32(const void* p) {
    uint32_t a;
    asm("{ .reg .u64 t; cvta.to.shared.u64 t, %1; cvt.u32.u64 %0, t; }" : "=r"(a) : "l"(p));
    return a;
}
__device__ __forceinline__ void mma16816(float* c, const uint32_t* a, const uint32_t* b) {
    asm("mma.sync.aligned.m16n8k16.row.col.f32.bf16.bf16.f32 "
        "{%0,%1,%2,%3}, {%4,%5,%6,%7}, {%8,%9}, {%0,%1,%2,%3};"
        : "+f"(c[0]), "+f"(c[1]), "+f"(c[2]), "+f"(c[3])
        : "r"(a[0]), "r"(a[1]), "r"(a[2]), "r"(a[3]), "r"(b[0]), "r"(b[1]));
}
#define LDSM4(r, addr)                                                         \
    asm volatile("ldmatrix.sync.aligned.m8n8.x4.shared.b16 {%0,%1,%2,%3}, [%4];" \
        : "=r"((r)[0]), "=r"((r)[1]), "=r"((r)[2]), "=r"((r)[3]) : "r"(addr))
__device__ __forceinline__ void cp16(uint32_t dst, const void* src) {
    asm volatile("cp.async.cg.shared.global [%0], [%1], 16;" :: "r"(dst), "l"(src));
}
#define CP_COMMIT() asm volatile("cp.async.commit_group;" ::: "memory")
#define CP_WAIT0()  asm volatile("cp.async.wait_group 0;" ::: "memory")

__global__ void zero_k(float4* p, int n4) {
    int i = blockIdx.x * 256 + threadIdx.x;
    if (i < n4) p[i] = make_float4(0.f, 0.f, 0.f, 0.f);
}

// ---------------- merged weight prep ---------------------------------------
__global__ void prep_w_k(const float* __restrict__ enc_we, const float* __restrict__ enc_be,
                         const float* __restrict__ mw1, const float* __restrict__ mb1,
                         const float* __restrict__ rw1, const float* __restrict__ rb1,
                         const float* __restrict__ mw2, const float* __restrict__ rw2,
                         const float* __restrict__ uw1, const float* __restrict__ mb2,
                         const float* __restrict__ rmb2, const float* __restrict__ ub1) {
    int b = blockIdx.x, tid = threadIdx.x;
    if (b < 512) {
        int idx = b * 256 + tid;
        int d = idx >> 10, c = idx & 1023;
        float v;
        if      (c < 256) v = mw1[d * 256 + c];
        else if (c < 512) v = mw1[(128 + d) * 256 + (c - 256)];
        else if (c < 768) v = rw1[d * 256 + (c - 512)];
        else              v = rw1[(128 + d) * 256 + (c - 768)];
        g_Wcat[idx] = v;
    } else if (b < 1152) {
        int r = b - 512, n = tid;
        float acc = 0.f;
        if (r < 256) {
            for (int d = 0; d < 128; d++)
                acc = fmaf(mw2[r * 128 + d], uw1[d * 256 + n], acc);
        } else if (r < 512) {
            int k = r - 256;
            for (int d = 0; d < 128; d++)
                acc = fmaf(rw2[k * 128 + d], uw1[(128 + d) * 256 + n], acc);
        } else {
            acc = uw1[(256 + r - 512) * 256 + n];
        }
        g_Vcat[r * 256 + n] = acc;
        if (r == 0) {
            float c1 = 0.f, c2 = 0.f;
            for (int d = 0; d < 128; d++) {
                c1 = fmaf(mb2[d], uw1[d * 256 + n], c1);
                c2 = fmaf(rmb2[d], uw1[(128 + d) * 256 + n], c2);
            }
            g_bias3[n] = ub1[n];
            g_bias3[256 + n] = c1;
            g_bias3[512 + n] = c2;
        }
    } else {
        for (int j = tid; j < 512; j += 256) {
            const float* W1 = (j < 256) ? mw1 : rw1;
            const float* b1 = (j < 256) ? mb1 : rb1;
            int jc = j & 255;
            for (int k = 0; k < 16; k++) {
                float acc = 0.f;
                for (int d = 0; d < 128; d++)
                    acc = fmaf(enc_we[k * 128 + d], W1[(256 + d) * 256 + jc], acc);
                g_WE[k * 512 + j] = acc;
            }
            float acc = b1[jc];
            for (int d = 0; d < 128; d++)
                acc = fmaf(enc_be[d], W1[(256 + d) * 256 + jc], acc);
            g_c[j] = acc;
        }
    }
}

__device__ __forceinline__ void spt_one(const float* W, int off, int K, int N, int idx) {
    if (idx >= K * N) return;
    int k = idx / N, n = idx % N;
    float v = W[idx];
    uint32_t xu = __float_as_uint(v);
    unsigned short hb = (unsigned short)(xu >> 16);
    float hf = __uint_as_float(xu & 0xFFFF0000u);
    __nv_bfloat16 l = __float2bfloat16(v - hf);
    union { unsigned short s; __nv_bfloat16 b; } u; u.s = hb;
    g_Bh[off + (size_t)n * K + k] = u.b;
    g_Bl[off + (size_t)n * K + k] = l;
}
__global__ void spt_all_k(const float* __restrict__ uw2, const float* __restrict__ aw1,
                          const float* __restrict__ enc_wn) {
    int b = blockIdx.x, tid = threadIdx.x;
    if      (b < 512)  spt_one(g_Wcat, OFF_CAT, 128, 1024, b * 256 + tid);
    else if (b < 1152) spt_one(g_Vcat, OFF_UPD, 640, 256, (b - 512) * 256 + tid);
    else if (b < 1280) spt_one(uw2,    OFF_UW2, 256, 128, (b - 1152) * 256 + tid);
    else if (b < 1408) spt_one(aw1,    OFF_AW1, 128, 256, (b - 1280) * 256 + tid);
    else if (b < 1424) spt_one(enc_wn, OFF_ENW, 32, 128,  (b - 1408) * 256 + tid);
    else               spt_one(g_WE,   OFF_WET, 16, 512,  (b - 1424) * 256 + tid);
}

__global__ void hist_k(const int* __restrict__ from, const int* __restrict__ to) {
    int i = blockIdx.x * 256 + threadIdx.x;
    if (i >= N_EDGES) return;
    atomicAdd(&g_deg[to[i]], 1);
    atomicAdd(&g_deg[N_NODES + from[i]], 1);
}

__global__ void scan_k() {
    __shared__ int part[1024];
    const int* deg = g_deg + blockIdx.x * N_NODES;
    int* cur = g_cur + blockIdx.x * N_NODES;
    int tid = threadIdx.x;
    int base = tid * 30;
    int local[30];
    int s = 0;
    #pragma unroll
    for (int i = 0; i < 30; i++) {
        int idx = base + i;
        int v = (idx < N_NODES) ? deg[idx] : 0;
        local[i] = s; s += v;
    }
    part[tid] = s;
    __syncthreads();
    for (int d = 1; d < 1024; d <<= 1) {
        int v = (tid >= d) ? part[tid - d] : 0;
        __syncthreads();
        part[tid] += v;
        __syncthreads();
    }
    int pre = (tid > 0) ? part[tid - 1] : 0;
    #pragma unroll
    for (int i = 0; i < 30; i++) {
        int idx = base + i;
        if (idx < N_NODES) cur[idx] = pre + local[i];
    }
}

__global__ void build_k(const int* __restrict__ from, const int* __restrict__ to) {
    int e = blockIdx.x * 256 + threadIdx.x;
    if (e >= N_EDGES) return;
    int pt = atomicAdd(&g_cur[to[e]], 1);
    g_eidt[pt] = e;
    int pf = atomicAdd(&g_cur[N_NODES + from[e]], 1);
    g_eidf[pf] = e;
}

// ---------------- pipelined warp-MMA split-bf16 GEMM ------------------------
#define AST 20
#define SSTW (128 * AST)
#define STGW (4 * SSTW)
#define TG_DSMEM (2 * STGW * 4)

__global__ void __launch_bounds__(256, 2) tgemm_k(
    const float* __restrict__ A, int lda, int K,
    const __nv_bfloat16* __restrict__ Bh, const __nv_bfloat16* __restrict__ Bl,
    const float* __restrict__ bias, const int* __restrict__ rs1,
    const int* __restrict__ rs2,
    float* __restrict__ C, int ldc, int M, int N, int flags)
{
    extern __shared__ __align__(16) uint32_t dsm[];
    const uint32_t sb = smem_u32(dsm);
    const int tid = threadIdx.x, wid = tid >> 5, lane = tid & 31;
    const int g = lane >> 2, t = lane & 3;
    const int m0 = blockIdx.x * 128, n0 = blockIdx.y * 128;
    const int mbase = (wid & 3) * 32, nbase = (wid >> 2) * 64;
    const int lrow = (lane & 7) + ((lane >> 3) & 1) * 8;
    const int lcol = ((lane >> 4) & 1) * 4;

    float acc[2][8][4];
    #pragma unroll
    for (int i = 0; i < 2; i++)
        #pragma unroll
        for (int j = 0; j < 8; j++)
            #pragma unroll
            for (int q = 0; q < 4; q++) acc[i][j][q] = 0.f;

    const int arow = tid >> 1, ahalf = tid & 1;
    const bool mok = (m0 + arow) < M;
    const float* Ap = A + (size_t)(m0 + arow) * lda;
    const __nv_bfloat16* Bhp = Bh + (size_t)(n0 + arow) * K + ahalf * 16;
    const __nv_bfloat16* Blp = Bl + (size_t)(n0 + arow) * K + ahalf * 16;
    const uint32_t bWord = (uint32_t)(arow * AST + ahalf * 8);

    float4 areg[4];
    const int nchunk = K >> 5;

    #pragma unroll
    for (int j = 0; j < 4; j++)
        areg[j] = mok ? *(const float4*)(Ap + ahalf * 16 + j * 4)
                      : make_float4(0.f, 0.f, 0.f, 0.f);
    {
        uint32_t bbase = sb + 2 * SSTW * 4;
        cp16(bbase + bWord * 4, Bhp);
        cp16(bbase + (bWord + 4) * 4, Bhp + 8);
        cp16(bbase + SSTW * 4 + bWord * 4, Blp);
        cp16(bbase + SSTW * 4 + (bWord + 4) * 4, Blp + 8);
        CP_COMMIT();
    }
    {
        uint32_t* pAh = dsm + bWord;
        uint32_t* pAl = dsm + SSTW + bWord;
        #pragma unroll
        for (int j = 0; j < 4; j++) {
            float4 v = areg[j];
            uint32_t x0 = __float_as_uint(v.x), x1 = __float_as_uint(v.y);
            uint32_t x2 = __float_as_uint(v.z), x3 = __float_as_uint(v.w);
            pAh[j * 2]     = (x1 & 0xFFFF0000u) | (x0 >> 16);
            pAh[j * 2 + 1] = (x3 & 0xFFFF0000u) | (x2 >> 16);
            float l0 = v.x - __uint_as_float(x0 & 0xFFFF0000u);
            float l1 = v.y - __uint_as_float(x1 & 0xFFFF0000u);
            float l2 = v.z - __uint_as_float(x2 & 0xFFFF0000u);
            float l3 = v.w - __uint_as_float(x3 & 0xFFFF0000u);
            pAl[j * 2]     = packlo2(l0, l1);
            pAl[j * 2 + 1] = packlo2(l2, l3);
        }
    }
    CP_WAIT0();
    __syncthreads();

    for (int c = 0; c < nchunk; c++) {
        const int cur = c & 1, nxt = (c + 1) & 1;
        const bool more = (c + 1) < nchunk;
        if (more) {
            #pragma unroll
            for (int j = 0; j < 4; j++)
                areg[j] = mok ? *(const float4*)(Ap + (c + 1) * 32 + ahalf * 16 + j * 4)
                              : make_float4(0.f, 0.f, 0.f, 0.f);
            uint32_t bbase = sb + (nxt * STGW + 2 * SSTW) * 4;
            const __nv_bfloat16* bh = Bhp + (c + 1) * 32;
            const __nv_bfloat16* bl = Blp + (c + 1) * 32;
            cp16(bbase + bWord * 4, bh);
            cp16(bbase + (bWord + 4) * 4, bh + 8);
            cp16(bbase + SSTW * 4 + bWord * 4, bl);
            cp16(bbase + SSTW * 4 + (bWord + 4) * 4, bl + 8);
            CP_COMMIT();
        }

        const uint32_t uAh = sb + cur * STGW * 4;
        const uint32_t uBh = uAh + 2 * SSTW * 4;
        const uint32_t dLo = SSTW * 4;
        #pragma unroll
        for (int ks = 0; ks < 2; ks++) {
            uint32_t ah[2][4], al[2][4];
            #pragma unroll
            for (int i = 0; i < 2; i++) {
                uint32_t ad = uAh + (uint32_t)(((mbase + 16 * i + lrow) * AST + ks * 8 + lcol) * 4);
                LDSM4(ah[i], ad);
                LDSM4(al[i], ad + dLo);
            }
            uint32_t bh[2][4], bl[2][4];
            {
                uint32_t bd = uBh + (uint32_t)(((nbase + lrow) * AST + ks * 8 + lcol) * 4);
                LDSM4(bh[0], bd);
                LDSM4(bl[0], bd + dLo);
            }
            #pragma unroll
            for (int jj = 0; jj < 4; jj++) {
                const int cb = jj & 1, nb = cb ^ 1;
                if (jj < 3) {
                    uint32_t bd = uBh + (uint32_t)(((nbase + 16 * (jj + 1) + lrow) * AST + ks * 8 + lcol) * 4);
                    LDSM4(bh[nb], bd);
                    LDSM4(bl[nb], bd + dLo);
                }
                uint32_t b0[2] = { bh[cb][0], bh[cb][2] }, b1[2] = { bh[cb][1], bh[cb][3] };
                uint32_t c0[2] = { bl[cb][0], bl[cb][2] }, c1[2] = { bl[cb][1], bl[cb][3] };
                int j0 = 2 * jj, j1 = 2 * jj + 1;
                mma16816(acc[0][j0], ah[0], b0);
                mma16816(acc[1][j0], ah[1], b0);
                mma16816(acc[0][j1], ah[0], b1);
                mma16816(acc[1][j1], ah[1], b1);
                mma16816(acc[0][j0], al[0], b0);
                mma16816(acc[1][j0], al[1], b0);
                mma16816(acc[0][j1], al[0], b1);
                mma16816(acc[1][j1], al[1], b1);
                mma16816(acc[0][j0], ah[0], c0);
                mma16816(acc[1][j0], ah[1], c0);
                mma16816(acc[0][j1], ah[0], c1);
                mma16816(acc[1][j1], ah[1], c1);
            }
        }

        if (more) {
            uint32_t* pAh = dsm + nxt * STGW + bWord;
            uint32_t* pAl = pAh + SSTW;
            #pragma unroll
            for (int j = 0; j < 4; j++) {
                float4 v = areg[j];
                uint32_t x0 = __float_as_uint(v.x), x1 = __float_as_uint(v.y);
                uint32_t x2 = __float_as_uint(v.z), x3 = __float_as_uint(v.w);
                pAh[j * 2]     = (x1 & 0xFFFF0000u) | (x0 >> 16);
                pAh[j * 2 + 1] = (x3 & 0xFFFF0000u) | (x2 >> 16);
                float l0 = v.x - __uint_as_float(x0 & 0xFFFF0000u);
                float l1 = v.y - __uint_as_float(x1 & 0xFFFF0000u);
                float l2 = v.z - __uint_as_float(x2 & 0xFFFF0000u);
                float l3 = v.w - __uint_as_float(x3 & 0xFFFF0000u);
                pAl[j * 2]     = packlo2(l0, l1);
                pAl[j * 2 + 1] = packlo2(l2, l3);
            }
            CP_WAIT0();
        }
        __syncthreads();
    }

    #pragma unroll
    for (int i = 0; i < 2; i++) {
        #pragma unroll
        for (int rr = 0; rr < 2; rr++) {
            int row = m0 + mbase + 16 * i + g + 8 * rr;
            if (row >= M) continue;
            float r1 = 0.f, r2 = 0.f;
            if (flags & FLAG_BIAS3) { r1 = (float)rs1[row]; r2 = (float)rs2[row]; }
            float* crow = C + (size_t)row * ldc;
            #pragma unroll
            for (int j = 0; j < 8; j++) {
                int nn = n0 + nbase + 8 * j + 2 * t;
                float2 v = make_float2(acc[i][j][2 * rr], acc[i][j][2 * rr + 1]);
                if (flags & FLAG_BIAS3) {
                    v.x += bias[nn] + r1 * bias[256 + nn] + r2 * bias[512 + nn];
                    v.y += bias[nn + 1] + r1 * bias[256 + nn + 1] + r2 * bias[512 + nn + 1];
                } else if (bias) {
                    v.x += bias[nn]; v.y += bias[nn + 1];
                }
                if (flags & FLAG_ADDC) {
                    float2 c0 = *(const float2*)(crow + nn);
                    v.x += c0.x; v.y += c0.y;
                }
                if (flags & FLAG_RELU) {
                    v.x = fmaxf(v.x, 0.f); v.y = fmaxf(v.y, 0.f);
                }
                if (flags & FLAG_FP16OUT) {
                    *(__half2*)((__half*)C + (size_t)row * ldc + nn) =
                        __floats2half2_rn(v.x, v.y);
                } else {
                    *(float2*)(crow + nn) = v;
                }
                if (flags & FLAG_COPYSH)
                    *(float2*)(g_SH + (size_t)row * 640 + 512 + nn) = v;
                if ((flags & FLAG_ZEROSH) && nn < 512)
                    *(float2*)(g_SH + (size_t)row * 640 + nn) = make_float2(0.f, 0.f);
            }
        }
    }
}

// ---------------- CSR-sorted fused edge pass (both dirs, one launch) --------
#define CASTE 12
#define ECST 132
#define oAh 0
#define oAl 6144
#define oWh 12288
#define oWl 18432
#define oEc 24576
#define oCc 92160
#define oEi 94208
#define oDs 94720
#define oSr 95232
#define ESMEM 95744
#define GEB ((N_EDGES + 127) / 128)

__global__ void __launch_bounds__(256) edge_csr_k(
    const float* __restrict__ ef, const int* __restrict__ from,
    const int* __restrict__ to)
{
    extern __shared__ __align__(16) char esm[];
    const uint32_t sb = smem_u32(esm);
    float* Ech = (float*)(esm + oEc);
    float* scf = (float*)(esm + oCc);
    int* sEid = (int*)(esm + oEi);
    int* sDest = (int*)(esm + oDs);
    int* sSrc = (int*)(esm + oSr);

    const int tid = threadIdx.x, wid = tid >> 5, lane = tid & 31;
    const int g = lane >> 2, t = lane & 3;
    const int mbase = (wid & 3) * 32, nbase = (wid >> 2) * 64;
    const int lrow = (lane & 7) + ((lane >> 3) & 1) * 8;
    const int lcol = ((lane >> 4) & 1) * 4;

    const int dir = (blockIdx.x >= GEB) ? 1 : 0;
    const int p0 = (blockIdx.x - dir * GEB) * 128;
    const int cnt = (N_EDGES - p0 < 128) ? (N_EDGES - p0) : 128;
    const int* eidArr = dir ? g_eidf : g_eidt;
    const int* dstArr = dir ? from : to;
    const int* srcArr = dir ? to : from;

    if (tid < 128) {
        int p = p0 + tid;
        int e = (p < N_EDGES) ? eidArr[p] : -1;
        sEid[tid] = e;
        sDest[tid] = (e >= 0) ? dstArr[e] : -1;
        sSrc[tid] = (e >= 0) ? srcArr[e] : 0;
    }
    for (int i = tid; i < 512; i += 256) scf[i] = g_c[i];
    __syncthreads();

    {
        int row = tid >> 1, half = tid & 1;
        int e = sEid[row];
        float4 v0 = make_float4(0.f, 0.f, 0.f, 0.f), v1 = v0;
        if (e >= 0) {
            v0 = *(const float4*)(ef + (size_t)e * 16 + half * 8);
            v1 = *(const float4*)(ef + (size_t)e * 16 + half * 8 + 4);
        }
        uint32_t* pAh = (uint32_t*)(esm + oAh) + row * CASTE + half * 4;
        uint32_t* pAl = (uint32_t*)(esm + oAl) + row * CASTE + half * 4;
        #pragma unroll
        for (int q = 0; q < 2; q++) {
            float4 v = q ? v1 : v0;
            uint32_t x0 = __float_as_uint(v.x), x1 = __float_as_uint(v.y);
            uint32_t x2 = __float_as_uint(v.z), x3 = __float_as_uint(v.w);
            pAh[2 * q]     = (x1 & 0xFFFF0000u) | (x0 >> 16);
            pAh[2 * q + 1] = (x3 & 0xFFFF0000u) | (x2 >> 16);
            float l0 = v.x - __uint_as_float(x0 & 0xFFFF0000u);
            float l1 = v.y - __uint_as_float(x1 & 0xFFFF0000u);
            float l2 = v.z - __uint_as_float(x2 & 0xFFFF0000u);
            float l3 = v.w - __uint_as_float(x3 & 0xFFFF0000u);
            pAl[2 * q]     = packlo2(l0, l1);
            pAl[2 * q + 1] = packlo2(l2, l3);
        }
    }
    __syncthreads();

    uint32_t ah[2][4], al[2][4];
    #pragma unroll
    for (int i = 0; i < 2; i++) {
        uint32_t ad = sb + oAh + (uint32_t)(((mbase + 16 * i + lrow) * CASTE + lcol) * 4);
        LDSM4(ah[i], ad);
        LDSM4(al[i], ad + (oAl - oAh));
    }

    for (int c = 0; c < 2; c++) {
        {
            int row = tid >> 1, half = tid & 1;
            const __nv_bfloat16* srcH = g_Bh + OFF_WET + (size_t)((dir * 2 + c) * 128 + row) * 16 + half * 8;
            const __nv_bfloat16* srcL = g_Bl + OFF_WET + (size_t)((dir * 2 + c) * 128 + row) * 16 + half * 8;
            *(uint4*)(esm + oWh + (row * CASTE + half * 4) * 4) = *(const uint4*)srcH;
            *(uint4*)(esm + oWl + (row * CASTE + half * 4) * 4) = *(const uint4*)srcL;
        }
        __syncthreads();

        float acc[2][8][4];
        #pragma unroll
        for (int i = 0; i < 2; i++)
            #pragma unroll
            for (int j = 0; j < 8; j++)
                #pragma unroll
                for (int q = 0; q < 4; q++) acc[i][j][q] = 0.f;
        #pragma unroll
        for (int jj = 0; jj < 4; jj++) {
            uint32_t bd = sb + oWh + (uint32_t)(((nbase + 16 * jj + lrow) * CASTE + lcol) * 4);
            uint32_t bh[4], bl[4];
            LDSM4(bh, bd);
            LDSM4(bl, bd + (oWl - oWh));
            uint32_t b0[2] = { bh[0], bh[2] }, b1[2] = { bh[1], bh[3] };
            uint32_t c0[2] = { bl[0], bl[2] }, c1[2] = { bl[1], bl[3] };
            int j0 = 2 * jj, j1 = 2 * jj + 1;
            mma16816(acc[0][j0], ah[0], b0);
            mma16816(acc[1][j0], ah[1], b0);
            mma16816(acc[0][j1], ah[0], b1);
            mma16816(acc[1][j1], ah[1], b1);
            mma16816(acc[0][j0], al[0], b0);
            mma16816(acc[1][j0], al[1], b0);
            mma16816(acc[0][j1], al[0], b1);
            mma16816(acc[1][j1], al[1], b1);
            mma16816(acc[0][j0], ah[0], c0);
            mma16816(acc[1][j0], ah[1], c0);
            mma16816(acc[0][j1], ah[0], c1);
            mma16816(acc[1][j1], ah[1], c1);
        }
        #pragma unroll
        for (int i = 0; i < 2; i++)
            #pragma unroll
            for (int rr = 0; rr < 2; rr++) {
                int row = mbase + 16 * i + g + 8 * rr;
                #pragma unroll
                for (int j = 0; j < 8; j++) {
                    int col = nbase + 8 * j + 2 * t;
                    *(float2*)&Ech[row * ECST + col] =
                        make_float2(acc[i][j][2 * rr], acc[i][j][2 * rr + 1]);
                }
            }
        __syncthreads();

        // ---- segmented consume: fp16 PQ gathers + depth-1 scalar prefetch ----
        {
            const int coff = c * 128 + lane * 4;
            const int rbeg = wid * 16;
            const int rend = (rbeg + 16 < cnt) ? rbeg + 16 : cnt;
            if (rbeg < rend) {
                float4 bias4 = *(float4*)&scf[dir * 256 + coff];
                const size_t pOff = (size_t)(dir * 512 + coff);
                int cur = sDest[rbeg];
                uint2 pN = *(const uint2*)(g_PQh + (size_t)sSrc[rbeg] * 1024 + pOff);
                uint2 qN = *(const uint2*)(g_PQh + (size_t)cur * 1024 + pOff + 256);
                float4 a4 = make_float4(0.f, 0.f, 0.f, 0.f);
                bool first = true;
                for (int r = rbeg; r < rend; r++) {
                    uint2 pr = pN, qr = qN;
                    if (r + 1 < rend) {
                        pN = *(const uint2*)(g_PQh + (size_t)sSrc[r + 1] * 1024 + pOff);
                        qN = *(const uint2*)(g_PQh + (size_t)sDest[r + 1] * 1024 + pOff + 256);
                    }
                    int d = sDest[r];
                    if (d != cur) {
                        float* dst = g_SH + (size_t)cur * 640 + dir * 256 + coff;
                        if (first) red_add_v4(dst, a4);
                        else *(float4*)dst = a4;
                        first = false;
                        a4 = make_float4(0.f, 0.f, 0.f, 0.f);
                        cur = d;
                    }
                    float2 p01 = __half22float2(*(__half2*)&pr.x);
                    float2 p23 = __half22float2(*(__half2*)&pr.y);
                    float2 q01 = __half22float2(*(__half2*)&qr.x);
                    float2 q23 = __half22float2(*(__half2*)&qr.y);
                    float4 e4 = *(float4*)&Ech[r * ECST + lane * 4];
                    a4.x += fmaxf(p01.x + q01.x + e4.x + bias4.x, 0.f);
                    a4.y += fmaxf(p01.y + q01.y + e4.y + bias4.y, 0.f);
                    a4.z += fmaxf(p23.x + q23.x + e4.z + bias4.z, 0.f);
                    a4.w += fmaxf(p23.y + q23.y + e4.w + bias4.w, 0.f);
                }
                bool complete = (!first) && (rend < cnt) && (sDest[rend] != cur);
                float* dst = g_SH + (size_t)cur * 640 + dir * 256 + coff;
                if (complete) *(float4*)dst = a4;
                else red_add_v4(dst, a4);
            }
        }
        __syncthreads();
    }
}

// ---------------- tail kernels ----------------------------------------------
__global__ void gate_k(const int* __restrict__ gidx) {
    int idx = blockIdx.x * 256 + threadIdx.x;
    if (idx >= N_NODES * 32) return;
    int n = idx >> 5, c4 = (idx & 31) * 4;
    const float* gr = g_Hu + (size_t)n * 256;
    float4 a = *(const float4*)&gr[c4];
    float4 b = *(const float4*)&gr[128 + c4];
    float4 v;
    v.x = b.x / (1.f + expf(-a.x));
    v.y = b.y / (1.f + expf(-a.y));
    v.z = b.z / (1.f + expf(-a.z));
    v.w = b.w / (1.f + expf(-a.w));
    red_add_v4(&g_gv[gidx[n] * 128 + c4], v);
}

__global__ void gv2_k(const float* __restrict__ W, const float* __restrict__ b) {
    __shared__ float row[128];
    int r = blockIdx.x, d = threadIdx.x;
    row[d] = g_gv[r * 128 + d];
    __syncthreads();
    float acc = b[d];
    #pragma unroll 8
    for (int k = 0; k < 128; k++) acc = fmaf(row[k], W[k * 128 + d], acc);
    g_gv2[r * 128 + d] = acc;
}

__global__ void out_k(float* __restrict__ out) {
    __shared__ float sdata[128];
    int p = blockIdx.x, t = threadIdx.x;
    float dxy = g_gv2[(2 * p) * 128 + t] - g_gv2[(2 * p + 1) * 128 + t];
    sdata[t] = dxy * dxy;
    __syncthreads();
    for (int s = 64; s > 0; s >>= 1) {
        if (t < s) sdata[t] += sdata[t + s];
        __syncthreads();
    }
    if (t == 0) out[p] = -sdata[0];
}

// ---------------- host launch ----------------------------------------------
static void* sym(const void* s) { void* p = nullptr; cudaGetSymbolAddress(&p, s); return p; }

extern "C" void kernel_launch(void* const* d_in, const int* in_sizes, int n_in,
                              void* d_out, int out_size) {
    const float* nf     = (const float*)d_in[0];
    const float* ef     = (const float*)d_in[1];
    const int*   from   = (const int*)d_in[2];
    const int*   to     = (const int*)d_in[3];
    const int*   gidx   = (const int*)d_in[4];
    const float* enc_wn = (const float*)d_in[5];
    const float* enc_bn = (const float*)d_in[6];
    const float* enc_we = (const float*)d_in[7];
    const float* enc_be = (const float*)d_in[8];
    const float* msg_w1 = (const float*)d_in[9];
    const float* msg_b1 = (const float*)d_in[10];
    const float* msg_w2 = (const float*)d_in[11];
    const float* msg_b2 = (const float*)d_in[12];
    const float* rmsg_w1= (const float*)d_in[13];
    const float* rmsg_b1= (const float*)d_in[14];
    const float* rmsg_w2= (const float*)d_in[15];
    const float* rmsg_b2= (const float*)d_in[16];
    const float* upd_w1 = (const float*)d_in[17];
    const float* upd_b1 = (const float*)d_in[18];
    const float* upd_w2 = (const float*)d_in[19];
    const float* upd_b2 = (const float*)d_in[20];
    const float* agg_w1 = (const float*)d_in[21];
    const float* agg_b1 = (const float*)d_in[22];
    const float* agg_w2 = (const float*)d_in[23];
    const float* agg_b2 = (const float*)d_in[24];
    float* out = (float*)d_out;

    float* p_h    = (float*)sym(g_h);
    __half* p_PQh = (__half*)sym(g_PQh);
    float* p_SH   = (float*)sym(g_SH);
    float* p_Hu   = (float*)sym(g_Hu);
    float* p_gv   = (float*)sym(g_gv);
    float* p_b3   = (float*)sym(g_bias3);
    int*   p_deg  = (int*)sym(g_deg);
    __nv_bfloat16* p_Bh = (__nv_bfloat16*)sym(g_Bh);
    __nv_bfloat16* p_Bl = (__nv_bfloat16*)sym(g_Bl);

    cudaFuncSetAttribute(tgemm_k, cudaFuncAttributeMaxDynamicSharedMemorySize, TG_DSMEM);
    cudaFuncSetAttribute(edge_csr_k, cudaFuncAttributeMaxDynamicSharedMemorySize, ESMEM);

    const int GM = (N_NODES + 127) / 128;   // 235

    prep_w_k<<<1153, 256>>>(enc_we, enc_be, msg_w1, msg_b1, rmsg_w1, rmsg_b1,
                            msg_w2, rmsg_w2, upd_w1, msg_b2, rmsg_b2, upd_b1);
    spt_all_k<<<1456, 256>>>(upd_w2, agg_w1, enc_wn);
    tgemm_k<<<dim3(GM, 1), 256, TG_DSMEM>>>(nf, 32, 32, p_Bh + OFF_ENW, p_Bl + OFF_ENW,
                                            enc_bn, nullptr, nullptr, p_h, 128, N_NODES, 128,
                                            FLAG_COPYSH);
    tgemm_k<<<dim3(GM, 8), 256, TG_DSMEM>>>(p_h, 128, 128, p_Bh + OFF_CAT, p_Bl + OFF_CAT,
                                            nullptr, nullptr, nullptr, (float*)p_PQh, 1024,
                                            N_NODES, 1024, FLAG_ZEROSH | FLAG_FP16OUT);
    zero_k<<<(2 * N_NODES / 4 + 255) / 256, 256>>>((float4*)p_deg, 2 * N_NODES / 4);
    hist_k<<<(N_EDGES + 255) / 256, 256>>>(from, to);
    scan_k<<<2, 1024>>>();
    build_k<<<(N_EDGES + 255) / 256, 256>>>(from, to);

    for (int l = 0; l < NLAYERS; l++) {
        if (l > 0)
            tgemm_k<<<dim3(GM, 8), 256, TG_DSMEM>>>(p_h, 128, 128, p_Bh + OFF_CAT, p_Bl + OFF_CAT,
                                                    nullptr, nullptr, nullptr, (float*)p_PQh, 1024,
                                                    N_NODES, 1024, FLAG_ZEROSH | FLAG_FP16OUT);
        edge_csr_k<<<2 * GEB, 256, ESMEM>>>(ef, from, to);
        tgemm_k<<<dim3(GM, 2), 256, TG_DSMEM>>>(p_SH, 640, 640, p_Bh + OFF_UPD, p_Bl + OFF_UPD,
                                                p_b3, p_deg, p_deg + N_NODES, p_Hu, 256, N_NODES, 256,
                                                FLAG_RELU | FLAG_BIAS3);
        int fl = FLAG_ADDC | ((l < NLAYERS - 1) ? FLAG_COPYSH : 0);
        tgemm_k<<<dim3(GM, 1), 256, TG_DSMEM>>>(p_Hu, 256, 256, p_Bh + OFF_UW2, p_Bl + OFF_UW2,
                                                upd_b2, nullptr, nullptr, p_h, 128, N_NODES, 128, fl);
    }

    tgemm_k<<<dim3(GM, 2), 256, TG_DSMEM>>>(p_h, 128, 128, p_Bh + OFF_AW1, p_Bl + OFF_AW1,
                                            agg_b1, nullptr, nullptr, p_Hu, 256, N_NODES, 256, 0);
    zero_k<<<(N_GRAPHS * 32 + 255) / 256, 256>>>((float4*)p_gv, N_GRAPHS * 32);
    gate_k<<<(N_NODES * 32 + 255) / 256, 256>>>(gidx);
    gv2_k<<<N_GRAPHS, 128>>>(agg_w2, agg_b2);
    out_k<<<128, 128>>>(out);
    (void)in_sizes; (void)n_in; (void)out_size;
}

// round 15
// speedup vs baseline: 1.5034x; 1.1232x over previous
#include <cuda_runtime.h>
#include <cuda_bf16.h>
#include <cuda_fp16.h>
#include <math.h>
#include <stdint.h>

#define N_NODES 30000
#define N_EDGES 300000
#define N_GRAPHS 256
#define DD 128
#define HH 256
#define NLAYERS 3

#define FLAG_RELU 1
#define FLAG_ADDC 2
#define FLAG_BIAS3 4
#define FLAG_COPYSH 8
#define FLAG_ZEROSH 16
#define FLAG_FP16OUT 32

// ---------------- scratch -------------------------------------------------
__device__ float g_h[N_NODES * DD];
__device__ __half g_PQh[(size_t)N_NODES * 1024];   // fp16 PQ (61 MB, L2-resident)
__device__ float g_SH[(size_t)N_NODES * 640];
__device__ float g_Hu[N_NODES * HH];
__device__ float g_gv[N_GRAPHS * DD];
__device__ float g_gv2[N_GRAPHS * DD];
__device__ int   g_deg[2 * N_NODES];
__device__ int   g_cur[2 * N_NODES];
__device__ int   g_eidt[N_EDGES];
__device__ int   g_eidf[N_EDGES];
__device__ float g_WE[16 * 512];
__device__ float g_c[512];
__device__ float g_Wcat[128 * 1024];
__device__ float g_Vcat[640 * 256];
__device__ float g_bias3[768];

#define OFF_CAT 0
#define OFF_UPD 131072
#define OFF_UW2 294912
#define OFF_AW1 327680
#define OFF_ENW 360448
#define OFF_WET 364544
#define BPOOL   372736
__device__ __nv_bfloat16 g_Bh[BPOOL];
__device__ __nv_bfloat16 g_Bl[BPOOL];

// ---------------- helpers ---------------------------------------------------
__device__ __forceinline__ void red_add_v4(float* addr, float4 v) {
    asm volatile("red.global.add.v4.f32 [%0], {%1,%2,%3,%4};"
                 :: "l"(addr), "f"(v.x), "f"(v.y), "f"(v.z), "f"(v.w) : "memory");
}
__device__ __forceinline__ uint32_t packlo2(float a, float b) {
    uint32_t r;
    asm("cvt.rn.bf16x2.f32 %0, %1, %2;" : "=r"(r) : "f"(b), "f"(a));
    return r;
}
__device__ __forceinline__ uint32_t smem_u32(const void* p) {
    uint32_t a;
    asm("{ .reg .u64 t; cvta.to.shared.u64 t, %1; cvt.u32.u64 %0, t; }" : "=r"(a) : "l"(p));
    return a;
}
__device__ __forceinline__ void mma16816(float* c, const uint32_t* a, const uint32_t* b) {
    asm("mma.sync.aligned.m16n8k16.row.col.f32.bf16.bf16.f32 "
        "{%0,%1,%2,%3}, {%4,%5,%6,%7}, {%8,%9}, {%0,%1,%2,%3};"
        : "+f"(c[0]), "+f"(c[1]), "+f"(c[2]), "+f"(c[3])
        : "r"(a[0]), "r"(a[1]), "r"(a[2]), "r"(a[3]), "r"(b[0]), "r"(b[1]));
}
#define LDSM4(r, addr)                                                         \
    asm volatile("ldmatrix.sync.aligned.m8n8.x4.shared.b16 {%0,%1,%2,%3}, [%4];" \
        : "=r"((r)[0]), "=r"((r)[1]), "=r"((r)[2]), "=r"((r)[3]) : "r"(addr))
__device__ __forceinline__ void cp16(uint32_t dst, const void* src) {
    asm volatile("cp.async.cg.shared.global [%0], [%1], 16;" :: "r"(dst), "l"(src));
}
#define CP_COMMIT() asm volatile("cp.async.commit_group;" ::: "memory")
#define CP_WAIT0()  asm volatile("cp.async.wait_group 0;" ::: "memory")

__global__ void zero_k(float4* p, int n4) {
    int i = blockIdx.x * 256 + threadIdx.x;
    if (i < n4) p[i] = make_float4(0.f, 0.f, 0.f, 0.f);
}

// ---------------- merged weight prep ---------------------------------------
__global__ void prep_w_k(const float* __restrict__ enc_we, const float* __restrict__ enc_be,
                         const float* __restrict__ mw1, const float* __restrict__ mb1,
                         const float* __restrict__ rw1, const float* __restrict__ rb1,
                         const float* __restrict__ mw2, const float* __restrict__ rw2,
                         const float* __restrict__ uw1, const float* __restrict__ mb2,
                         const float* __restrict__ rmb2, const float* __restrict__ ub1) {
    int b = blockIdx.x, tid = threadIdx.x;
    if (b < 512) {
        int idx = b * 256 + tid;
        int d = idx >> 10, c = idx & 1023;
        float v;
        if      (c < 256) v = mw1[d * 256 + c];
        else if (c < 512) v = mw1[(128 + d) * 256 + (c - 256)];
        else if (c < 768) v = rw1[d * 256 + (c - 512)];
        else              v = rw1[(128 + d) * 256 + (c - 768)];
        g_Wcat[idx] = v;
    } else if (b < 1152) {
        int r = b - 512, n = tid;
        float acc = 0.f;
        if (r < 256) {
            for (int d = 0; d < 128; d++)
                acc = fmaf(mw2[r * 128 + d], uw1[d * 256 + n], acc);
        } else if (r < 512) {
            int k = r - 256;
            for (int d = 0; d < 128; d++)
                acc = fmaf(rw2[k * 128 + d], uw1[(128 + d) * 256 + n], acc);
        } else {
            acc = uw1[(256 + r - 512) * 256 + n];
        }
        g_Vcat[r * 256 + n] = acc;
        if (r == 0) {
            float c1 = 0.f, c2 = 0.f;
            for (int d = 0; d < 128; d++) {
                c1 = fmaf(mb2[d], uw1[d * 256 + n], c1);
                c2 = fmaf(rmb2[d], uw1[(128 + d) * 256 + n], c2);
            }
            g_bias3[n] = ub1[n];
            g_bias3[256 + n] = c1;
            g_bias3[512 + n] = c2;
        }
    } else {
        for (int j = tid; j < 512; j += 256) {
            const float* W1 = (j < 256) ? mw1 : rw1;
            const float* b1 = (j < 256) ? mb1 : rb1;
            int jc = j & 255;
            for (int k = 0; k < 16; k++) {
                float acc = 0.f;
                for (int d = 0; d < 128; d++)
                    acc = fmaf(enc_we[k * 128 + d], W1[(256 + d) * 256 + jc], acc);
                g_WE[k * 512 + j] = acc;
            }
            float acc = b1[jc];
            for (int d = 0; d < 128; d++)
                acc = fmaf(enc_be[d], W1[(256 + d) * 256 + jc], acc);
            g_c[j] = acc;
        }
    }
}

__device__ __forceinline__ void spt_one(const float* W, int off, int K, int N, int idx) {
    if (idx >= K * N) return;
    int k = idx / N, n = idx % N;
    float v = W[idx];
    uint32_t xu = __float_as_uint(v);
    unsigned short hb = (unsigned short)(xu >> 16);
    float hf = __uint_as_float(xu & 0xFFFF0000u);
    __nv_bfloat16 l = __float2bfloat16(v - hf);
    union { unsigned short s; __nv_bfloat16 b; } u; u.s = hb;
    g_Bh[off + (size_t)n * K + k] = u.b;
    g_Bl[off + (size_t)n * K + k] = l;
}
__global__ void spt_all_k(const float* __restrict__ uw2, const float* __restrict__ aw1,
                          const float* __restrict__ enc_wn) {
    int b = blockIdx.x, tid = threadIdx.x;
    if      (b < 512)  spt_one(g_Wcat, OFF_CAT, 128, 1024, b * 256 + tid);
    else if (b < 1152) spt_one(g_Vcat, OFF_UPD, 640, 256, (b - 512) * 256 + tid);
    else if (b < 1280) spt_one(uw2,    OFF_UW2, 256, 128, (b - 1152) * 256 + tid);
    else if (b < 1408) spt_one(aw1,    OFF_AW1, 128, 256, (b - 1280) * 256 + tid);
    else if (b < 1424) spt_one(enc_wn, OFF_ENW, 32, 128,  (b - 1408) * 256 + tid);
    else               spt_one(g_WE,   OFF_WET, 16, 512,  (b - 1424) * 256 + tid);
}

__global__ void hist_k(const int* __restrict__ from, const int* __restrict__ to) {
    int i = blockIdx.x * 256 + threadIdx.x;
    if (i >= N_EDGES) return;
    atomicAdd(&g_deg[to[i]], 1);
    atomicAdd(&g_deg[N_NODES + from[i]], 1);
}

__global__ void scan_k() {
    __shared__ int part[1024];
    const int* deg = g_deg + blockIdx.x * N_NODES;
    int* cur = g_cur + blockIdx.x * N_NODES;
    int tid = threadIdx.x;
    int base = tid * 30;
    int local[30];
    int s = 0;
    #pragma unroll
    for (int i = 0; i < 30; i++) {
        int idx = base + i;
        int v = (idx < N_NODES) ? deg[idx] : 0;
        local[i] = s; s += v;
    }
    part[tid] = s;
    __syncthreads();
    for (int d = 1; d < 1024; d <<= 1) {
        int v = (tid >= d) ? part[tid - d] : 0;
        __syncthreads();
        part[tid] += v;
        __syncthreads();
    }
    int pre = (tid > 0) ? part[tid - 1] : 0;
    #pragma unroll
    for (int i = 0; i < 30; i++) {
        int idx = base + i;
        if (idx < N_NODES) cur[idx] = pre + local[i];
    }
}

__global__ void build_k(const int* __restrict__ from, const int* __restrict__ to) {
    int e = blockIdx.x * 256 + threadIdx.x;
    if (e >= N_EDGES) return;
    int pt = atomicAdd(&g_cur[to[e]], 1);
    g_eidt[pt] = e;
    int pf = atomicAdd(&g_cur[N_NODES + from[e]], 1);
    g_eidf[pf] = e;
}

// ---------------- pipelined warp-MMA split-bf16 GEMM ------------------------
#define AST 20
#define SSTW (128 * AST)
#define STGW (4 * SSTW)
#define TG_DSMEM (2 * STGW * 4)

__global__ void __launch_bounds__(256, 2) tgemm_k(
    const float* __restrict__ A, int lda, int K,
    const __nv_bfloat16* __restrict__ Bh, const __nv_bfloat16* __restrict__ Bl,
    const float* __restrict__ bias, const int* __restrict__ rs1,
    const int* __restrict__ rs2,
    float* __restrict__ C, int ldc, int M, int N, int flags)
{
    extern __shared__ __align__(16) uint32_t dsm[];
    const uint32_t sb = smem_u32(dsm);
    const int tid = threadIdx.x, wid = tid >> 5, lane = tid & 31;
    const int g = lane >> 2, t = lane & 3;
    const int m0 = blockIdx.x * 128, n0 = blockIdx.y * 128;
    const int mbase = (wid & 3) * 32, nbase = (wid >> 2) * 64;
    const int lrow = (lane & 7) + ((lane >> 3) & 1) * 8;
    const int lcol = ((lane >> 4) & 1) * 4;

    float acc[2][8][4];
    #pragma unroll
    for (int i = 0; i < 2; i++)
        #pragma unroll
        for (int j = 0; j < 8; j++)
            #pragma unroll
            for (int q = 0; q < 4; q++) acc[i][j][q] = 0.f;

    const int arow = tid >> 1, ahalf = tid & 1;
    const bool mok = (m0 + arow) < M;
    const float* Ap = A + (size_t)(m0 + arow) * lda;
    const __nv_bfloat16* Bhp = Bh + (size_t)(n0 + arow) * K + ahalf * 16;
    const __nv_bfloat16* Blp = Bl + (size_t)(n0 + arow) * K + ahalf * 16;
    const uint32_t bWord = (uint32_t)(arow * AST + ahalf * 8);

    float4 areg[4];
    const int nchunk = K >> 5;

    #pragma unroll
    for (int j = 0; j < 4; j++)
        areg[j] = mok ? *(const float4*)(Ap + ahalf * 16 + j * 4)
                      : make_float4(0.f, 0.f, 0.f, 0.f);
    {
        uint32_t bbase = sb + 2 * SSTW * 4;
        cp16(bbase + bWord * 4, Bhp);
        cp16(bbase + (bWord + 4) * 4, Bhp + 8);
        cp16(bbase + SSTW * 4 + bWord * 4, Blp);
        cp16(bbase + SSTW * 4 + (bWord + 4) * 4, Blp + 8);
        CP_COMMIT();
    }
    {
        uint32_t* pAh = dsm + bWord;
        uint32_t* pAl = dsm + SSTW + bWord;
        #pragma unroll
        for (int j = 0; j < 4; j++) {
            float4 v = areg[j];
            uint32_t x0 = __float_as_uint(v.x), x1 = __float_as_uint(v.y);
            uint32_t x2 = __float_as_uint(v.z), x3 = __float_as_uint(v.w);
            pAh[j * 2]     = (x1 & 0xFFFF0000u) | (x0 >> 16);
            pAh[j * 2 + 1] = (x3 & 0xFFFF0000u) | (x2 >> 16);
            float l0 = v.x - __uint_as_float(x0 & 0xFFFF0000u);
            float l1 = v.y - __uint_as_float(x1 & 0xFFFF0000u);
            float l2 = v.z - __uint_as_float(x2 & 0xFFFF0000u);
            float l3 = v.w - __uint_as_float(x3 & 0xFFFF0000u);
            pAl[j * 2]     = packlo2(l0, l1);
            pAl[j * 2 + 1] = packlo2(l2, l3);
        }
    }
    CP_WAIT0();
    __syncthreads();

    for (int c = 0; c < nchunk; c++) {
        const int cur = c & 1, nxt = (c + 1) & 1;
        const bool more = (c + 1) < nchunk;
        if (more) {
            #pragma unroll
            for (int j = 0; j < 4; j++)
                areg[j] = mok ? *(const float4*)(Ap + (c + 1) * 32 + ahalf * 16 + j * 4)
                              : make_float4(0.f, 0.f, 0.f, 0.f);
            uint32_t bbase = sb + (nxt * STGW + 2 * SSTW) * 4;
            const __nv_bfloat16* bh = Bhp + (c + 1) * 32;
            const __nv_bfloat16* bl = Blp + (c + 1) * 32;
            cp16(bbase + bWord * 4, bh);
            cp16(bbase + (bWord + 4) * 4, bh + 8);
            cp16(bbase + SSTW * 4 + bWord * 4, bl);
            cp16(bbase + SSTW * 4 + (bWord + 4) * 4, bl + 8);
            CP_COMMIT();
        }

        const uint32_t uAh = sb + cur * STGW * 4;
        const uint32_t uBh = uAh + 2 * SSTW * 4;
        const uint32_t dLo = SSTW * 4;
        #pragma unroll
        for (int ks = 0; ks < 2; ks++) {
            uint32_t ah[2][4], al[2][4];
            #pragma unroll
            for (int i = 0; i < 2; i++) {
                uint32_t ad = uAh + (uint32_t)(((mbase + 16 * i + lrow) * AST + ks * 8 + lcol) * 4);
                LDSM4(ah[i], ad);
                LDSM4(al[i], ad + dLo);
            }
            uint32_t bh[2][4], bl[2][4];
            {
                uint32_t bd = uBh + (uint32_t)(((nbase + lrow) * AST + ks * 8 + lcol) * 4);
                LDSM4(bh[0], bd);
                LDSM4(bl[0], bd + dLo);
            }
            #pragma unroll
            for (int jj = 0; jj < 4; jj++) {
                const int cb = jj & 1, nb = cb ^ 1;
                if (jj < 3) {
                    uint32_t bd = uBh + (uint32_t)(((nbase + 16 * (jj + 1) + lrow) * AST + ks * 8 + lcol) * 4);
                    LDSM4(bh[nb], bd);
                    LDSM4(bl[nb], bd + dLo);
                }
                uint32_t b0[2] = { bh[cb][0], bh[cb][2] }, b1[2] = { bh[cb][1], bh[cb][3] };
                uint32_t c0[2] = { bl[cb][0], bl[cb][2] }, c1[2] = { bl[cb][1], bl[cb][3] };
                int j0 = 2 * jj, j1 = 2 * jj + 1;
                mma16816(acc[0][j0], ah[0], b0);
                mma16816(acc[1][j0], ah[1], b0);
                mma16816(acc[0][j1], ah[0], b1);
                mma16816(acc[1][j1], ah[1], b1);
                mma16816(acc[0][j0], al[0], b0);
                mma16816(acc[1][j0], al[1], b0);
                mma16816(acc[0][j1], al[0], b1);
                mma16816(acc[1][j1], al[1], b1);
                mma16816(acc[0][j0], ah[0], c0);
                mma16816(acc[1][j0], ah[1], c0);
                mma16816(acc[0][j1], ah[0], c1);
                mma16816(acc[1][j1], ah[1], c1);
            }
        }

        if (more) {
            uint32_t* pAh = dsm + nxt * STGW + bWord;
            uint32_t* pAl = pAh + SSTW;
            #pragma unroll
            for (int j = 0; j < 4; j++) {
                float4 v = areg[j];
                uint32_t x0 = __float_as_uint(v.x), x1 = __float_as_uint(v.y);
                uint32_t x2 = __float_as_uint(v.z), x3 = __float_as_uint(v.w);
                pAh[j * 2]     = (x1 & 0xFFFF0000u) | (x0 >> 16);
                pAh[j * 2 + 1] = (x3 & 0xFFFF0000u) | (x2 >> 16);
                float l0 = v.x - __uint_as_float(x0 & 0xFFFF0000u);
                float l1 = v.y - __uint_as_float(x1 & 0xFFFF0000u);
                float l2 = v.z - __uint_as_float(x2 & 0xFFFF0000u);
                float l3 = v.w - __uint_as_float(x3 & 0xFFFF0000u);
                pAl[j * 2]     = packlo2(l0, l1);
                pAl[j * 2 + 1] = packlo2(l2, l3);
            }
            CP_WAIT0();
        }
        __syncthreads();
    }

    #pragma unroll
    for (int i = 0; i < 2; i++) {
        #pragma unroll
        for (int rr = 0; rr < 2; rr++) {
            int row = m0 + mbase + 16 * i + g + 8 * rr;
            if (row >= M) continue;
            float r1 = 0.f, r2 = 0.f;
            if (flags & FLAG_BIAS3) { r1 = (float)rs1[row]; r2 = (float)rs2[row]; }
            float* crow = C + (size_t)row * ldc;
            #pragma unroll
            for (int j = 0; j < 8; j++) {
                int nn = n0 + nbase + 8 * j + 2 * t;
                float2 v = make_float2(acc[i][j][2 * rr], acc[i][j][2 * rr + 1]);
                if (flags & FLAG_BIAS3) {
                    v.x += bias[nn] + r1 * bias[256 + nn] + r2 * bias[512 + nn];
                    v.y += bias[nn + 1] + r1 * bias[256 + nn + 1] + r2 * bias[512 + nn + 1];
                } else if (bias) {
                    v.x += bias[nn]; v.y += bias[nn + 1];
                }
                if (flags & FLAG_ADDC) {
                    float2 c0 = *(const float2*)(crow + nn);
                    v.x += c0.x; v.y += c0.y;
                }
                if (flags & FLAG_RELU) {
                    v.x = fmaxf(v.x, 0.f); v.y = fmaxf(v.y, 0.f);
                }
                if (flags & FLAG_FP16OUT) {
                    *(__half2*)((__half*)C + (size_t)row * ldc + nn) =
                        __floats2half2_rn(v.x, v.y);
                } else {
                    *(float2*)(crow + nn) = v;
                }
                if (flags & FLAG_COPYSH)
                    *(float2*)(g_SH + (size_t)row * 640 + 512 + nn) = v;
                if ((flags & FLAG_ZEROSH) && nn < 512)
                    *(float2*)(g_SH + (size_t)row * 640 + nn) = make_float2(0.f, 0.f);
            }
        }
    }
}

// ---------------- CSR-sorted fused edge pass (both dirs, one launch) --------
// fp16 Ech; W tiles for both K-chunks preloaded once.
#define CASTE 12
#define ECSTH 132
#define oAh 0
#define oAl 6144
#define oWh 12288
#define oWl 24576
#define oEc 36864
#define oCc 70656
#define oEi 72704
#define oDs 73216
#define oSr 73728
#define ESMEM 74240
#define GEB ((N_EDGES + 127) / 128)

__global__ void __launch_bounds__(256) edge_csr_k(
    const float* __restrict__ ef, const int* __restrict__ from,
    const int* __restrict__ to)
{
    extern __shared__ __align__(16) char esm[];
    const uint32_t sb = smem_u32(esm);
    __half* Ech = (__half*)(esm + oEc);
    float* scf = (float*)(esm + oCc);
    int* sEid = (int*)(esm + oEi);
    int* sDest = (int*)(esm + oDs);
    int* sSrc = (int*)(esm + oSr);

    const int tid = threadIdx.x, wid = tid >> 5, lane = tid & 31;
    const int g = lane >> 2, t = lane & 3;
    const int mbase = (wid & 3) * 32, nbase = (wid >> 2) * 64;
    const int lrow = (lane & 7) + ((lane >> 3) & 1) * 8;
    const int lcol = ((lane >> 4) & 1) * 4;

    const int dir = (blockIdx.x >= GEB) ? 1 : 0;
    const int p0 = (blockIdx.x - dir * GEB) * 128;
    const int cnt = (N_EDGES - p0 < 128) ? (N_EDGES - p0) : 128;
    const int* eidArr = dir ? g_eidf : g_eidt;
    const int* dstArr = dir ? from : to;
    const int* srcArr = dir ? to : from;

    if (tid < 128) {
        int p = p0 + tid;
        int e = (p < N_EDGES) ? eidArr[p] : -1;
        sEid[tid] = e;
        sDest[tid] = (e >= 0) ? dstArr[e] : -1;
        sSrc[tid] = (e >= 0) ? srcArr[e] : 0;
    }
    for (int i = tid; i < 512; i += 256) scf[i] = g_c[i];
    // W tiles for BOTH K-chunks of this direction (256 rows, hi+lo)
    {
        int row = tid;   // 0..255
        const __nv_bfloat16* srcH = g_Bh + OFF_WET + (size_t)(dir * 256 + row) * 16;
        const __nv_bfloat16* srcL = g_Bl + OFF_WET + (size_t)(dir * 256 + row) * 16;
        int cc = row >> 7, rloc = row & 127;
        uint32_t wb = (uint32_t)(cc * 6144 + (rloc * CASTE) * 4);
        *(uint4*)(esm + oWh + wb) = *(const uint4*)srcH;
        *(uint4*)(esm + oWh + wb + 16) = *(const uint4*)(srcH + 8);
        *(uint4*)(esm + oWl + wb) = *(const uint4*)srcL;
        *(uint4*)(esm + oWl + wb + 16) = *(const uint4*)(srcL + 8);
    }
    __syncthreads();

    // gather + split ef rows by sorted edge id
    {
        int row = tid >> 1, half = tid & 1;
        int e = sEid[row];
        float4 v0 = make_float4(0.f, 0.f, 0.f, 0.f), v1 = v0;
        if (e >= 0) {
            v0 = *(const float4*)(ef + (size_t)e * 16 + half * 8);
            v1 = *(const float4*)(ef + (size_t)e * 16 + half * 8 + 4);
        }
        uint32_t* pAh = (uint32_t*)(esm + oAh) + row * CASTE + half * 4;
        uint32_t* pAl = (uint32_t*)(esm + oAl) + row * CASTE + half * 4;
        #pragma unroll
        for (int q = 0; q < 2; q++) {
            float4 v = q ? v1 : v0;
            uint32_t x0 = __float_as_uint(v.x), x1 = __float_as_uint(v.y);
            uint32_t x2 = __float_as_uint(v.z), x3 = __float_as_uint(v.w);
            pAh[2 * q]     = (x1 & 0xFFFF0000u) | (x0 >> 16);
            pAh[2 * q + 1] = (x3 & 0xFFFF0000u) | (x2 >> 16);
            float l0 = v.x - __uint_as_float(x0 & 0xFFFF0000u);
            float l1 = v.y - __uint_as_float(x1 & 0xFFFF0000u);
            float l2 = v.z - __uint_as_float(x2 & 0xFFFF0000u);
            float l3 = v.w - __uint_as_float(x3 & 0xFFFF0000u);
            pAl[2 * q]     = packlo2(l0, l1);
            pAl[2 * q + 1] = packlo2(l2, l3);
        }
    }
    __syncthreads();

    uint32_t ah[2][4], al[2][4];
    #pragma unroll
    for (int i = 0; i < 2; i++) {
        uint32_t ad = sb + oAh + (uint32_t)(((mbase + 16 * i + lrow) * CASTE + lcol) * 4);
        LDSM4(ah[i], ad);
        LDSM4(al[i], ad + (oAl - oAh));
    }

    for (int c = 0; c < 2; c++) {
        float acc[2][8][4];
        #pragma unroll
        for (int i = 0; i < 2; i++)
            #pragma unroll
            for (int j = 0; j < 8; j++)
                #pragma unroll
                for (int q = 0; q < 4; q++) acc[i][j][q] = 0.f;
        #pragma unroll
        for (int jj = 0; jj < 4; jj++) {
            uint32_t bd = sb + oWh + (uint32_t)(c * 6144 + ((nbase + 16 * jj + lrow) * CASTE + lcol) * 4);
            uint32_t bh[4], bl[4];
            LDSM4(bh, bd);
            LDSM4(bl, bd + (oWl - oWh));
            uint32_t b0[2] = { bh[0], bh[2] }, b1[2] = { bh[1], bh[3] };
            uint32_t c0[2] = { bl[0], bl[2] }, c1[2] = { bl[1], bl[3] };
            int j0 = 2 * jj, j1 = 2 * jj + 1;
            mma16816(acc[0][j0], ah[0], b0);
            mma16816(acc[1][j0], ah[1], b0);
            mma16816(acc[0][j1], ah[0], b1);
            mma16816(acc[1][j1], ah[1], b1);
            mma16816(acc[0][j0], al[0], b0);
            mma16816(acc[1][j0], al[1], b0);
            mma16816(acc[0][j1], al[0], b1);
            mma16816(acc[1][j1], al[1], b1);
            mma16816(acc[0][j0], ah[0], c0);
            mma16816(acc[1][j0], ah[1], c0);
            mma16816(acc[0][j1], ah[0], c1);
            mma16816(acc[1][j1], ah[1], c1);
        }
        // write Echunk as fp16
        #pragma unroll
        for (int i = 0; i < 2; i++)
            #pragma unroll
            for (int rr = 0; rr < 2; rr++) {
                int row = mbase + 16 * i + g + 8 * rr;
                #pragma unroll
                for (int j = 0; j < 8; j++) {
                    int col = nbase + 8 * j + 2 * t;
                    *(__half2*)&Ech[row * ECSTH + col] =
                        __floats2half2_rn(acc[i][j][2 * rr], acc[i][j][2 * rr + 1]);
                }
            }
        __syncthreads();

        // ---- segmented consume: fp16 gathers + depth-1 scalar prefetch ----
        {
            const int coff = c * 128 + lane * 4;
            const int rbeg = wid * 16;
            const int rend = (rbeg + 16 < cnt) ? rbeg + 16 : cnt;
            if (rbeg < rend) {
                float4 bias4 = *(float4*)&scf[dir * 256 + coff];
                const size_t pOff = (size_t)(dir * 512 + coff);
                int cur = sDest[rbeg];
                uint2 pN = *(const uint2*)(g_PQh + (size_t)sSrc[rbeg] * 1024 + pOff);
                uint2 qN = *(const uint2*)(g_PQh + (size_t)cur * 1024 + pOff + 256);
                float4 a4 = make_float4(0.f, 0.f, 0.f, 0.f);
                bool first = true;
                for (int r = rbeg; r < rend; r++) {
                    uint2 pr = pN, qr = qN;
                    if (r + 1 < rend) {
                        pN = *(const uint2*)(g_PQh + (size_t)sSrc[r + 1] * 1024 + pOff);
                        qN = *(const uint2*)(g_PQh + (size_t)sDest[r + 1] * 1024 + pOff + 256);
                    }
                    int d = sDest[r];
                    if (d != cur) {
                        float* dst = g_SH + (size_t)cur * 640 + dir * 256 + coff;
                        if (first) red_add_v4(dst, a4);
                        else *(float4*)dst = a4;
                        first = false;
                        a4 = make_float4(0.f, 0.f, 0.f, 0.f);
                        cur = d;
                    }
                    float2 p01 = __half22float2(*(__half2*)&pr.x);
                    float2 p23 = __half22float2(*(__half2*)&pr.y);
                    float2 q01 = __half22float2(*(__half2*)&qr.x);
                    float2 q23 = __half22float2(*(__half2*)&qr.y);
                    uint2 er = *(const uint2*)&Ech[r * ECSTH + lane * 4];
                    float2 e01 = __half22float2(*(__half2*)&er.x);
                    float2 e23 = __half22float2(*(__half2*)&er.y);
                    a4.x += fmaxf(p01.x + q01.x + e01.x + bias4.x, 0.f);
                    a4.y += fmaxf(p01.y + q01.y + e01.y + bias4.y, 0.f);
                    a4.z += fmaxf(p23.x + q23.x + e23.x + bias4.z, 0.f);
                    a4.w += fmaxf(p23.y + q23.y + e23.y + bias4.w, 0.f);
                }
                bool complete = (!first) && (rend < cnt) && (sDest[rend] != cur);
                float* dst = g_SH + (size_t)cur * 640 + dir * 256 + coff;
                if (complete) *(float4*)dst = a4;
                else red_add_v4(dst, a4);
            }
        }
        __syncthreads();
    }
}

// ---------------- tail kernels ----------------------------------------------
__global__ void gate_k(const int* __restrict__ gidx) {
    int idx = blockIdx.x * 256 + threadIdx.x;
    if (idx >= N_NODES * 32) return;
    int n = idx >> 5, c4 = (idx & 31) * 4;
    const float* gr = g_Hu + (size_t)n * 256;
    float4 a = *(const float4*)&gr[c4];
    float4 b = *(const float4*)&gr[128 + c4];
    float4 v;
    v.x = b.x / (1.f + expf(-a.x));
    v.y = b.y / (1.f + expf(-a.y));
    v.z = b.z / (1.f + expf(-a.z));
    v.w = b.w / (1.f + expf(-a.w));
    red_add_v4(&g_gv[gidx[n] * 128 + c4], v);
}

__global__ void gv2_k(const float* __restrict__ W, const float* __restrict__ b) {
    __shared__ float row[128];
    int r = blockIdx.x, d = threadIdx.x;
    row[d] = g_gv[r * 128 + d];
    __syncthreads();
    float acc = b[d];
    #pragma unroll 8
    for (int k = 0; k < 128; k++) acc = fmaf(row[k], W[k * 128 + d], acc);
    g_gv2[r * 128 + d] = acc;
}

__global__ void out_k(float* __restrict__ out) {
    __shared__ float sdata[128];
    int p = blockIdx.x, t = threadIdx.x;
    float dxy = g_gv2[(2 * p) * 128 + t] - g_gv2[(2 * p + 1) * 128 + t];
    sdata[t] = dxy * dxy;
    __syncthreads();
    for (int s = 64; s > 0; s >>= 1) {
        if (t < s) sdata[t] += sdata[t + s];
        __syncthreads();
    }
    if (t == 0) out[p] = -sdata[0];
}

// ---------------- host launch ----------------------------------------------
static void* sym(const void* s) { void* p = nullptr; cudaGetSymbolAddress(&p, s); return p; }

extern "C" void kernel_launch(void* const* d_in, const int* in_sizes, int n_in,
                              void* d_out, int out_size) {
    const float* nf     = (const float*)d_in[0];
    const float* ef     = (const float*)d_in[1];
    const int*   from   = (const int*)d_in[2];
    const int*   to     = (const int*)d_in[3];
    const int*   gidx   = (const int*)d_in[4];
    const float* enc_wn = (const float*)d_in[5];
    const float* enc_bn = (const float*)d_in[6];
    const float* enc_we = (const float*)d_in[7];
    const float* enc_be = (const float*)d_in[8];
    const float* msg_w1 = (const float*)d_in[9];
    const float* msg_b1 = (const float*)d_in[10];
    const float* msg_w2 = (const float*)d_in[11];
    const float* msg_b2 = (const float*)d_in[12];
    const float* rmsg_w1= (const float*)d_in[13];
    const float* rmsg_b1= (const float*)d_in[14];
    const float* rmsg_w2= (const float*)d_in[15];
    const float* rmsg_b2= (const float*)d_in[16];
    const float* upd_w1 = (const float*)d_in[17];
    const float* upd_b1 = (const float*)d_in[18];
    const float* upd_w2 = (const float*)d_in[19];
    const float* upd_b2 = (const float*)d_in[20];
    const float* agg_w1 = (const float*)d_in[21];
    const float* agg_b1 = (const float*)d_in[22];
    const float* agg_w2 = (const float*)d_in[23];
    const float* agg_b2 = (const float*)d_in[24];
    float* out = (float*)d_out;

    float* p_h    = (float*)sym(g_h);
    __half* p_PQh = (__half*)sym(g_PQh);
    float* p_SH   = (float*)sym(g_SH);
    float* p_Hu   = (float*)sym(g_Hu);
    float* p_gv   = (float*)sym(g_gv);
    float* p_b3   = (float*)sym(g_bias3);
    int*   p_deg  = (int*)sym(g_deg);
    __nv_bfloat16* p_Bh = (__nv_bfloat16*)sym(g_Bh);
    __nv_bfloat16* p_Bl = (__nv_bfloat16*)sym(g_Bl);

    cudaFuncSetAttribute(tgemm_k, cudaFuncAttributeMaxDynamicSharedMemorySize, TG_DSMEM);
    cudaFuncSetAttribute(edge_csr_k, cudaFuncAttributeMaxDynamicSharedMemorySize, ESMEM);

    const int GM = (N_NODES + 127) / 128;   // 235

    prep_w_k<<<1153, 256>>>(enc_we, enc_be, msg_w1, msg_b1, rmsg_w1, rmsg_b1,
                            msg_w2, rmsg_w2, upd_w1, msg_b2, rmsg_b2, upd_b1);
    spt_all_k<<<1456, 256>>>(upd_w2, agg_w1, enc_wn);
    tgemm_k<<<dim3(GM, 1), 256, TG_DSMEM>>>(nf, 32, 32, p_Bh + OFF_ENW, p_Bl + OFF_ENW,
                                            enc_bn, nullptr, nullptr, p_h, 128, N_NODES, 128,
                                            FLAG_COPYSH);
    tgemm_k<<<dim3(GM, 8), 256, TG_DSMEM>>>(p_h, 128, 128, p_Bh + OFF_CAT, p_Bl + OFF_CAT,
                                            nullptr, nullptr, nullptr, (float*)p_PQh, 1024,
                                            N_NODES, 1024, FLAG_ZEROSH | FLAG_FP16OUT);
    zero_k<<<(2 * N_NODES / 4 + 255) / 256, 256>>>((float4*)p_deg, 2 * N_NODES / 4);
    hist_k<<<(N_EDGES + 255) / 256, 256>>>(from, to);
    scan_k<<<2, 1024>>>();
    build_k<<<(N_EDGES + 255) / 256, 256>>>(from, to);

    for (int l = 0; l < NLAYERS; l++) {
        if (l > 0)
            tgemm_k<<<dim3(GM, 8), 256, TG_DSMEM>>>(p_h, 128, 128, p_Bh + OFF_CAT, p_Bl + OFF_CAT,
                                                    nullptr, nullptr, nullptr, (float*)p_PQh, 1024,
                                                    N_NODES, 1024, FLAG_ZEROSH | FLAG_FP16OUT);
        edge_csr_k<<<2 * GEB, 256, ESMEM>>>(ef, from, to);
        tgemm_k<<<dim3(GM, 2), 256, TG_DSMEM>>>(p_SH, 640, 640, p_Bh + OFF_UPD, p_Bl + OFF_UPD,
                                                p_b3, p_deg, p_deg + N_NODES, p_Hu, 256, N_NODES, 256,
                                                FLAG_RELU | FLAG_BIAS3);
        int fl = FLAG_ADDC | ((l < NLAYERS - 1) ? FLAG_COPYSH : 0);
        tgemm_k<<<dim3(GM, 1), 256, TG_DSMEM>>>(p_Hu, 256, 256, p_Bh + OFF_UW2, p_Bl + OFF_UW2,
                                                upd_b2, nullptr, nullptr, p_h, 128, N_NODES, 128, fl);
    }

    tgemm_k<<<dim3(GM, 2), 256, TG_DSMEM>>>(p_h, 128, 128, p_Bh + OFF_AW1, p_Bl + OFF_AW1,
                                            agg_b1, nullptr, nullptr, p_Hu, 256, N_NODES, 256, 0);
    zero_k<<<(N_GRAPHS * 32 + 255) / 256, 256>>>((float4*)p_gv, N_GRAPHS * 32);
    gate_k<<<(N_NODES * 32 + 255) / 256, 256>>>(gidx);
    gv2_k<<<N_GRAPHS, 128>>>(agg_w2, agg_b2);
    out_k<<<128, 128>>>(out);
    (void)in_sizes; (void)n_in; (void)out_size;
}

// round 16
// speedup vs baseline: 1.6589x; 1.1034x over previous
#include <cuda_runtime.h>
#include <cuda_fp16.h>
#include <math.h>
#include <stdint.h>

#define N_NODES 30000
#define N_EDGES 300000
#define N_GRAPHS 256
#define DD 128
#define HH 256
#define NLAYERS 3

#define FLAG_RELU 1
#define FLAG_ADDC 2
#define FLAG_BIAS3 4
#define FLAG_COPYSH 8
#define FLAG_ZEROSH 16
#define FLAG_FP16OUT 32

// ---------------- scratch -------------------------------------------------
__device__ float g_h[N_NODES * DD];
__device__ __half g_PQh[(size_t)N_NODES * 1024];
__device__ float g_SH[(size_t)N_NODES * 640];
__device__ float g_Hu[N_NODES * HH];
__device__ float g_gv[N_GRAPHS * DD];
__device__ float g_gv2[N_GRAPHS * DD];
__device__ int   g_deg[2 * N_NODES];
__device__ int   g_cur[2 * N_NODES];
__device__ int   g_eidt[N_EDGES];
__device__ int   g_eidf[N_EDGES];
__device__ float g_WE[16 * 512];
__device__ float g_c[512];
__device__ float g_Wcat[128 * 1024];
__device__ float g_Vcat[640 * 256];
__device__ float g_bias3[768];

// fp16 hi/lo weight pool, [N][K] K-major
#define OFF_CAT 0
#define OFF_UPD 131072
#define OFF_UW2 294912
#define OFF_AW1 327680
#define OFF_ENW 360448
#define OFF_WET 364544
#define BPOOL   372736
__device__ __half g_Bh[BPOOL];
__device__ __half g_Bl[BPOOL];

// ---------------- helpers ---------------------------------------------------
__device__ __forceinline__ void red_add_v4(float* addr, float4 v) {
    asm volatile("red.global.add.v4.f32 [%0], {%1,%2,%3,%4};"
                 :: "l"(addr), "f"(v.x), "f"(v.y), "f"(v.z), "f"(v.w) : "memory");
}
__device__ __forceinline__ uint32_t f2h2(float a, float b) {
    __half2 h = __floats2half2_rn(a, b);
    return *(uint32_t*)&h;
}
__device__ __forceinline__ uint32_t smem_u32(const void* p) {
    uint32_t a;
    asm("{ .reg .u64 t; cvta.to.shared.u64 t, %1; cvt.u32.u64 %0, t; }" : "=r"(a) : "l"(p));
    return a;
}
__device__ __forceinline__ void mma16816(float* c, const uint32_t* a, const uint32_t* b) {
    asm("mma.sync.aligned.m16n8k16.row.col.f32.f16.f16.f32 "
        "{%0,%1,%2,%3}, {%4,%5,%6,%7}, {%8,%9}, {%0,%1,%2,%3};"
        : "+f"(c[0]), "+f"(c[1]), "+f"(c[2]), "+f"(c[3])
        : "r"(a[0]), "r"(a[1]), "r"(a[2]), "r"(a[3]), "r"(b[0]), "r"(b[1]));
}
#define LDSM4(r, addr)                                                         \
    asm volatile("ldmatrix.sync.aligned.m8n8.x4.shared.b16 {%0,%1,%2,%3}, [%4];" \
        : "=r"((r)[0]), "=r"((r)[1]), "=r"((r)[2]), "=r"((r)[3]) : "r"(addr))
__device__ __forceinline__ void cp16(uint32_t dst, const void* src) {
    asm volatile("cp.async.cg.shared.global [%0], [%1], 16;" :: "r"(dst), "l"(src));
}
#define CP_COMMIT() asm volatile("cp.async.commit_group;" ::: "memory")
#define CP_WAIT0()  asm volatile("cp.async.wait_group 0;" ::: "memory")

__global__ void zero_k(float4* p, int n4) {
    int i = blockIdx.x * 256 + threadIdx.x;
    if (i < n4) p[i] = make_float4(0.f, 0.f, 0.f, 0.f);
}

// ---------------- merged weight prep ---------------------------------------
__global__ void prep_w_k(const float* __restrict__ enc_we, const float* __restrict__ enc_be,
                         const float* __restrict__ mw1, const float* __restrict__ mb1,
                         const float* __restrict__ rw1, const float* __restrict__ rb1,
                         const float* __restrict__ mw2, const float* __restrict__ rw2,
                         const float* __restrict__ uw1, const float* __restrict__ mb2,
                         const float* __restrict__ rmb2, const float* __restrict__ ub1) {
    int b = blockIdx.x, tid = threadIdx.x;
    if (b < 512) {
        int idx = b * 256 + tid;
        int d = idx >> 10, c = idx & 1023;
        float v;
        if      (c < 256) v = mw1[d * 256 + c];
        else if (c < 512) v = mw1[(128 + d) * 256 + (c - 256)];
        else if (c < 768) v = rw1[d * 256 + (c - 512)];
        else              v = rw1[(128 + d) * 256 + (c - 768)];
        g_Wcat[idx] = v;
    } else if (b < 1152) {
        int r = b - 512, n = tid;
        float acc = 0.f;
        if (r < 256) {
            for (int d = 0; d < 128; d++)
                acc = fmaf(mw2[r * 128 + d], uw1[d * 256 + n], acc);
        } else if (r < 512) {
            int k = r - 256;
            for (int d = 0; d < 128; d++)
                acc = fmaf(rw2[k * 128 + d], uw1[(128 + d) * 256 + n], acc);
        } else {
            acc = uw1[(256 + r - 512) * 256 + n];
        }
        g_Vcat[r * 256 + n] = acc;
        if (r == 0) {
            float c1 = 0.f, c2 = 0.f;
            for (int d = 0; d < 128; d++) {
                c1 = fmaf(mb2[d], uw1[d * 256 + n], c1);
                c2 = fmaf(rmb2[d], uw1[(128 + d) * 256 + n], c2);
            }
            g_bias3[n] = ub1[n];
            g_bias3[256 + n] = c1;
            g_bias3[512 + n] = c2;
        }
    } else {
        for (int j = tid; j < 512; j += 256) {
            const float* W1 = (j < 256) ? mw1 : rw1;
            const float* b1 = (j < 256) ? mb1 : rb1;
            int jc = j & 255;
            for (int k = 0; k < 16; k++) {
                float acc = 0.f;
                for (int d = 0; d < 128; d++)
                    acc = fmaf(enc_we[k * 128 + d], W1[(256 + d) * 256 + jc], acc);
                g_WE[k * 512 + j] = acc;
            }
            float acc = b1[jc];
            for (int d = 0; d < 128; d++)
                acc = fmaf(enc_be[d], W1[(256 + d) * 256 + jc], acc);
            g_c[j] = acc;
        }
    }
}

// split + transpose: W[K][N] f32 -> fp16 hi/lo [N][K]
__device__ __forceinline__ void spt_one(const float* W, int off, int K, int N, int idx) {
    if (idx >= K * N) return;
    int k = idx / N, n = idx % N;
    float v = W[idx];
    __half h = __float2half_rn(v);
    __half l = __float2half_rn(v - __half2float(h));
    g_Bh[off + (size_t)n * K + k] = h;
    g_Bl[off + (size_t)n * K + k] = l;
}
__global__ void spt_all_k(const float* __restrict__ uw2, const float* __restrict__ aw1,
                          const float* __restrict__ enc_wn) {
    int b = blockIdx.x, tid = threadIdx.x;
    if      (b < 512)  spt_one(g_Wcat, OFF_CAT, 128, 1024, b * 256 + tid);
    else if (b < 1152) spt_one(g_Vcat, OFF_UPD, 640, 256, (b - 512) * 256 + tid);
    else if (b < 1280) spt_one(uw2,    OFF_UW2, 256, 128, (b - 1152) * 256 + tid);
    else if (b < 1408) spt_one(aw1,    OFF_AW1, 128, 256, (b - 1280) * 256 + tid);
    else if (b < 1424) spt_one(enc_wn, OFF_ENW, 32, 128,  (b - 1408) * 256 + tid);
    else               spt_one(g_WE,   OFF_WET, 16, 512,  (b - 1424) * 256 + tid);
}

__global__ void hist_k(const int* __restrict__ from, const int* __restrict__ to) {
    int i = blockIdx.x * 256 + threadIdx.x;
    if (i >= N_EDGES) return;
    atomicAdd(&g_deg[to[i]], 1);
    atomicAdd(&g_deg[N_NODES + from[i]], 1);
}

__global__ void scan_k() {
    __shared__ int part[1024];
    const int* deg = g_deg + blockIdx.x * N_NODES;
    int* cur = g_cur + blockIdx.x * N_NODES;
    int tid = threadIdx.x;
    int base = tid * 30;
    int local[30];
    int s = 0;
    #pragma unroll
    for (int i = 0; i < 30; i++) {
        int idx = base + i;
        int v = (idx < N_NODES) ? deg[idx] : 0;
        local[i] = s; s += v;
    }
    part[tid] = s;
    __syncthreads();
    for (int d = 1; d < 1024; d <<= 1) {
        int v = (tid >= d) ? part[tid - d] : 0;
        __syncthreads();
        part[tid] += v;
        __syncthreads();
    }
    int pre = (tid > 0) ? part[tid - 1] : 0;
    #pragma unroll
    for (int i = 0; i < 30; i++) {
        int idx = base + i;
        if (idx < N_NODES) cur[idx] = pre + local[i];
    }
}

__global__ void build_k(const int* __restrict__ from, const int* __restrict__ to) {
    int e = blockIdx.x * 256 + threadIdx.x;
    if (e >= N_EDGES) return;
    int pt = atomicAdd(&g_cur[to[e]], 1);
    g_eidt[pt] = e;
    int pf = atomicAdd(&g_cur[N_NODES + from[e]], 1);
    g_eidf[pf] = e;
}

// ---------------- pipelined warp-MMA fp16 GEMM (A fp16, B hi/lo) ------------
#define AST 20
#define SSTW (128 * AST)          // 2560 words per array
#define STGW (3 * SSTW)           // A | Bh | Bl
#define TG_DSMEM (2 * STGW * 4)   // 61440 bytes

__global__ void __launch_bounds__(256, 2) tgemm_k(
    const float* __restrict__ A, int lda, int K,
    const __half* __restrict__ Bh, const __half* __restrict__ Bl,
    const float* __restrict__ bias, const int* __restrict__ rs1,
    const int* __restrict__ rs2,
    float* __restrict__ C, int ldc, int M, int N, int flags)
{
    extern __shared__ __align__(16) uint32_t dsm[];
    const uint32_t sb = smem_u32(dsm);
    const int tid = threadIdx.x, wid = tid >> 5, lane = tid & 31;
    const int g = lane >> 2, t = lane & 3;
    const int m0 = blockIdx.x * 128, n0 = blockIdx.y * 128;
    const int mbase = (wid & 3) * 32, nbase = (wid >> 2) * 64;
    const int lrow = (lane & 7) + ((lane >> 3) & 1) * 8;
    const int lcol = ((lane >> 4) & 1) * 4;

    float acc[2][8][4];
    #pragma unroll
    for (int i = 0; i < 2; i++)
        #pragma unroll
        for (int j = 0; j < 8; j++)
            #pragma unroll
            for (int q = 0; q < 4; q++) acc[i][j][q] = 0.f;

    const int arow = tid >> 1, ahalf = tid & 1;
    const bool mok = (m0 + arow) < M;
    const float* Ap = A + (size_t)(m0 + arow) * lda;
    const __half* Bhp = Bh + (size_t)(n0 + arow) * K + ahalf * 16;
    const __half* Blp = Bl + (size_t)(n0 + arow) * K + ahalf * 16;
    const uint32_t bWord = (uint32_t)(arow * AST + ahalf * 8);

    float4 areg[4];
    const int nchunk = K >> 5;

    #pragma unroll
    for (int j = 0; j < 4; j++)
        areg[j] = mok ? *(const float4*)(Ap + ahalf * 16 + j * 4)
                      : make_float4(0.f, 0.f, 0.f, 0.f);
    {
        uint32_t bbase = sb + SSTW * 4;      // stage0 Bh
        cp16(bbase + bWord * 4, Bhp);
        cp16(bbase + (bWord + 4) * 4, Bhp + 8);
        cp16(bbase + SSTW * 4 + bWord * 4, Blp);
        cp16(bbase + SSTW * 4 + (bWord + 4) * 4, Blp + 8);
        CP_COMMIT();
    }
    {
        uint32_t* pA = dsm + bWord;
        #pragma unroll
        for (int j = 0; j < 4; j++) {
            float4 v = areg[j];
            pA[j * 2]     = f2h2(v.x, v.y);
            pA[j * 2 + 1] = f2h2(v.z, v.w);
        }
    }
    CP_WAIT0();
    __syncthreads();

    for (int c = 0; c < nchunk; c++) {
        const int cur = c & 1, nxt = (c + 1) & 1;
        const bool more = (c + 1) < nchunk;
        if (more) {
            #pragma unroll
            for (int j = 0; j < 4; j++)
                areg[j] = mok ? *(const float4*)(Ap + (c + 1) * 32 + ahalf * 16 + j * 4)
                              : make_float4(0.f, 0.f, 0.f, 0.f);
            uint32_t bbase = sb + (nxt * STGW + SSTW) * 4;
            const __half* bh = Bhp + (c + 1) * 32;
            const __half* bl = Blp + (c + 1) * 32;
            cp16(bbase + bWord * 4, bh);
            cp16(bbase + (bWord + 4) * 4, bh + 8);
            cp16(bbase + SSTW * 4 + bWord * 4, bl);
            cp16(bbase + SSTW * 4 + (bWord + 4) * 4, bl + 8);
            CP_COMMIT();
        }

        const uint32_t uA = sb + cur * STGW * 4;
        const uint32_t uBh = uA + SSTW * 4;
        const uint32_t dLo = SSTW * 4;
        #pragma unroll
        for (int ks = 0; ks < 2; ks++) {
            uint32_t ah[2][4];
            #pragma unroll
            for (int i = 0; i < 2; i++) {
                uint32_t ad = uA + (uint32_t)(((mbase + 16 * i + lrow) * AST + ks * 8 + lcol) * 4);
                LDSM4(ah[i], ad);
            }
            uint32_t bh[2][4], bl[2][4];
            {
                uint32_t bd = uBh + (uint32_t)(((nbase + lrow) * AST + ks * 8 + lcol) * 4);
                LDSM4(bh[0], bd);
                LDSM4(bl[0], bd + dLo);
            }
            #pragma unroll
            for (int jj = 0; jj < 4; jj++) {
                const int cb = jj & 1, nb = cb ^ 1;
                if (jj < 3) {
                    uint32_t bd = uBh + (uint32_t)(((nbase + 16 * (jj + 1) + lrow) * AST + ks * 8 + lcol) * 4);
                    LDSM4(bh[nb], bd);
                    LDSM4(bl[nb], bd + dLo);
                }
                uint32_t b0[2] = { bh[cb][0], bh[cb][2] }, b1[2] = { bh[cb][1], bh[cb][3] };
                uint32_t c0[2] = { bl[cb][0], bl[cb][2] }, c1[2] = { bl[cb][1], bl[cb][3] };
                int j0 = 2 * jj, j1 = 2 * jj + 1;
                mma16816(acc[0][j0], ah[0], b0);
                mma16816(acc[1][j0], ah[1], b0);
                mma16816(acc[0][j1], ah[0], b1);
                mma16816(acc[1][j1], ah[1], b1);
                mma16816(acc[0][j0], ah[0], c0);
                mma16816(acc[1][j0], ah[1], c0);
                mma16816(acc[0][j1], ah[0], c1);
                mma16816(acc[1][j1], ah[1], c1);
            }
        }

        if (more) {
            uint32_t* pA = dsm + nxt * STGW + bWord;
            #pragma unroll
            for (int j = 0; j < 4; j++) {
                float4 v = areg[j];
                pA[j * 2]     = f2h2(v.x, v.y);
                pA[j * 2 + 1] = f2h2(v.z, v.w);
            }
            CP_WAIT0();
        }
        __syncthreads();
    }

    #pragma unroll
    for (int i = 0; i < 2; i++) {
        #pragma unroll
        for (int rr = 0; rr < 2; rr++) {
            int row = m0 + mbase + 16 * i + g + 8 * rr;
            if (row >= M) continue;
            float r1 = 0.f, r2 = 0.f;
            if (flags & FLAG_BIAS3) { r1 = (float)rs1[row]; r2 = (float)rs2[row]; }
            float* crow = C + (size_t)row * ldc;
            #pragma unroll
            for (int j = 0; j < 8; j++) {
                int nn = n0 + nbase + 8 * j + 2 * t;
                float2 v = make_float2(acc[i][j][2 * rr], acc[i][j][2 * rr + 1]);
                if (flags & FLAG_BIAS3) {
                    v.x += bias[nn] + r1 * bias[256 + nn] + r2 * bias[512 + nn];
                    v.y += bias[nn + 1] + r1 * bias[256 + nn + 1] + r2 * bias[512 + nn + 1];
                } else if (bias) {
                    v.x += bias[nn]; v.y += bias[nn + 1];
                }
                if (flags & FLAG_ADDC) {
                    float2 c0 = *(const float2*)(crow + nn);
                    v.x += c0.x; v.y += c0.y;
                }
                if (flags & FLAG_RELU) {
                    v.x = fmaxf(v.x, 0.f); v.y = fmaxf(v.y, 0.f);
                }
                if (flags & FLAG_FP16OUT) {
                    *(__half2*)((__half*)C + (size_t)row * ldc + nn) =
                        __floats2half2_rn(v.x, v.y);
                } else {
                    *(float2*)(crow + nn) = v;
                }
                if (flags & FLAG_COPYSH)
                    *(float2*)(g_SH + (size_t)row * 640 + 512 + nn) = v;
                if ((flags & FLAG_ZEROSH) && nn < 512)
                    *(float2*)(g_SH + (size_t)row * 640 + nn) = make_float2(0.f, 0.f);
            }
        }
    }
}

// ---------------- CSR-sorted fused edge pass (both dirs, one launch) --------
// fp16 A (ef), fp16 W hi/lo (both chunks preloaded), fp16 Ech.
#define CASTE 12
#define ECSTH 132
#define oA  0
#define oWh 6144
#define oWl 18432
#define oEc 30720
#define oCc 64512
#define oEi 66560
#define oDs 67072
#define oSr 67584
#define ESMEM 68096
#define GEB ((N_EDGES + 127) / 128)

__global__ void __launch_bounds__(256) edge_csr_k(
    const float* __restrict__ ef, const int* __restrict__ from,
    const int* __restrict__ to)
{
    extern __shared__ __align__(16) char esm[];
    const uint32_t sb = smem_u32(esm);
    __half* Ech = (__half*)(esm + oEc);
    float* scf = (float*)(esm + oCc);
    int* sEid = (int*)(esm + oEi);
    int* sDest = (int*)(esm + oDs);
    int* sSrc = (int*)(esm + oSr);

    const int tid = threadIdx.x, wid = tid >> 5, lane = tid & 31;
    const int g = lane >> 2, t = lane & 3;
    const int mbase = (wid & 3) * 32, nbase = (wid >> 2) * 64;
    const int lrow = (lane & 7) + ((lane >> 3) & 1) * 8;
    const int lcol = ((lane >> 4) & 1) * 4;

    const int dir = (blockIdx.x >= GEB) ? 1 : 0;
    const int p0 = (blockIdx.x - dir * GEB) * 128;
    const int cnt = (N_EDGES - p0 < 128) ? (N_EDGES - p0) : 128;
    const int* eidArr = dir ? g_eidf : g_eidt;
    const int* dstArr = dir ? from : to;
    const int* srcArr = dir ? to : from;

    if (tid < 128) {
        int p = p0 + tid;
        int e = (p < N_EDGES) ? eidArr[p] : -1;
        sEid[tid] = e;
        sDest[tid] = (e >= 0) ? dstArr[e] : -1;
        sSrc[tid] = (e >= 0) ? srcArr[e] : 0;
    }
    for (int i = tid; i < 512; i += 256) scf[i] = g_c[i];
    // W tiles for BOTH K-chunks of this direction (256 rows, hi+lo)
    {
        int row = tid;   // 0..255
        const __half* srcH = g_Bh + OFF_WET + (size_t)(dir * 256 + row) * 16;
        const __half* srcL = g_Bl + OFF_WET + (size_t)(dir * 256 + row) * 16;
        int cc = row >> 7, rloc = row & 127;
        uint32_t wb = (uint32_t)(cc * 6144 + (rloc * CASTE) * 4);
        *(uint4*)(esm + oWh + wb) = *(const uint4*)srcH;
        *(uint4*)(esm + oWh + wb + 16) = *(const uint4*)(srcH + 8);
        *(uint4*)(esm + oWl + wb) = *(const uint4*)srcL;
        *(uint4*)(esm + oWl + wb + 16) = *(const uint4*)(srcL + 8);
    }
    __syncthreads();

    // gather ef rows by sorted edge id, convert to fp16
    {
        int row = tid >> 1, half = tid & 1;
        int e = sEid[row];
        float4 v0 = make_float4(0.f, 0.f, 0.f, 0.f), v1 = v0;
        if (e >= 0) {
            v0 = *(const float4*)(ef + (size_t)e * 16 + half * 8);
            v1 = *(const float4*)(ef + (size_t)e * 16 + half * 8 + 4);
        }
        uint32_t* pA = (uint32_t*)(esm + oA) + row * CASTE + half * 4;
        pA[0] = f2h2(v0.x, v0.y);
        pA[1] = f2h2(v0.z, v0.w);
        pA[2] = f2h2(v1.x, v1.y);
        pA[3] = f2h2(v1.z, v1.w);
    }
    __syncthreads();

    uint32_t ah[2][4];
    #pragma unroll
    for (int i = 0; i < 2; i++) {
        uint32_t ad = sb + oA + (uint32_t)(((mbase + 16 * i + lrow) * CASTE + lcol) * 4);
        LDSM4(ah[i], ad);
    }

    for (int c = 0; c < 2; c++) {
        float acc[2][8][4];
        #pragma unroll
        for (int i = 0; i < 2; i++)
            #pragma unroll
            for (int j = 0; j < 8; j++)
                #pragma unroll
                for (int q = 0; q < 4; q++) acc[i][j][q] = 0.f;
        #pragma unroll
        for (int jj = 0; jj < 4; jj++) {
            uint32_t bd = sb + oWh + (uint32_t)(c * 6144 + ((nbase + 16 * jj + lrow) * CASTE + lcol) * 4);
            uint32_t bh[4], bl[4];
            LDSM4(bh, bd);
            LDSM4(bl, bd + (oWl - oWh));
            uint32_t b0[2] = { bh[0], bh[2] }, b1[2] = { bh[1], bh[3] };
            uint32_t c0[2] = { bl[0], bl[2] }, c1[2] = { bl[1], bl[3] };
            int j0 = 2 * jj, j1 = 2 * jj + 1;
            mma16816(acc[0][j0], ah[0], b0);
            mma16816(acc[1][j0], ah[1], b0);
            mma16816(acc[0][j1], ah[0], b1);
            mma16816(acc[1][j1], ah[1], b1);
            mma16816(acc[0][j0], ah[0], c0);
            mma16816(acc[1][j0], ah[1], c0);
            mma16816(acc[0][j1], ah[0], c1);
            mma16816(acc[1][j1], ah[1], c1);
        }
        // write Echunk as fp16
        #pragma unroll
        for (int i = 0; i < 2; i++)
            #pragma unroll
            for (int rr = 0; rr < 2; rr++) {
                int row = mbase + 16 * i + g + 8 * rr;
                #pragma unroll
                for (int j = 0; j < 8; j++) {
                    int col = nbase + 8 * j + 2 * t;
                    *(__half2*)&Ech[row * ECSTH + col] =
                        __floats2half2_rn(acc[i][j][2 * rr], acc[i][j][2 * rr + 1]);
                }
            }
        __syncthreads();

        // ---- segmented consume: fp16 gathers + depth-1 scalar prefetch ----
        {
            const int coff = c * 128 + lane * 4;
            const int rbeg = wid * 16;
            const int rend = (rbeg + 16 < cnt) ? rbeg + 16 : cnt;
            if (rbeg < rend) {
                float4 bias4 = *(float4*)&scf[dir * 256 + coff];
                const size_t pOff = (size_t)(dir * 512 + coff);
                int cur = sDest[rbeg];
                uint2 pN = *(const uint2*)(g_PQh + (size_t)sSrc[rbeg] * 1024 + pOff);
                uint2 qN = *(const uint2*)(g_PQh + (size_t)cur * 1024 + pOff + 256);
                float4 a4 = make_float4(0.f, 0.f, 0.f, 0.f);
                bool first = true;
                for (int r = rbeg; r < rend; r++) {
                    uint2 pr = pN, qr = qN;
                    if (r + 1 < rend) {
                        pN = *(const uint2*)(g_PQh + (size_t)sSrc[r + 1] * 1024 + pOff);
                        qN = *(const uint2*)(g_PQh + (size_t)sDest[r + 1] * 1024 + pOff + 256);
                    }
                    int d = sDest[r];
                    if (d != cur) {
                        float* dst = g_SH + (size_t)cur * 640 + dir * 256 + coff;
                        if (first) red_add_v4(dst, a4);
                        else *(float4*)dst = a4;
                        first = false;
                        a4 = make_float4(0.f, 0.f, 0.f, 0.f);
                        cur = d;
                    }
                    float2 p01 = __half22float2(*(__half2*)&pr.x);
                    float2 p23 = __half22float2(*(__half2*)&pr.y);
                    float2 q01 = __half22float2(*(__half2*)&qr.x);
                    float2 q23 = __half22float2(*(__half2*)&qr.y);
                    uint2 er = *(const uint2*)&Ech[r * ECSTH + lane * 4];
                    float2 e01 = __half22float2(*(__half2*)&er.x);
                    float2 e23 = __half22float2(*(__half2*)&er.y);
                    a4.x += fmaxf(p01.x + q01.x + e01.x + bias4.x, 0.f);
                    a4.y += fmaxf(p01.y + q01.y + e01.y + bias4.y, 0.f);
                    a4.z += fmaxf(p23.x + q23.x + e23.x + bias4.z, 0.f);
                    a4.w += fmaxf(p23.y + q23.y + e23.y + bias4.w, 0.f);
                }
                bool complete = (!first) && (rend < cnt) && (sDest[rend] != cur);
                float* dst = g_SH + (size_t)cur * 640 + dir * 256 + coff;
                if (complete) *(float4*)dst = a4;
                else red_add_v4(dst, a4);
            }
        }
        __syncthreads();
    }
}

// ---------------- tail kernels ----------------------------------------------
__global__ void gate_k(const int* __restrict__ gidx) {
    int idx = blockIdx.x * 256 + threadIdx.x;
    if (idx >= N_NODES * 32) return;
    int n = idx >> 5, c4 = (idx & 31) * 4;
    const float* gr = g_Hu + (size_t)n * 256;
    float4 a = *(const float4*)&gr[c4];
    float4 b = *(const float4*)&gr[128 + c4];
    float4 v;
    v.x = b.x / (1.f + expf(-a.x));
    v.y = b.y / (1.f + expf(-a.y));
    v.z = b.z / (1.f + expf(-a.z));
    v.w = b.w / (1.f + expf(-a.w));
    red_add_v4(&g_gv[gidx[n] * 128 + c4], v);
}

__global__ void gv2_k(const float* __restrict__ W, const float* __restrict__ b) {
    __shared__ float row[128];
    int r = blockIdx.x, d = threadIdx.x;
    row[d] = g_gv[r * 128 + d];
    __syncthreads();
    float acc = b[d];
    #pragma unroll 8
    for (int k = 0; k < 128; k++) acc = fmaf(row[k], W[k * 128 + d], acc);
    g_gv2[r * 128 + d] = acc;
}

__global__ void out_k(float* __restrict__ out) {
    __shared__ float sdata[128];
    int p = blockIdx.x, t = threadIdx.x;
    float dxy = g_gv2[(2 * p) * 128 + t] - g_gv2[(2 * p + 1) * 128 + t];
    sdata[t] = dxy * dxy;
    __syncthreads();
    for (int s = 64; s > 0; s >>= 1) {
        if (t < s) sdata[t] += sdata[t + s];
        __syncthreads();
    }
    if (t == 0) out[p] = -sdata[0];
}

// ---------------- host launch ----------------------------------------------
static void* sym(const void* s) { void* p = nullptr; cudaGetSymbolAddress(&p, s); return p; }

extern "C" void kernel_launch(void* const* d_in, const int* in_sizes, int n_in,
                              void* d_out, int out_size) {
    const float* nf     = (const float*)d_in[0];
    const float* ef     = (const float*)d_in[1];
    const int*   from   = (const int*)d_in[2];
    const int*   to     = (const int*)d_in[3];
    const int*   gidx   = (const int*)d_in[4];
    const float* enc_wn = (const float*)d_in[5];
    const float* enc_bn = (const float*)d_in[6];
    const float* enc_we = (const float*)d_in[7];
    const float* enc_be = (const float*)d_in[8];
    const float* msg_w1 = (const float*)d_in[9];
    const float* msg_b1 = (const float*)d_in[10];
    const float* msg_w2 = (const float*)d_in[11];
    const float* msg_b2 = (const float*)d_in[12];
    const float* rmsg_w1= (const float*)d_in[13];
    const float* rmsg_b1= (const float*)d_in[14];
    const float* rmsg_w2= (const float*)d_in[15];
    const float* rmsg_b2= (const float*)d_in[16];
    const float* upd_w1 = (const float*)d_in[17];
    const float* upd_b1 = (const float*)d_in[18];
    const float* upd_w2 = (const float*)d_in[19];
    const float* upd_b2 = (const float*)d_in[20];
    const float* agg_w1 = (const float*)d_in[21];
    const float* agg_b1 = (const float*)d_in[22];
    const float* agg_w2 = (const float*)d_in[23];
    const float* agg_b2 = (const float*)d_in[24];
    float* out = (float*)d_out;

    float* p_h    = (float*)sym(g_h);
    __half* p_PQh = (__half*)sym(g_PQh);
    float* p_SH   = (float*)sym(g_SH);
    float* p_Hu   = (float*)sym(g_Hu);
    float* p_gv   = (float*)sym(g_gv);
    float* p_b3   = (float*)sym(g_bias3);
    int*   p_deg  = (int*)sym(g_deg);
    __half* p_Bh  = (__half*)sym(g_Bh);
    __half* p_Bl  = (__half*)sym(g_Bl);

    cudaFuncSetAttribute(tgemm_k, cudaFuncAttributeMaxDynamicSharedMemorySize, TG_DSMEM);
    cudaFuncSetAttribute(edge_csr_k, cudaFuncAttributeMaxDynamicSharedMemorySize, ESMEM);

    const int GM = (N_NODES + 127) / 128;   // 235

    prep_w_k<<<1153, 256>>>(enc_we, enc_be, msg_w1, msg_b1, rmsg_w1, rmsg_b1,
                            msg_w2, rmsg_w2, upd_w1, msg_b2, rmsg_b2, upd_b1);
    spt_all_k<<<1456, 256>>>(upd_w2, agg_w1, enc_wn);
    tgemm_k<<<dim3(GM, 1), 256, TG_DSMEM>>>(nf, 32, 32, p_Bh + OFF_ENW, p_Bl + OFF_ENW,
                                            enc_bn, nullptr, nullptr, p_h, 128, N_NODES, 128,
                                            FLAG_COPYSH);
    tgemm_k<<<dim3(GM, 8), 256, TG_DSMEM>>>(p_h, 128, 128, p_Bh + OFF_CAT, p_Bl + OFF_CAT,
                                            nullptr, nullptr, nullptr, (float*)p_PQh, 1024,
                                            N_NODES, 1024, FLAG_ZEROSH | FLAG_FP16OUT);
    zero_k<<<(2 * N_NODES / 4 + 255) / 256, 256>>>((float4*)p_deg, 2 * N_NODES / 4);
    hist_k<<<(N_EDGES + 255) / 256, 256>>>(from, to);
    scan_k<<<2, 1024>>>();
    build_k<<<(N_EDGES + 255) / 256, 256>>>(from, to);

    for (int l = 0; l < NLAYERS; l++) {
        if (l > 0)
            tgemm_k<<<dim3(GM, 8), 256, TG_DSMEM>>>(p_h, 128, 128, p_Bh + OFF_CAT, p_Bl + OFF_CAT,
                                                    nullptr, nullptr, nullptr, (float*)p_PQh, 1024,
                                                    N_NODES, 1024, FLAG_ZEROSH | FLAG_FP16OUT);
        edge_csr_k<<<2 * GEB, 256, ESMEM>>>(ef, from, to);
        tgemm_k<<<dim3(GM, 2), 256, TG_DSMEM>>>(p_SH, 640, 640, p_Bh + OFF_UPD, p_Bl + OFF_UPD,
                                                p_b3, p_deg, p_deg + N_NODES, p_Hu, 256, N_NODES, 256,
                                                FLAG_RELU | FLAG_BIAS3);
        int fl = FLAG_ADDC | ((l < NLAYERS - 1) ? FLAG_COPYSH : 0);
        tgemm_k<<<dim3(GM, 1), 256, TG_DSMEM>>>(p_Hu, 256, 256, p_Bh + OFF_UW2, p_Bl + OFF_UW2,
                                                upd_b2, nullptr, nullptr, p_h, 128, N_NODES, 128, fl);
    }

    tgemm_k<<<dim3(GM, 2), 256, TG_DSMEM>>>(p_h, 128, 128, p_Bh + OFF_AW1, p_Bl + OFF_AW1,
                                            agg_b1, nullptr, nullptr, p_Hu, 256, N_NODES, 256, 0);
    zero_k<<<(N_GRAPHS * 32 + 255) / 256, 256>>>((float4*)p_gv, N_GRAPHS * 32);
    gate_k<<<(N_NODES * 32 + 255) / 256, 256>>>(gidx);
    gv2_k<<<N_GRAPHS, 128>>>(agg_w2, agg_b2);
    out_k<<<128, 128>>>(out);
    (void)in_sizes; (void)n_in; (void)out_size;
}

// round 17
// speedup vs baseline: 2.0229x; 1.2194x over previous
#include <cuda_runtime.h>
#include <cuda_fp16.h>
#include <math.h>
#include <stdint.h>

#define N_NODES 30000
#define N_EDGES 300000
#define N_GRAPHS 256
#define DD 128
#define HH 256
#define NLAYERS 3

#define FLAG_RELU 1
#define FLAG_ADDC 2
#define FLAG_BIAS3 4
#define FLAG_COPYSH 8
#define FLAG_ZEROSH 16
#define FLAG_FP16OUT 32

// ---------------- scratch -------------------------------------------------
__device__ float g_h[N_NODES * DD];
__device__ __half g_PQh[(size_t)N_NODES * 1024];
__device__ float g_SH[(size_t)N_NODES * 640];
__device__ float g_Hu[N_NODES * HH];
__device__ float g_gv[N_GRAPHS * DD];
__device__ float g_gv2[N_GRAPHS * DD];
__device__ int   g_deg[2 * N_NODES];
__device__ int   g_cur[2 * N_NODES];
__device__ int   g_eidt[N_EDGES];
__device__ int   g_eidf[N_EDGES];
__device__ float g_WE[16 * 512];
__device__ float g_c[512];
__device__ float g_Wcat[128 * 1024];
__device__ float g_Vcat[640 * 256];
__device__ float g_bias3[768];

// fp16 weight pool, [N][K] K-major
#define OFF_CAT 0
#define OFF_UPD 131072
#define OFF_UW2 294912
#define OFF_AW1 327680
#define OFF_ENW 360448
#define OFF_WET 364544
#define BPOOL   372736
__device__ __half g_Bh[BPOOL];

// ---------------- helpers ---------------------------------------------------
__device__ __forceinline__ void red_add_v4(float* addr, float4 v) {
    asm volatile("red.global.add.v4.f32 [%0], {%1,%2,%3,%4};"
                 :: "l"(addr), "f"(v.x), "f"(v.y), "f"(v.z), "f"(v.w) : "memory");
}
__device__ __forceinline__ uint32_t f2h2(float a, float b) {
    __half2 h = __floats2half2_rn(a, b);
    return *(uint32_t*)&h;
}
__device__ __forceinline__ uint32_t smem_u32(const void* p) {
    uint32_t a;
    asm("{ .reg .u64 t; cvta.to.shared.u64 t, %1; cvt.u32.u64 %0, t; }" : "=r"(a) : "l"(p));
    return a;
}
__device__ __forceinline__ void mma16816(float* c, const uint32_t* a, const uint32_t* b) {
    asm("mma.sync.aligned.m16n8k16.row.col.f32.f16.f16.f32 "
        "{%0,%1,%2,%3}, {%4,%5,%6,%7}, {%8,%9}, {%0,%1,%2,%3};"
        : "+f"(c[0]), "+f"(c[1]), "+f"(c[2]), "+f"(c[3])
        : "r"(a[0]), "r"(a[1]), "r"(a[2]), "r"(a[3]), "r"(b[0]), "r"(b[1]));
}
#define LDSM4(r, addr)                                                         \
    asm volatile("ldmatrix.sync.aligned.m8n8.x4.shared.b16 {%0,%1,%2,%3}, [%4];" \
        : "=r"((r)[0]), "=r"((r)[1]), "=r"((r)[2]), "=r"((r)[3]) : "r"(addr))
__device__ __forceinline__ void cp16(uint32_t dst, const void* src) {
    asm volatile("cp.async.cg.shared.global [%0], [%1], 16;" :: "r"(dst), "l"(src));
}
#define CP_COMMIT() asm volatile("cp.async.commit_group;" ::: "memory")
#define CP_WAIT0()  asm volatile("cp.async.wait_group 0;" ::: "memory")

__global__ void zero_k(float4* p, int n4) {
    int i = blockIdx.x * 256 + threadIdx.x;
    if (i < n4) p[i] = make_float4(0.f, 0.f, 0.f, 0.f);
}

// ---------------- merged weight prep ---------------------------------------
__global__ void prep_w_k(const float* __restrict__ enc_we, const float* __restrict__ enc_be,
                         const float* __restrict__ mw1, const float* __restrict__ mb1,
                         const float* __restrict__ rw1, const float* __restrict__ rb1,
                         const float* __restrict__ mw2, const float* __restrict__ rw2,
                         const float* __restrict__ uw1, const float* __restrict__ mb2,
                         const float* __restrict__ rmb2, const float* __restrict__ ub1) {
    int b = blockIdx.x, tid = threadIdx.x;
    if (b < 512) {
        int idx = b * 256 + tid;
        int d = idx >> 10, c = idx & 1023;
        float v;
        if      (c < 256) v = mw1[d * 256 + c];
        else if (c < 512) v = mw1[(128 + d) * 256 + (c - 256)];
        else if (c < 768) v = rw1[d * 256 + (c - 512)];
        else              v = rw1[(128 + d) * 256 + (c - 768)];
        g_Wcat[idx] = v;
    } else if (b < 1152) {
        int r = b - 512, n = tid;
        float acc = 0.f;
        if (r < 256) {
            for (int d = 0; d < 128; d++)
                acc = fmaf(mw2[r * 128 + d], uw1[d * 256 + n], acc);
        } else if (r < 512) {
            int k = r - 256;
            for (int d = 0; d < 128; d++)
                acc = fmaf(rw2[k * 128 + d], uw1[(128 + d) * 256 + n], acc);
        } else {
            acc = uw1[(256 + r - 512) * 256 + n];
        }
        g_Vcat[r * 256 + n] = acc;
        if (r == 0) {
            float c1 = 0.f, c2 = 0.f;
            for (int d = 0; d < 128; d++) {
                c1 = fmaf(mb2[d], uw1[d * 256 + n], c1);
                c2 = fmaf(rmb2[d], uw1[(128 + d) * 256 + n], c2);
            }
            g_bias3[n] = ub1[n];
            g_bias3[256 + n] = c1;
            g_bias3[512 + n] = c2;
        }
    } else {
        for (int j = tid; j < 512; j += 256) {
            const float* W1 = (j < 256) ? mw1 : rw1;
            const float* b1 = (j < 256) ? mb1 : rb1;
            int jc = j & 255;
            for (int k = 0; k < 16; k++) {
                float acc = 0.f;
                for (int d = 0; d < 128; d++)
                    acc = fmaf(enc_we[k * 128 + d], W1[(256 + d) * 256 + jc], acc);
                g_WE[k * 512 + j] = acc;
            }
            float acc = b1[jc];
            for (int d = 0; d < 128; d++)
                acc = fmaf(enc_be[d], W1[(256 + d) * 256 + jc], acc);
            g_c[j] = acc;
        }
    }
}

// transpose + fp16: W[K][N] f32 -> fp16 [N][K]
__device__ __forceinline__ void spt_one(const float* W, int off, int K, int N, int idx) {
    if (idx >= K * N) return;
    int k = idx / N, n = idx % N;
    g_Bh[off + (size_t)n * K + k] = __float2half_rn(W[idx]);
}
__global__ void spt_all_k(const float* __restrict__ uw2, const float* __restrict__ aw1,
                          const float* __restrict__ enc_wn) {
    int b = blockIdx.x, tid = threadIdx.x;
    if      (b < 512)  spt_one(g_Wcat, OFF_CAT, 128, 1024, b * 256 + tid);
    else if (b < 1152) spt_one(g_Vcat, OFF_UPD, 640, 256, (b - 512) * 256 + tid);
    else if (b < 1280) spt_one(uw2,    OFF_UW2, 256, 128, (b - 1152) * 256 + tid);
    else if (b < 1408) spt_one(aw1,    OFF_AW1, 128, 256, (b - 1280) * 256 + tid);
    else if (b < 1424) spt_one(enc_wn, OFF_ENW, 32, 128,  (b - 1408) * 256 + tid);
    else               spt_one(g_WE,   OFF_WET, 16, 512,  (b - 1424) * 256 + tid);
}

__global__ void hist_k(const int* __restrict__ from, const int* __restrict__ to) {
    int i = blockIdx.x * 256 + threadIdx.x;
    if (i >= N_EDGES) return;
    atomicAdd(&g_deg[to[i]], 1);
    atomicAdd(&g_deg[N_NODES + from[i]], 1);
}

__global__ void scan_k() {
    __shared__ int part[1024];
    const int* deg = g_deg + blockIdx.x * N_NODES;
    int* cur = g_cur + blockIdx.x * N_NODES;
    int tid = threadIdx.x;
    int base = tid * 30;
    int local[30];
    int s = 0;
    #pragma unroll
    for (int i = 0; i < 30; i++) {
        int idx = base + i;
        int v = (idx < N_NODES) ? deg[idx] : 0;
        local[i] = s; s += v;
    }
    part[tid] = s;
    __syncthreads();
    for (int d = 1; d < 1024; d <<= 1) {
        int v = (tid >= d) ? part[tid - d] : 0;
        __syncthreads();
        part[tid] += v;
        __syncthreads();
    }
    int pre = (tid > 0) ? part[tid - 1] : 0;
    #pragma unroll
    for (int i = 0; i < 30; i++) {
        int idx = base + i;
        if (idx < N_NODES) cur[idx] = pre + local[i];
    }
}

__global__ void build_k(const int* __restrict__ from, const int* __restrict__ to) {
    int e = blockIdx.x * 256 + threadIdx.x;
    if (e >= N_EDGES) return;
    int pt = atomicAdd(&g_cur[to[e]], 1);
    g_eidt[pt] = e;
    int pf = atomicAdd(&g_cur[N_NODES + from[e]], 1);
    g_eidf[pf] = e;
}

// ---------------- pipelined warp-MMA pure-fp16 GEMM -------------------------
#define AST 20
#define SSTW (128 * AST)          // 2560 words per array
#define STGW (2 * SSTW)           // A | B
#define TG_DSMEM (2 * STGW * 4)   // 40960 bytes

__global__ void __launch_bounds__(256, 2) tgemm_k(
    const float* __restrict__ A, int lda, int K,
    const __half* __restrict__ Bh,
    const float* __restrict__ bias, const int* __restrict__ rs1,
    const int* __restrict__ rs2,
    float* __restrict__ C, int ldc, int M, int N, int flags)
{
    extern __shared__ __align__(16) uint32_t dsm[];
    const uint32_t sb = smem_u32(dsm);
    const int tid = threadIdx.x, wid = tid >> 5, lane = tid & 31;
    const int g = lane >> 2, t = lane & 3;
    const int m0 = blockIdx.x * 128, n0 = blockIdx.y * 128;
    const int mbase = (wid & 3) * 32, nbase = (wid >> 2) * 64;
    const int lrow = (lane & 7) + ((lane >> 3) & 1) * 8;
    const int lcol = ((lane >> 4) & 1) * 4;

    float acc[2][8][4];
    #pragma unroll
    for (int i = 0; i < 2; i++)
        #pragma unroll
        for (int j = 0; j < 8; j++)
            #pragma unroll
            for (int q = 0; q < 4; q++) acc[i][j][q] = 0.f;

    const int arow = tid >> 1, ahalf = tid & 1;
    const bool mok = (m0 + arow) < M;
    const float* Ap = A + (size_t)(m0 + arow) * lda;
    const __half* Bhp = Bh + (size_t)(n0 + arow) * K + ahalf * 16;
    const uint32_t bWord = (uint32_t)(arow * AST + ahalf * 8);

    float4 areg[4];
    const int nchunk = K >> 5;

    #pragma unroll
    for (int j = 0; j < 4; j++)
        areg[j] = mok ? *(const float4*)(Ap + ahalf * 16 + j * 4)
                      : make_float4(0.f, 0.f, 0.f, 0.f);
    {
        uint32_t bbase = sb + SSTW * 4;      // stage0 B
        cp16(bbase + bWord * 4, Bhp);
        cp16(bbase + (bWord + 4) * 4, Bhp + 8);
        CP_COMMIT();
    }
    {
        uint32_t* pA = dsm + bWord;
        #pragma unroll
        for (int j = 0; j < 4; j++) {
            float4 v = areg[j];
            pA[j * 2]     = f2h2(v.x, v.y);
            pA[j * 2 + 1] = f2h2(v.z, v.w);
        }
    }
    CP_WAIT0();
    __syncthreads();

    for (int c = 0; c < nchunk; c++) {
        const int cur = c & 1, nxt = (c + 1) & 1;
        const bool more = (c + 1) < nchunk;
        if (more) {
            #pragma unroll
            for (int j = 0; j < 4; j++)
                areg[j] = mok ? *(const float4*)(Ap + (c + 1) * 32 + ahalf * 16 + j * 4)
                              : make_float4(0.f, 0.f, 0.f, 0.f);
            uint32_t bbase = sb + (nxt * STGW + SSTW) * 4;
            const __half* bh = Bhp + (c + 1) * 32;
            cp16(bbase + bWord * 4, bh);
            cp16(bbase + (bWord + 4) * 4, bh + 8);
            CP_COMMIT();
        }

        const uint32_t uA = sb + cur * STGW * 4;
        const uint32_t uBh = uA + SSTW * 4;
        #pragma unroll
        for (int ks = 0; ks < 2; ks++) {
            uint32_t ah[2][4];
            #pragma unroll
            for (int i = 0; i < 2; i++) {
                uint32_t ad = uA + (uint32_t)(((mbase + 16 * i + lrow) * AST + ks * 8 + lcol) * 4);
                LDSM4(ah[i], ad);
            }
            uint32_t bh[2][4];
            {
                uint32_t bd = uBh + (uint32_t)(((nbase + lrow) * AST + ks * 8 + lcol) * 4);
                LDSM4(bh[0], bd);
            }
            #pragma unroll
            for (int jj = 0; jj < 4; jj++) {
                const int cb = jj & 1, nb = cb ^ 1;
                if (jj < 3) {
                    uint32_t bd = uBh + (uint32_t)(((nbase + 16 * (jj + 1) + lrow) * AST + ks * 8 + lcol) * 4);
                    LDSM4(bh[nb], bd);
                }
                uint32_t b0[2] = { bh[cb][0], bh[cb][2] }, b1[2] = { bh[cb][1], bh[cb][3] };
                int j0 = 2 * jj, j1 = 2 * jj + 1;
                mma16816(acc[0][j0], ah[0], b0);
                mma16816(acc[1][j0], ah[1], b0);
                mma16816(acc[0][j1], ah[0], b1);
                mma16816(acc[1][j1], ah[1], b1);
            }
        }

        if (more) {
            uint32_t* pA = dsm + nxt * STGW + bWord;
            #pragma unroll
            for (int j = 0; j < 4; j++) {
                float4 v = areg[j];
                pA[j * 2]     = f2h2(v.x, v.y);
                pA[j * 2 + 1] = f2h2(v.z, v.w);
            }
            CP_WAIT0();
        }
        __syncthreads();
    }

    #pragma unroll
    for (int i = 0; i < 2; i++) {
        #pragma unroll
        for (int rr = 0; rr < 2; rr++) {
            int row = m0 + mbase + 16 * i + g + 8 * rr;
            if (row >= M) continue;
            float r1 = 0.f, r2 = 0.f;
            if (flags & FLAG_BIAS3) { r1 = (float)rs1[row]; r2 = (float)rs2[row]; }
            float* crow = C + (size_t)row * ldc;
            #pragma unroll
            for (int j = 0; j < 8; j++) {
                int nn = n0 + nbase + 8 * j + 2 * t;
                float2 v = make_float2(acc[i][j][2 * rr], acc[i][j][2 * rr + 1]);
                if (flags & FLAG_BIAS3) {
                    v.x += bias[nn] + r1 * bias[256 + nn] + r2 * bias[512 + nn];
                    v.y += bias[nn + 1] + r1 * bias[256 + nn + 1] + r2 * bias[512 + nn + 1];
                } else if (bias) {
                    v.x += bias[nn]; v.y += bias[nn + 1];
                }
                if (flags & FLAG_ADDC) {
                    float2 c0 = *(const float2*)(crow + nn);
                    v.x += c0.x; v.y += c0.y;
                }
                if (flags & FLAG_RELU) {
                    v.x = fmaxf(v.x, 0.f); v.y = fmaxf(v.y, 0.f);
                }
                if (flags & FLAG_FP16OUT) {
                    *(__half2*)((__half*)C + (size_t)row * ldc + nn) =
                        __floats2half2_rn(v.x, v.y);
                } else {
                    *(float2*)(crow + nn) = v;
                }
                if (flags & FLAG_COPYSH)
                    *(float2*)(g_SH + (size_t)row * 640 + 512 + nn) = v;
                if ((flags & FLAG_ZEROSH) && nn < 512)
                    *(float2*)(g_SH + (size_t)row * 640 + nn) = make_float2(0.f, 0.f);
            }
        }
    }
}

// ---------------- CSR-sorted fused edge pass (both dirs, one launch) --------
// pure fp16 MMA; W both chunks preloaded; fp16 Ech; 4 CTAs/SM.
#define CASTE 12
#define ECSTH 132
#define oA  0
#define oWh 6144
#define oEc 18432
#define oCc 52224
#define oEi 54272
#define oDs 54784
#define oSr 55296
#define ESMEM 55808
#define GEB ((N_EDGES + 127) / 128)

__global__ void __launch_bounds__(256) edge_csr_k(
    const float* __restrict__ ef, const int* __restrict__ from,
    const int* __restrict__ to)
{
    extern __shared__ __align__(16) char esm[];
    const uint32_t sb = smem_u32(esm);
    __half* Ech = (__half*)(esm + oEc);
    float* scf = (float*)(esm + oCc);
    int* sEid = (int*)(esm + oEi);
    int* sDest = (int*)(esm + oDs);
    int* sSrc = (int*)(esm + oSr);

    const int tid = threadIdx.x, wid = tid >> 5, lane = tid & 31;
    const int g = lane >> 2, t = lane & 3;
    const int mbase = (wid & 3) * 32, nbase = (wid >> 2) * 64;
    const int lrow = (lane & 7) + ((lane >> 3) & 1) * 8;
    const int lcol = ((lane >> 4) & 1) * 4;

    const int dir = (blockIdx.x >= GEB) ? 1 : 0;
    const int p0 = (blockIdx.x - dir * GEB) * 128;
    const int cnt = (N_EDGES - p0 < 128) ? (N_EDGES - p0) : 128;
    const int* eidArr = dir ? g_eidf : g_eidt;
    const int* dstArr = dir ? from : to;
    const int* srcArr = dir ? to : from;

    if (tid < 128) {
        int p = p0 + tid;
        int e = (p < N_EDGES) ? eidArr[p] : -1;
        sEid[tid] = e;
        sDest[tid] = (e >= 0) ? dstArr[e] : -1;
        sSrc[tid] = (e >= 0) ? srcArr[e] : 0;
    }
    for (int i = tid; i < 512; i += 256) scf[i] = g_c[i];
    // W tiles for BOTH K-chunks of this direction (256 rows)
    {
        int row = tid;   // 0..255
        const __half* srcH = g_Bh + OFF_WET + (size_t)(dir * 256 + row) * 16;
        int cc = row >> 7, rloc = row & 127;
        uint32_t wb = (uint32_t)(cc * 6144 + (rloc * CASTE) * 4);
        *(uint4*)(esm + oWh + wb) = *(const uint4*)srcH;
        *(uint4*)(esm + oWh + wb + 16) = *(const uint4*)(srcH + 8);
    }
    __syncthreads();

    // gather ef rows by sorted edge id, convert to fp16
    {
        int row = tid >> 1, half = tid & 1;
        int e = sEid[row];
        float4 v0 = make_float4(0.f, 0.f, 0.f, 0.f), v1 = v0;
        if (e >= 0) {
            v0 = *(const float4*)(ef + (size_t)e * 16 + half * 8);
            v1 = *(const float4*)(ef + (size_t)e * 16 + half * 8 + 4);
        }
        uint32_t* pA = (uint32_t*)(esm + oA) + row * CASTE + half * 4;
        pA[0] = f2h2(v0.x, v0.y);
        pA[1] = f2h2(v0.z, v0.w);
        pA[2] = f2h2(v1.x, v1.y);
        pA[3] = f2h2(v1.z, v1.w);
    }
    __syncthreads();

    uint32_t ah[2][4];
    #pragma unroll
    for (int i = 0; i < 2; i++) {
        uint32_t ad = sb + oA + (uint32_t)(((mbase + 16 * i + lrow) * CASTE + lcol) * 4);
        LDSM4(ah[i], ad);
    }

    for (int c = 0; c < 2; c++) {
        float acc[2][8][4];
        #pragma unroll
        for (int i = 0; i < 2; i++)
            #pragma unroll
            for (int j = 0; j < 8; j++)
                #pragma unroll
                for (int q = 0; q < 4; q++) acc[i][j][q] = 0.f;
        #pragma unroll
        for (int jj = 0; jj < 4; jj++) {
            uint32_t bd = sb + oWh + (uint32_t)(c * 6144 + ((nbase + 16 * jj + lrow) * CASTE + lcol) * 4);
            uint32_t bh[4];
            LDSM4(bh, bd);
            uint32_t b0[2] = { bh[0], bh[2] }, b1[2] = { bh[1], bh[3] };
            int j0 = 2 * jj, j1 = 2 * jj + 1;
            mma16816(acc[0][j0], ah[0], b0);
            mma16816(acc[1][j0], ah[1], b0);
            mma16816(acc[0][j1], ah[0], b1);
            mma16816(acc[1][j1], ah[1], b1);
        }
        // write Echunk as fp16
        #pragma unroll
        for (int i = 0; i < 2; i++)
            #pragma unroll
            for (int rr = 0; rr < 2; rr++) {
                int row = mbase + 16 * i + g + 8 * rr;
                #pragma unroll
                for (int j = 0; j < 8; j++) {
                    int col = nbase + 8 * j + 2 * t;
                    *(__half2*)&Ech[row * ECSTH + col] =
                        __floats2half2_rn(acc[i][j][2 * rr], acc[i][j][2 * rr + 1]);
                }
            }
        __syncthreads();

        // ---- segmented consume: fp16 gathers + depth-1 scalar prefetch ----
        {
            const int coff = c * 128 + lane * 4;
            const int rbeg = wid * 16;
            const int rend = (rbeg + 16 < cnt) ? rbeg + 16 : cnt;
            if (rbeg < rend) {
                float4 bias4 = *(float4*)&scf[dir * 256 + coff];
                const size_t pOff = (size_t)(dir * 512 + coff);
                int cur = sDest[rbeg];
                uint2 pN = *(const uint2*)(g_PQh + (size_t)sSrc[rbeg] * 1024 + pOff);
                uint2 qN = *(const uint2*)(g_PQh + (size_t)cur * 1024 + pOff + 256);
                float4 a4 = make_float4(0.f, 0.f, 0.f, 0.f);
                bool first = true;
                for (int r = rbeg; r < rend; r++) {
                    uint2 pr = pN, qr = qN;
                    if (r + 1 < rend) {
                        pN = *(const uint2*)(g_PQh + (size_t)sSrc[r + 1] * 1024 + pOff);
                        qN = *(const uint2*)(g_PQh + (size_t)sDest[r + 1] * 1024 + pOff + 256);
                    }
                    int d = sDest[r];
                    if (d != cur) {
                        float* dst = g_SH + (size_t)cur * 640 + dir * 256 + coff;
                        if (first) red_add_v4(dst, a4);
                        else *(float4*)dst = a4;
                        first = false;
                        a4 = make_float4(0.f, 0.f, 0.f, 0.f);
                        cur = d;
                    }
                    float2 p01 = __half22float2(*(__half2*)&pr.x);
                    float2 p23 = __half22float2(*(__half2*)&pr.y);
                    float2 q01 = __half22float2(*(__half2*)&qr.x);
                    float2 q23 = __half22float2(*(__half2*)&qr.y);
                    uint2 er = *(const uint2*)&Ech[r * ECSTH + lane * 4];
                    float2 e01 = __half22float2(*(__half2*)&er.x);
                    float2 e23 = __half22float2(*(__half2*)&er.y);
                    a4.x += fmaxf(p01.x + q01.x + e01.x + bias4.x, 0.f);
                    a4.y += fmaxf(p01.y + q01.y + e01.y + bias4.y, 0.f);
                    a4.z += fmaxf(p23.x + q23.x + e23.x + bias4.z, 0.f);
                    a4.w += fmaxf(p23.y + q23.y + e23.y + bias4.w, 0.f);
                }
                bool complete = (!first) && (rend < cnt) && (sDest[rend] != cur);
                float* dst = g_SH + (size_t)cur * 640 + dir * 256 + coff;
                if (complete) *(float4*)dst = a4;
                else red_add_v4(dst, a4);
            }
        }
        __syncthreads();
    }
}

// ---------------- tail kernels ----------------------------------------------
__global__ void gate_k(const int* __restrict__ gidx) {
    int idx = blockIdx.x * 256 + threadIdx.x;
    if (idx >= N_NODES * 32) return;
    int n = idx >> 5, c4 = (idx & 31) * 4;
    const float* gr = g_Hu + (size_t)n * 256;
    float4 a = *(const float4*)&gr[c4];
    float4 b = *(const float4*)&gr[128 + c4];
    float4 v;
    v.x = b.x / (1.f + expf(-a.x));
    v.y = b.y / (1.f + expf(-a.y));
    v.z = b.z / (1.f + expf(-a.z));
    v.w = b.w / (1.f + expf(-a.w));
    red_add_v4(&g_gv[gidx[n] * 128 + c4], v);
}

__global__ void gv2_k(const float* __restrict__ W, const float* __restrict__ b) {
    __shared__ float row[128];
    int r = blockIdx.x, d = threadIdx.x;
    row[d] = g_gv[r * 128 + d];
    __syncthreads();
    float acc = b[d];
    #pragma unroll 8
    for (int k = 0; k < 128; k++) acc = fmaf(row[k], W[k * 128 + d], acc);
    g_gv2[r * 128 + d] = acc;
}

__global__ void out_k(float* __restrict__ out) {
    __shared__ float sdata[128];
    int p = blockIdx.x, t = threadIdx.x;
    float dxy = g_gv2[(2 * p) * 128 + t] - g_gv2[(2 * p + 1) * 128 + t];
    sdata[t] = dxy * dxy;
    __syncthreads();
    for (int s = 64; s > 0; s >>= 1) {
        if (t < s) sdata[t] += sdata[t + s];
        __syncthreads();
    }
    if (t == 0) out[p] = -sdata[0];
}

// ---------------- host launch ----------------------------------------------
static void* sym(const void* s) { void* p = nullptr; cudaGetSymbolAddress(&p, s); return p; }

extern "C" void kernel_launch(void* const* d_in, const int* in_sizes, int n_in,
                              void* d_out, int out_size) {
    const float* nf     = (const float*)d_in[0];
    const float* ef     = (const float*)d_in[1];
    const int*   from   = (const int*)d_in[2];
    const int*   to     = (const int*)d_in[3];
    const int*   gidx   = (const int*)d_in[4];
    const float* enc_wn = (const float*)d_in[5];
    const float* enc_bn = (const float*)d_in[6];
    const float* enc_we = (const float*)d_in[7];
    const float* enc_be = (const float*)d_in[8];
    const float* msg_w1 = (const float*)d_in[9];
    const float* msg_b1 = (const float*)d_in[10];
    const float* msg_w2 = (const float*)d_in[11];
    const float* msg_b2 = (const float*)d_in[12];
    const float* rmsg_w1= (const float*)d_in[13];
    const float* rmsg_b1= (const float*)d_in[14];
    const float* rmsg_w2= (const float*)d_in[15];
    const float* rmsg_b2= (const float*)d_in[16];
    const float* upd_w1 = (const float*)d_in[17];
    const float* upd_b1 = (const float*)d_in[18];
    const float* upd_w2 = (const float*)d_in[19];
    const float* upd_b2 = (const float*)d_in[20];
    const float* agg_w1 = (const float*)d_in[21];
    const float* agg_b1 = (const float*)d_in[22];
    const float* agg_w2 = (const float*)d_in[23];
    const float* agg_b2 = (const float*)d_in[24];
    float* out = (float*)d_out;

    float* p_h    = (float*)sym(g_h);
    __half* p_PQh = (__half*)sym(g_PQh);
    float* p_SH   = (float*)sym(g_SH);
    float* p_Hu   = (float*)sym(g_Hu);
    float* p_gv   = (float*)sym(g_gv);
    float* p_b3   = (float*)sym(g_bias3);
    int*   p_deg  = (int*)sym(g_deg);
    __half* p_Bh  = (__half*)sym(g_Bh);

    cudaFuncSetAttribute(tgemm_k, cudaFuncAttributeMaxDynamicSharedMemorySize, TG_DSMEM);
    cudaFuncSetAttribute(edge_csr_k, cudaFuncAttributeMaxDynamicSharedMemorySize, ESMEM);

    const int GM = (N_NODES + 127) / 128;   // 235

    prep_w_k<<<1153, 256>>>(enc_we, enc_be, msg_w1, msg_b1, rmsg_w1, rmsg_b1,
                            msg_w2, rmsg_w2, upd_w1, msg_b2, rmsg_b2, upd_b1);
    spt_all_k<<<1456, 256>>>(upd_w2, agg_w1, enc_wn);
    tgemm_k<<<dim3(GM, 1), 256, TG_DSMEM>>>(nf, 32, 32, p_Bh + OFF_ENW,
                                            enc_bn, nullptr, nullptr, p_h, 128, N_NODES, 128,
                                            FLAG_COPYSH);
    tgemm_k<<<dim3(GM, 8), 256, TG_DSMEM>>>(p_h, 128, 128, p_Bh + OFF_CAT,
                                            nullptr, nullptr, nullptr, (float*)p_PQh, 1024,
                                            N_NODES, 1024, FLAG_ZEROSH | FLAG_FP16OUT);
    zero_k<<<(2 * N_NODES / 4 + 255) / 256, 256>>>((float4*)p_deg, 2 * N_NODES / 4);
    hist_k<<<(N_EDGES + 255) / 256, 256>>>(from, to);
    scan_k<<<2, 1024>>>();
    build_k<<<(N_EDGES + 255) / 256, 256>>>(from, to);

    for (int l = 0; l < NLAYERS; l++) {
        if (l > 0)
            tgemm_k<<<dim3(GM, 8), 256, TG_DSMEM>>>(p_h, 128, 128, p_Bh + OFF_CAT,
                                                    nullptr, nullptr, nullptr, (float*)p_PQh, 1024,
                                                    N_NODES, 1024, FLAG_ZEROSH | FLAG_FP16OUT);
        edge_csr_k<<<2 * GEB, 256, ESMEM>>>(ef, from, to);
        tgemm_k<<<dim3(GM, 2), 256, TG_DSMEM>>>(p_SH, 640, 640, p_Bh + OFF_UPD,
                                                p_b3, p_deg, p_deg + N_NODES, p_Hu, 256, N_NODES, 256,
                                                FLAG_RELU | FLAG_BIAS3);
        int fl = FLAG_ADDC | ((l < NLAYERS - 1) ? FLAG_COPYSH : 0);
        tgemm_k<<<dim3(GM, 1), 256, TG_DSMEM>>>(p_Hu, 256, 256, p_Bh + OFF_UW2,
                                                upd_b2, nullptr, nullptr, p_h, 128, N_NODES, 128, fl);
    }

    tgemm_k<<<dim3(GM, 2), 256, TG_DSMEM>>>(p_h, 128, 128, p_Bh + OFF_AW1,
                                            agg_b1, nullptr, nullptr, p_Hu, 256, N_NODES, 256, 0);
    zero_k<<<(N_GRAPHS * 32 + 255) / 256, 256>>>((float4*)p_gv, N_GRAPHS * 32);
    gate_k<<<(N_NODES * 32 + 255) / 256, 256>>>(gidx);
    gv2_k<<<N_GRAPHS, 128>>>(agg_w2, agg_b2);
    out_k<<<128, 128>>>(out);
    (void)in_sizes; (void)n_in; (void)out_size;
}